// round 8
// baseline (speedup 1.0000x reference)
#include <cuda_runtime.h>
#include <cstdint>
#include <cstdio>

#define TOK   2048
#define NBAT  2
#define NH    16
#define DHD   64
#define DMOD  1024
#define MROWS 4096   /* B*N */
#define FF    4096

// ---------------- scratch (static device globals; no runtime allocation) ---
__device__ float g_x2 [MROWS * DMOD];            // 16 MB : x after attn residual
__device__ float g_xf2[MROWS * DMOD];            // 16 MB : LN3 output
__device__ float g_h  [(size_t)MROWS * 2 * FF];  // 128 MB: FF1 output
__device__ float g_act[(size_t)MROWS * FF];      // 64 MB : geglu output

// ---------------- helpers --------------------------------------------------
__device__ __forceinline__ uint32_t f2tf32(float x) {
    uint32_t t;
    asm("cvt.rna.tf32.f32 %0, %1;" : "=r"(t) : "f"(x));
    return t;
}
__device__ __forceinline__ float f2tf32f(float x) { return __uint_as_float(f2tf32(x)); }

__device__ __forceinline__ void mma_tf32(float c[4], const uint32_t a[4],
                                         uint32_t b0, uint32_t b1) {
    asm volatile(
        "mma.sync.aligned.m16n8k8.row.col.f32.tf32.tf32.f32 "
        "{%0,%1,%2,%3}, {%4,%5,%6,%7}, {%8,%9}, {%0,%1,%2,%3};\n"
        : "+f"(c[0]), "+f"(c[1]), "+f"(c[2]), "+f"(c[3])
        : "r"(a[0]), "r"(a[1]), "r"(a[2]), "r"(a[3]), "r"(b0), "r"(b1));
}

__device__ __forceinline__ void cp_async16(uint32_t dst, const void* src) {
    asm volatile("cp.async.cg.shared.global [%0], [%1], 16;\n" :: "r"(dst), "l"(src));
}
__device__ __forceinline__ void cp_commit() {
    asm volatile("cp.async.commit_group;\n" ::: "memory");
}
__device__ __forceinline__ void cp_wait1() {
    asm volatile("cp.async.wait_group 1;\n" ::: "memory");
}

__device__ __forceinline__ float gelu_exact(float x) {
    return 0.5f * x * (1.0f + erff(x * 0.70710678118654752f));
}

// ---------------- LayerNorm (one block per row of 1024) --------------------
__global__ __launch_bounds__(256)
void ln_kernel(const float* __restrict__ x, const float* __restrict__ gw,
               const float* __restrict__ bw, float* __restrict__ y) {
    __shared__ float red[16];
    const int row = blockIdx.x;
    const int tid = threadIdx.x;
    const float4 v = reinterpret_cast<const float4*>(x + (size_t)row * DMOD)[tid];
    float s  = v.x + v.y + v.z + v.w;
    float ss = v.x * v.x + v.y * v.y + v.z * v.z + v.w * v.w;
#pragma unroll
    for (int o = 16; o > 0; o >>= 1) {
        s  += __shfl_xor_sync(0xffffffffu, s,  o);
        ss += __shfl_xor_sync(0xffffffffu, ss, o);
    }
    if ((tid & 31) == 0) { red[tid >> 5] = s; red[8 + (tid >> 5)] = ss; }
    __syncthreads();
    float ts = 0.f, tss = 0.f;
#pragma unroll
    for (int w = 0; w < 8; w++) { ts += red[w]; tss += red[8 + w]; }
    const float mu  = ts * (1.0f / DMOD);
    const float var = tss * (1.0f / DMOD) - mu * mu;
    const float rs  = rsqrtf(var + 1e-5f);
    const float4 gv = reinterpret_cast<const float4*>(gw)[tid];
    const float4 bv = reinterpret_cast<const float4*>(bw)[tid];
    float4 o;
    o.x = (v.x - mu) * rs * gv.x + bv.x;
    o.y = (v.y - mu) * rs * gv.y + bv.y;
    o.z = (v.z - mu) * rs * gv.z + bv.z;
    o.w = (v.w - mu) * rs * gv.w + bv.w;
    reinterpret_cast<float4*>(y + (size_t)row * DMOD)[tid] = o;
}

// -------- TF32 GEMM v3: CTA 128x256, 512 thr, warp 64x32, cp.async 3-stage --
// smem per stage: As[128][36] then Bs[32][264] (floats).
// A frag banks (g*4+tg) distinct; B frag banks (tg*8+nt*8+g) distinct.
constexpr int BM = 128, BN = 256, BK = 32, STAGES = 3;
constexpr int GTH = 512;                                       // GEMM threads
constexpr int LDA_S = 36, LDB_S = 264;
constexpr int STAGE_F = BM * LDA_S + BK * LDB_S;               // 13056 floats
constexpr int SMEM_GEMM = STAGES * STAGE_F * 4;                // 156672 bytes

// AMODE 0: A row-major [M][K].  AMODE 1: A gathered from inter_out (B,H,TOK,DHD).
template <int AMODE>
struct ALoader {
    static __device__ __forceinline__ const float* ptr(const float* A, int gm, int gk, int K) {
        if (AMODE == 0) return A + (size_t)gm * K + gk;
        int bb = gm >> 11, nn = gm & (TOK - 1);
        int hh = gk >> 6,  dd = gk & (DHD - 1);
        return A + (((size_t)(bb * NH + hh) * TOK + nn) * DHD + dd);
    }
};

template <int AMODE>
__device__ __forceinline__ void gemm_load_stage(
    const float* __restrict__ A, const float* __restrict__ B, int ldb,
    int m0, int nb, int kb, int K, uint32_t smem_stage) {
#pragma unroll
    for (int i = 0; i < 2; i++) {                // A: 128x32 = 1024 chunks / 512 thr
        int c = i * GTH + threadIdx.x;
        int row = c >> 3, kc = (c & 7) << 2;
        const float* src = ALoader<AMODE>::ptr(A, m0 + row, kb + kc, K);
        cp_async16(smem_stage + (uint32_t)(row * LDA_S + kc) * 4u, src);
    }
    const uint32_t bs = smem_stage + (uint32_t)(BM * LDA_S) * 4u;
#pragma unroll
    for (int i = 0; i < 4; i++) {                // B: 32x256 = 2048 chunks / 512 thr
        int c = i * GTH + threadIdx.x;
        int row = c >> 6, col = (c & 63) << 2;
        cp_async16(bs + (uint32_t)(row * LDB_S + col) * 4u,
                   B + (size_t)(kb + row) * ldb + nb + col);
    }
}

__device__ __forceinline__ void gemm_compute_stage(
    const float* __restrict__ st, int wm, int wn, float acc[4][4][4]) {
    const int lane = threadIdx.x & 31;
    const int g = lane >> 2, tg = lane & 3;
    const float* As = st;
    const float* Bs = st + BM * LDA_S;
#pragma unroll
    for (int kk = 0; kk < BK; kk += 8) {
        uint32_t af[4][4];
#pragma unroll
        for (int mt = 0; mt < 4; mt++) {
            const float* ar = As + (wm + mt * 16 + g) * LDA_S + kk + tg;
            af[mt][0] = f2tf32(ar[0]);
            af[mt][1] = f2tf32(ar[8 * LDA_S]);
            af[mt][2] = f2tf32(ar[4]);
            af[mt][3] = f2tf32(ar[8 * LDA_S + 4]);
        }
        uint32_t bf[4][2];
#pragma unroll
        for (int nt = 0; nt < 4; nt++) {
            const float* br = Bs + (kk + tg) * LDB_S + wn + nt * 8 + g;
            bf[nt][0] = f2tf32(br[0]);
            bf[nt][1] = f2tf32(br[4 * LDB_S]);
        }
#pragma unroll
        for (int mt = 0; mt < 4; mt++)
#pragma unroll
            for (int nt = 0; nt < 4; nt++)
                mma_tf32(acc[mt][nt], af[mt], bf[nt][0], bf[nt][1]);
    }
}

// ---- standard output: C row-major (ldc = N), optional bias + residual -----
template <int AMODE>
__global__ __launch_bounds__(GTH, 1)
void gemm3_kernel(const float* __restrict__ A, const float* __restrict__ B,
                  float* __restrict__ C, int M, int N, int K,
                  const float* __restrict__ bias, const float* __restrict__ res) {
    extern __shared__ float sm[];
    const uint32_t smem_u = (uint32_t)__cvta_generic_to_shared(sm);
    const int tid = threadIdx.x, wid = tid >> 5, lane = tid & 31;
    const int g = lane >> 2, tg = lane & 3;
    const int m0 = blockIdx.y * BM;
    const int n0 = blockIdx.x * BN;
    const int wm = (wid & 1) * 64;     // 2 warp-rows of 64
    const int wn = (wid >> 1) * 32;    // 8 warp-cols of 32

    float acc[4][4][4];
#pragma unroll
    for (int i = 0; i < 4; i++)
#pragma unroll
        for (int j = 0; j < 4; j++)
#pragma unroll
            for (int k = 0; k < 4; k++) acc[i][j][k] = 0.f;

    const int T = K / BK;
    gemm_load_stage<AMODE>(A, B, N, m0, n0, 0, K, smem_u);
    cp_commit();
    gemm_load_stage<AMODE>(A, B, N, m0, n0, BK, K, smem_u + STAGE_F * 4);
    cp_commit();

    int s = 0;
    for (int kt = 0; kt < T; kt++) {
        cp_wait1();
        __syncthreads();
        if (kt + 2 < T) {
            int s2 = (s + 2 >= STAGES) ? s + 2 - STAGES : s + 2;
            gemm_load_stage<AMODE>(A, B, N, m0, n0, (kt + 2) * BK, K,
                                   smem_u + (uint32_t)s2 * STAGE_F * 4);
        }
        cp_commit();
        gemm_compute_stage(sm + s * STAGE_F, wm, wn, acc);
        s = (s + 1 == STAGES) ? 0 : s + 1;
    }

#pragma unroll
    for (int mt = 0; mt < 4; mt++) {
        const int r0 = m0 + wm + mt * 16 + g;
        const int r1 = r0 + 8;
#pragma unroll
        for (int nt = 0; nt < 4; nt++) {
            const int c = n0 + wn + nt * 8 + 2 * tg;
            float2 v0 = make_float2(acc[mt][nt][0], acc[mt][nt][1]);
            float2 v1 = make_float2(acc[mt][nt][2], acc[mt][nt][3]);
            if (bias) {
                float2 bb = *reinterpret_cast<const float2*>(bias + c);
                v0.x += bb.x; v0.y += bb.y; v1.x += bb.x; v1.y += bb.y;
            }
            if (res) {
                float2 q0r = *reinterpret_cast<const float2*>(res + (size_t)r0 * N + c);
                float2 q1r = *reinterpret_cast<const float2*>(res + (size_t)r1 * N + c);
                v0.x += q0r.x; v0.y += q0r.y; v1.x += q1r.x; v1.y += q1r.y;
            }
            *reinterpret_cast<float2*>(C + (size_t)r0 * N + c) = v0;
            *reinterpret_cast<float2*>(C + (size_t)r1 * N + c) = v1;
        }
    }
}

// ---- fused QKV: one GEMM over N=3072, scatter into q_bh/k_bh/v_bh ---------
__global__ __launch_bounds__(GTH, 1)
void gemm_qkv_kernel(const float* __restrict__ A,
                     const float* __restrict__ Wq, const float* __restrict__ Wk,
                     const float* __restrict__ Wv,
                     float* __restrict__ Cq, float* __restrict__ Ck,
                     float* __restrict__ Cv) {
    extern __shared__ float sm[];
    const uint32_t smem_u = (uint32_t)__cvta_generic_to_shared(sm);
    const int tid = threadIdx.x, wid = tid >> 5, lane = tid & 31;
    const int g = lane >> 2, tg = lane & 3;
    const int m0 = blockIdx.y * BM;
    const int arr = blockIdx.x >> 2;                 // 0..2 : which weight/output
    const int nb  = (blockIdx.x & 3) * BN;           // column base within the array
    const float* B = (arr == 0) ? Wq : (arr == 1) ? Wk : Wv;
    float* C = (arr == 0) ? Cq : (arr == 1) ? Ck : Cv;
    const int wm = (wid & 1) * 64;
    const int wn = (wid >> 1) * 32;
    const int K = DMOD;

    float acc[4][4][4];
#pragma unroll
    for (int i = 0; i < 4; i++)
#pragma unroll
        for (int j = 0; j < 4; j++)
#pragma unroll
            for (int k = 0; k < 4; k++) acc[i][j][k] = 0.f;

    const int T = K / BK;
    gemm_load_stage<0>(A, B, DMOD, m0, nb, 0, K, smem_u);
    cp_commit();
    gemm_load_stage<0>(A, B, DMOD, m0, nb, BK, K, smem_u + STAGE_F * 4);
    cp_commit();

    int s = 0;
    for (int kt = 0; kt < T; kt++) {
        cp_wait1();
        __syncthreads();
        if (kt + 2 < T) {
            int s2 = (s + 2 >= STAGES) ? s + 2 - STAGES : s + 2;
            gemm_load_stage<0>(A, B, DMOD, m0, nb, (kt + 2) * BK, K,
                               smem_u + (uint32_t)s2 * STAGE_F * 4);
        }
        cp_commit();
        gemm_compute_stage(sm + s * STAGE_F, wm, wn, acc);
        s = (s + 1 == STAGES) ? 0 : s + 1;
    }

    // scatter to (B*H, TOK, DHD)
#pragma unroll
    for (int mt = 0; mt < 4; mt++) {
        const int r0 = m0 + wm + mt * 16 + g;
        const int r1 = r0 + 8;
        const int b0_ = r0 >> 11, n0_ = r0 & (TOK - 1);
        const int b1_ = r1 >> 11, n1_ = r1 & (TOK - 1);
#pragma unroll
        for (int nt = 0; nt < 4; nt++) {
            const int cl = nb + wn + nt * 8 + 2 * tg;
            const int hh = cl >> 6, dd = cl & (DHD - 1);
            float2 v0 = make_float2(acc[mt][nt][0], acc[mt][nt][1]);
            float2 v1 = make_float2(acc[mt][nt][2], acc[mt][nt][3]);
            *reinterpret_cast<float2*>(
                C + ((size_t)(b0_ * NH + hh) * TOK + n0_) * DHD + dd) = v0;
            *reinterpret_cast<float2*>(
                C + ((size_t)(b1_ * NH + hh) * TOK + n1_) * DHD + dd) = v1;
        }
    }
}

// ---------------- flash attention (per (b,h); BM=128, DH=64) ---------------
__global__ __launch_bounds__(256)
void flash_attn_kernel(const float* __restrict__ Q, const float* __restrict__ Kg,
                       const float* __restrict__ V, float* __restrict__ O) {
    extern __shared__ float sm[];
    float(*Ks)[DHD + 4] = reinterpret_cast<float(*)[DHD + 4]>(sm);
    float(*Vs)[DHD + 4] = reinterpret_cast<float(*)[DHD + 4]>(sm + 128 * (DHD + 4));

    const int tid = threadIdx.x, wid = tid >> 5, lane = tid & 31;
    const int g = lane >> 2, tg = lane & 3;
    const int bh = blockIdx.y;
    const int q0 = blockIdx.x * 128;
    const float* Qp = Q + (size_t)bh * TOK * DHD;
    const float* Kp = Kg + (size_t)bh * TOK * DHD;
    const float* Vp = V + (size_t)bh * TOK * DHD;
    float* Op = O + (size_t)bh * TOK * DHD;
    const int wm = wid * 16;
    const int r0 = q0 + wm + g, r1 = r0 + 8;

    uint32_t qf[8][4];
#pragma unroll
    for (int ks = 0; ks < 8; ks++) {
        int c = ks * 8 + tg;
        qf[ks][0] = f2tf32(Qp[(size_t)r0 * DHD + c] * 0.125f);
        qf[ks][1] = f2tf32(Qp[(size_t)r1 * DHD + c] * 0.125f);
        qf[ks][2] = f2tf32(Qp[(size_t)r0 * DHD + c + 4] * 0.125f);
        qf[ks][3] = f2tf32(Qp[(size_t)r1 * DHD + c + 4] * 0.125f);
    }

    float m0 = -1e30f, m1 = -1e30f, l0 = 0.f, l1 = 0.f;
    float o[8][4];
#pragma unroll
    for (int i = 0; i < 8; i++)
#pragma unroll
        for (int j = 0; j < 4; j++) o[i][j] = 0.f;

    for (int j = 0; j < TOK; j += 128) {
        __syncthreads();
#pragma unroll
        for (int i = 0; i < 8; i++) {
            int s = tid + i * 256;
            int r = s >> 4, c = (s & 15) << 2;
            float4 kv = *reinterpret_cast<const float4*>(Kp + (size_t)(j + r) * DHD + c);
            float4 vv = *reinterpret_cast<const float4*>(Vp + (size_t)(j + r) * DHD + c);
            float4 kc = make_float4(f2tf32f(kv.x), f2tf32f(kv.y), f2tf32f(kv.z), f2tf32f(kv.w));
            float4 vc = make_float4(f2tf32f(vv.x), f2tf32f(vv.y), f2tf32f(vv.z), f2tf32f(vv.w));
            *reinterpret_cast<float4*>(&Ks[r][c]) = kc;
            *reinterpret_cast<float4*>(&Vs[r][c]) = vc;
        }
        __syncthreads();

        float sc[16][4];
#pragma unroll
        for (int nt = 0; nt < 16; nt++)
#pragma unroll
            for (int k4 = 0; k4 < 4; k4++) sc[nt][k4] = 0.f;
#pragma unroll
        for (int ks = 0; ks < 8; ks++) {
#pragma unroll
            for (int nt = 0; nt < 16; nt++) {
                uint32_t b0 = __float_as_uint(Ks[nt * 8 + g][ks * 8 + tg]);
                uint32_t b1 = __float_as_uint(Ks[nt * 8 + g][ks * 8 + tg + 4]);
                mma_tf32(sc[nt], qf[ks], b0, b1);
            }
        }

        float tm0 = -1e30f, tm1 = -1e30f;
#pragma unroll
        for (int nt = 0; nt < 16; nt++) {
            tm0 = fmaxf(tm0, fmaxf(sc[nt][0], sc[nt][1]));
            tm1 = fmaxf(tm1, fmaxf(sc[nt][2], sc[nt][3]));
        }
        tm0 = fmaxf(tm0, __shfl_xor_sync(0xffffffffu, tm0, 1));
        tm0 = fmaxf(tm0, __shfl_xor_sync(0xffffffffu, tm0, 2));
        tm1 = fmaxf(tm1, __shfl_xor_sync(0xffffffffu, tm1, 1));
        tm1 = fmaxf(tm1, __shfl_xor_sync(0xffffffffu, tm1, 2));
        const float nm0 = fmaxf(m0, tm0), nm1 = fmaxf(m1, tm1);
        const float a0 = __expf(m0 - nm0), a1 = __expf(m1 - nm1);
        float ts0 = 0.f, ts1 = 0.f;
#pragma unroll
        for (int nt = 0; nt < 16; nt++) {
            float p0 = __expf(sc[nt][0] - nm0);
            float p1 = __expf(sc[nt][1] - nm0);
            float p2 = __expf(sc[nt][2] - nm1);
            float p3 = __expf(sc[nt][3] - nm1);
            ts0 += p0 + p1; ts1 += p2 + p3;
            sc[nt][0] = f2tf32f(p0); sc[nt][1] = f2tf32f(p1);
            sc[nt][2] = f2tf32f(p2); sc[nt][3] = f2tf32f(p3);
        }
        ts0 += __shfl_xor_sync(0xffffffffu, ts0, 1);
        ts0 += __shfl_xor_sync(0xffffffffu, ts0, 2);
        ts1 += __shfl_xor_sync(0xffffffffu, ts1, 1);
        ts1 += __shfl_xor_sync(0xffffffffu, ts1, 2);
        l0 = l0 * a0 + ts0; l1 = l1 * a1 + ts1;
        m0 = nm0; m1 = nm1;
#pragma unroll
        for (int nt = 0; nt < 8; nt++) {
            o[nt][0] *= a0; o[nt][1] *= a0; o[nt][2] *= a1; o[nt][3] *= a1;
        }

        const int qb = lane & ~3;
        const int srcA = qb + (tg >> 1);
        const int srcB = srcA + 2;
        const bool odd = (tg & 1);
#pragma unroll
        for (int kt = 0; kt < 16; kt++) {
            float p0 = sc[kt][0], p1 = sc[kt][1], p2 = sc[kt][2], p3 = sc[kt][3];
            float e0 = __shfl_sync(0xffffffffu, p0, srcA);
            float e1 = __shfl_sync(0xffffffffu, p1, srcA);
            float e2 = __shfl_sync(0xffffffffu, p2, srcA);
            float e3 = __shfl_sync(0xffffffffu, p3, srcA);
            float h0 = __shfl_sync(0xffffffffu, p0, srcB);
            float h1 = __shfl_sync(0xffffffffu, p1, srcB);
            float h2 = __shfl_sync(0xffffffffu, p2, srcB);
            float h3 = __shfl_sync(0xffffffffu, p3, srcB);
            uint32_t af[4];
            af[0] = __float_as_uint(odd ? e1 : e0);
            af[1] = __float_as_uint(odd ? e3 : e2);
            af[2] = __float_as_uint(odd ? h1 : h0);
            af[3] = __float_as_uint(odd ? h3 : h2);
#pragma unroll
            for (int nt = 0; nt < 8; nt++) {
                uint32_t b0 = __float_as_uint(Vs[kt * 8 + tg][nt * 8 + g]);
                uint32_t b1 = __float_as_uint(Vs[kt * 8 + tg + 4][nt * 8 + g]);
                mma_tf32(o[nt], af, b0, b1);
            }
        }
    }

    const float il0 = 1.f / l0, il1 = 1.f / l1;
#pragma unroll
    for (int nt = 0; nt < 8; nt++) {
        int c = nt * 8 + 2 * tg;
        float2 v0 = make_float2(o[nt][0] * il0, o[nt][1] * il0);
        float2 v1 = make_float2(o[nt][2] * il1, o[nt][3] * il1);
        *reinterpret_cast<float2*>(Op + (size_t)r0 * DHD + c) = v0;
        *reinterpret_cast<float2*>(Op + (size_t)r1 * DHD + c) = v1;
    }
}

// ---------------- GEGLU ----------------------------------------------------
__global__ __launch_bounds__(256)
void geglu_kernel(const float* __restrict__ h, float* __restrict__ act) {
    const int idx = blockIdx.x * 256 + threadIdx.x;
    const int m = idx >> 10;
    const int c = (idx & 1023) << 2;
    const float4 a  = *reinterpret_cast<const float4*>(h + (size_t)m * (2 * FF) + c);
    const float4 gt = *reinterpret_cast<const float4*>(h + (size_t)m * (2 * FF) + FF + c);
    float4 o;
    o.x = a.x * gelu_exact(gt.x);
    o.y = a.y * gelu_exact(gt.y);
    o.z = a.z * gelu_exact(gt.z);
    o.w = a.w * gelu_exact(gt.w);
    *reinterpret_cast<float4*>(act + (size_t)m * FF + c) = o;
}

// ---------------- launch ---------------------------------------------------
extern "C" void kernel_launch(void* const* d_in, const int* in_sizes, int n_in,
                              void* d_out, int out_size) {
    (void)in_sizes; (void)n_in; (void)out_size;
    const float* x     = (const float*)d_in[0];
    const float* Wq    = (const float*)d_in[1];
    const float* Wk    = (const float*)d_in[2];
    const float* Wv    = (const float*)d_in[3];
    const float* Wo    = (const float*)d_in[4];
    const float* bo    = (const float*)d_in[5];
    const float* ln1_g = (const float*)d_in[6];
    const float* ln1_b = (const float*)d_in[7];
    const float* ln3_g = (const float*)d_in[8];
    const float* ln3_b = (const float*)d_in[9];
    const float* Wff1  = (const float*)d_in[10];
    const float* bff1  = (const float*)d_in[11];
    const float* Wff2  = (const float*)d_in[12];
    const float* bff2  = (const float*)d_in[13];

    float* out = (float*)d_out;
    const size_t SZ = (size_t)MROWS * DMOD;
    float* out_x  = out;            // x
    float* out_q  = out + SZ;       // q_bh
    float* out_k  = out + 2 * SZ;   // k_bh
    float* out_v  = out + 3 * SZ;   // v_bh
    float* out_io = out + 4 * SZ;   // inter_out
    float* out_xf = out + 5 * SZ;   // x_features

    float *x2, *xf2, *hbuf, *actbuf;
    cudaGetSymbolAddress((void**)&x2,     g_x2);
    cudaGetSymbolAddress((void**)&xf2,    g_xf2);
    cudaGetSymbolAddress((void**)&hbuf,   g_h);
    cudaGetSymbolAddress((void**)&actbuf, g_act);

    static bool attr_done = false;
    if (!attr_done) {
        cudaFuncSetAttribute(gemm_qkv_kernel,
                             cudaFuncAttributeMaxDynamicSharedMemorySize, SMEM_GEMM);
        cudaFuncSetAttribute(gemm3_kernel<0>,
                             cudaFuncAttributeMaxDynamicSharedMemorySize, SMEM_GEMM);
        cudaFuncSetAttribute(gemm3_kernel<1>,
                             cudaFuncAttributeMaxDynamicSharedMemorySize, SMEM_GEMM);
        cudaFuncSetAttribute(flash_attn_kernel,
                             cudaFuncAttributeMaxDynamicSharedMemorySize,
                             2 * 128 * (DHD + 4) * (int)sizeof(float));
        attr_done = true;
    }

    const dim3 blk(GTH);

    // 1) LN1 -> x_features
    ln_kernel<<<MROWS, 256>>>(x, ln1_g, ln1_b, out_xf);

    // 2) fused QKV GEMM (N = 3072), scattered directly to (B*H, N, DH)
    gemm_qkv_kernel<<<dim3(3 * DMOD / BN, MROWS / BM), blk, SMEM_GEMM>>>(
        out_xf, Wq, Wk, Wv, out_q, out_k, out_v);

    // 3) attention -> inter_out (B,H,N,DH)
    const int smem_fa = 2 * 128 * (DHD + 4) * (int)sizeof(float);
    flash_attn_kernel<<<dim3(TOK / 128, NBAT * NH), 256, smem_fa>>>(
        out_q, out_k, out_v, out_io);

    // 4) Wo GEMM (gather-A from inter_out layout) + bo + residual x -> x2
    gemm3_kernel<1><<<dim3(DMOD / BN, MROWS / BM), blk, SMEM_GEMM>>>(
        out_io, Wo, x2, MROWS, DMOD, DMOD, bo, x);

    // 5) LN3 -> xf2
    ln_kernel<<<MROWS, 256>>>(x2, ln3_g, ln3_b, xf2);

    // 6) FF1 GEMM (+bff1) -> h
    gemm3_kernel<0><<<dim3(2 * FF / BN, MROWS / BM), blk, SMEM_GEMM>>>(
        xf2, Wff1, hbuf, MROWS, 2 * FF, DMOD, bff1, nullptr);

    // 7) GEGLU -> act
    geglu_kernel<<<(MROWS * (FF / 4)) / 256, 256>>>(hbuf, actbuf);

    // 8) FF2 GEMM (+bff2) + residual x2 -> final x
    gemm3_kernel<0><<<dim3(DMOD / BN, MROWS / BM), blk, SMEM_GEMM>>>(
        actbuf, Wff2, out_x, MROWS, DMOD, FF, bff2, x2);
}

// round 9
// speedup vs baseline: 1.0608x; 1.0608x over previous
#include <cuda_runtime.h>
#include <cstdint>
#include <cstdio>

#define TOK   2048
#define NBAT  2
#define NH    16
#define DHD   64
#define DMOD  1024
#define MROWS 4096   /* B*N */
#define FF    4096

// ---------------- scratch (static device globals; no runtime allocation) ---
__device__ float g_x2 [MROWS * DMOD];            // 16 MB : x after attn residual (exact)
__device__ float g_xf2[MROWS * DMOD];            // 16 MB : LN3 output (tf32-rounded)
__device__ float g_xfr[MROWS * DMOD];            // 16 MB : LN1 output (tf32-rounded)
__device__ float g_ior[MROWS * DMOD];            // 16 MB : inter_out (tf32-rounded)
__device__ float g_h  [(size_t)MROWS * 2 * FF];  // 128 MB: FF1 output (exact)
__device__ float g_act[(size_t)MROWS * FF];      // 64 MB : geglu output (tf32-rounded)
__device__ float g_w  [16 * 1024 * 1024];        // 64 MB : all weights, tf32-rounded
// offsets (floats) within g_w:
#define WOFF_Q    0
#define WOFF_K    (1024 * 1024)
#define WOFF_V    (2 * 1024 * 1024)
#define WOFF_O    (3 * 1024 * 1024)
#define WOFF_FF1  (4 * 1024 * 1024)
#define WOFF_FF2  (12 * 1024 * 1024)

// ---------------- helpers --------------------------------------------------
__device__ __forceinline__ uint32_t f2tf32(float x) {
    uint32_t t;
    asm("cvt.rna.tf32.f32 %0, %1;" : "=r"(t) : "f"(x));
    return t;
}
__device__ __forceinline__ float f2tf32f(float x) { return __uint_as_float(f2tf32(x)); }

__device__ __forceinline__ void mma_tf32(float c[4], const uint32_t a[4],
                                         uint32_t b0, uint32_t b1) {
    asm volatile(
        "mma.sync.aligned.m16n8k8.row.col.f32.tf32.tf32.f32 "
        "{%0,%1,%2,%3}, {%4,%5,%6,%7}, {%8,%9}, {%0,%1,%2,%3};\n"
        : "+f"(c[0]), "+f"(c[1]), "+f"(c[2]), "+f"(c[3])
        : "r"(a[0]), "r"(a[1]), "r"(a[2]), "r"(a[3]), "r"(b0), "r"(b1));
}

__device__ __forceinline__ void cp_async16(uint32_t dst, const void* src) {
    asm volatile("cp.async.cg.shared.global [%0], [%1], 16;\n" :: "r"(dst), "l"(src));
}
__device__ __forceinline__ void cp_commit() {
    asm volatile("cp.async.commit_group;\n" ::: "memory");
}
__device__ __forceinline__ void cp_wait1() {
    asm volatile("cp.async.wait_group 1;\n" ::: "memory");
}

__device__ __forceinline__ float gelu_exact(float x) {
    return 0.5f * x * (1.0f + erff(x * 0.70710678118654752f));
}

// ---------------- weight pre-rounding to tf32 -------------------------------
__global__ __launch_bounds__(256)
void cvt_tf32_kernel(const float4* __restrict__ src, float4* __restrict__ dst, int n4) {
    int i = blockIdx.x * 256 + threadIdx.x;
    if (i < n4) {
        float4 v = src[i];
        dst[i] = make_float4(f2tf32f(v.x), f2tf32f(v.y), f2tf32f(v.z), f2tf32f(v.w));
    }
}

// ---------------- LayerNorm (one block per row of 1024) --------------------
// y: exact output (nullable). yr: tf32-rounded output (nullable).
__global__ __launch_bounds__(256)
void ln_kernel(const float* __restrict__ x, const float* __restrict__ gw,
               const float* __restrict__ bw, float* __restrict__ y,
               float* __restrict__ yr) {
    __shared__ float red[16];
    const int row = blockIdx.x;
    const int tid = threadIdx.x;
    const float4 v = reinterpret_cast<const float4*>(x + (size_t)row * DMOD)[tid];
    float s  = v.x + v.y + v.z + v.w;
    float ss = v.x * v.x + v.y * v.y + v.z * v.z + v.w * v.w;
#pragma unroll
    for (int o = 16; o > 0; o >>= 1) {
        s  += __shfl_xor_sync(0xffffffffu, s,  o);
        ss += __shfl_xor_sync(0xffffffffu, ss, o);
    }
    if ((tid & 31) == 0) { red[tid >> 5] = s; red[8 + (tid >> 5)] = ss; }
    __syncthreads();
    float ts = 0.f, tss = 0.f;
#pragma unroll
    for (int w = 0; w < 8; w++) { ts += red[w]; tss += red[8 + w]; }
    const float mu  = ts * (1.0f / DMOD);
    const float var = tss * (1.0f / DMOD) - mu * mu;
    const float rs  = rsqrtf(var + 1e-5f);
    const float4 gv = reinterpret_cast<const float4*>(gw)[tid];
    const float4 bv = reinterpret_cast<const float4*>(bw)[tid];
    float4 o;
    o.x = (v.x - mu) * rs * gv.x + bv.x;
    o.y = (v.y - mu) * rs * gv.y + bv.y;
    o.z = (v.z - mu) * rs * gv.z + bv.z;
    o.w = (v.w - mu) * rs * gv.w + bv.w;
    if (y)  reinterpret_cast<float4*>(y  + (size_t)row * DMOD)[tid] = o;
    if (yr) {
        float4 r = make_float4(f2tf32f(o.x), f2tf32f(o.y), f2tf32f(o.z), f2tf32f(o.w));
        reinterpret_cast<float4*>(yr + (size_t)row * DMOD)[tid] = r;
    }
}

// -------- TF32 GEMM v4: CTA 128x256, 512 thr, warp 64x32, cp.async 3-stage --
// All operands PRE-ROUNDED to tf32 (stored as f32 bits) -> no cvt in the loop.
constexpr int BM = 128, BN = 256, BK = 32, STAGES = 3;
constexpr int GTH = 512;                                       // GEMM threads
constexpr int LDA_S = 36, LDB_S = 264;
constexpr int STAGE_F = BM * LDA_S + BK * LDB_S;               // 13056 floats
constexpr int SMEM_GEMM = STAGES * STAGE_F * 4;                // 156672 bytes

// AMODE 0: A row-major [M][K].  AMODE 1: A gathered from inter_out (B,H,TOK,DHD).
template <int AMODE>
struct ALoader {
    static __device__ __forceinline__ const float* ptr(const float* A, int gm, int gk, int K) {
        if (AMODE == 0) return A + (size_t)gm * K + gk;
        int bb = gm >> 11, nn = gm & (TOK - 1);
        int hh = gk >> 6,  dd = gk & (DHD - 1);
        return A + (((size_t)(bb * NH + hh) * TOK + nn) * DHD + dd);
    }
};

template <int AMODE>
__device__ __forceinline__ void gemm_load_stage(
    const float* __restrict__ A, const float* __restrict__ B, int ldb,
    int m0, int nb, int kb, int K, uint32_t smem_stage) {
#pragma unroll
    for (int i = 0; i < 2; i++) {                // A: 128x32 = 1024 chunks / 512 thr
        int c = i * GTH + threadIdx.x;
        int row = c >> 3, kc = (c & 7) << 2;
        const float* src = ALoader<AMODE>::ptr(A, m0 + row, kb + kc, K);
        cp_async16(smem_stage + (uint32_t)(row * LDA_S + kc) * 4u, src);
    }
    const uint32_t bs = smem_stage + (uint32_t)(BM * LDA_S) * 4u;
#pragma unroll
    for (int i = 0; i < 4; i++) {                // B: 32x256 = 2048 chunks / 512 thr
        int c = i * GTH + threadIdx.x;
        int row = c >> 6, col = (c & 63) << 2;
        cp_async16(bs + (uint32_t)(row * LDB_S + col) * 4u,
                   B + (size_t)(kb + row) * ldb + nb + col);
    }
}

__device__ __forceinline__ void gemm_compute_stage(
    const float* __restrict__ st, int wm, int wn, float acc[4][4][4]) {
    const int lane = threadIdx.x & 31;
    const int g = lane >> 2, tg = lane & 3;
    const float* As = st;
    const float* Bs = st + BM * LDA_S;
#pragma unroll
    for (int kk = 0; kk < BK; kk += 8) {
        uint32_t af[4][4];
#pragma unroll
        for (int mt = 0; mt < 4; mt++) {
            const float* ar = As + (wm + mt * 16 + g) * LDA_S + kk + tg;
            af[mt][0] = __float_as_uint(ar[0]);
            af[mt][1] = __float_as_uint(ar[8 * LDA_S]);
            af[mt][2] = __float_as_uint(ar[4]);
            af[mt][3] = __float_as_uint(ar[8 * LDA_S + 4]);
        }
        uint32_t bf[4][2];
#pragma unroll
        for (int nt = 0; nt < 4; nt++) {
            const float* br = Bs + (kk + tg) * LDB_S + wn + nt * 8 + g;
            bf[nt][0] = __float_as_uint(br[0]);
            bf[nt][1] = __float_as_uint(br[4 * LDB_S]);
        }
#pragma unroll
        for (int mt = 0; mt < 4; mt++)
#pragma unroll
            for (int nt = 0; nt < 4; nt++)
                mma_tf32(acc[mt][nt], af[mt], bf[nt][0], bf[nt][1]);
    }
}

// ---- standard output: C row-major (ldc = N), optional bias + residual -----
template <int AMODE>
__global__ __launch_bounds__(GTH, 1)
void gemm3_kernel(const float* __restrict__ A, const float* __restrict__ B,
                  float* __restrict__ C, int M, int N, int K,
                  const float* __restrict__ bias, const float* __restrict__ res) {
    extern __shared__ float sm[];
    const uint32_t smem_u = (uint32_t)__cvta_generic_to_shared(sm);
    const int tid = threadIdx.x, wid = tid >> 5, lane = tid & 31;
    const int g = lane >> 2, tg = lane & 3;
    const int m0 = blockIdx.y * BM;
    const int n0 = blockIdx.x * BN;
    const int wm = (wid & 1) * 64;     // 2 warp-rows of 64
    const int wn = (wid >> 1) * 32;    // 8 warp-cols of 32

    float acc[4][4][4];
#pragma unroll
    for (int i = 0; i < 4; i++)
#pragma unroll
        for (int j = 0; j < 4; j++)
#pragma unroll
            for (int k = 0; k < 4; k++) acc[i][j][k] = 0.f;

    const int T = K / BK;
    gemm_load_stage<AMODE>(A, B, N, m0, n0, 0, K, smem_u);
    cp_commit();
    gemm_load_stage<AMODE>(A, B, N, m0, n0, BK, K, smem_u + STAGE_F * 4);
    cp_commit();

    int s = 0;
    for (int kt = 0; kt < T; kt++) {
        cp_wait1();
        __syncthreads();
        if (kt + 2 < T) {
            int s2 = (s + 2 >= STAGES) ? s + 2 - STAGES : s + 2;
            gemm_load_stage<AMODE>(A, B, N, m0, n0, (kt + 2) * BK, K,
                                   smem_u + (uint32_t)s2 * STAGE_F * 4);
        }
        cp_commit();
        gemm_compute_stage(sm + s * STAGE_F, wm, wn, acc);
        s = (s + 1 == STAGES) ? 0 : s + 1;
    }

#pragma unroll
    for (int mt = 0; mt < 4; mt++) {
        const int r0 = m0 + wm + mt * 16 + g;
        const int r1 = r0 + 8;
#pragma unroll
        for (int nt = 0; nt < 4; nt++) {
            const int c = n0 + wn + nt * 8 + 2 * tg;
            float2 v0 = make_float2(acc[mt][nt][0], acc[mt][nt][1]);
            float2 v1 = make_float2(acc[mt][nt][2], acc[mt][nt][3]);
            if (bias) {
                float2 bb = *reinterpret_cast<const float2*>(bias + c);
                v0.x += bb.x; v0.y += bb.y; v1.x += bb.x; v1.y += bb.y;
            }
            if (res) {
                float2 q0r = *reinterpret_cast<const float2*>(res + (size_t)r0 * N + c);
                float2 q1r = *reinterpret_cast<const float2*>(res + (size_t)r1 * N + c);
                v0.x += q0r.x; v0.y += q0r.y; v1.x += q1r.x; v1.y += q1r.y;
            }
            *reinterpret_cast<float2*>(C + (size_t)r0 * N + c) = v0;
            *reinterpret_cast<float2*>(C + (size_t)r1 * N + c) = v1;
        }
    }
}

// ---- fused QKV: one GEMM over N=3072, scatter into q_bh/k_bh/v_bh ---------
__global__ __launch_bounds__(GTH, 1)
void gemm_qkv_kernel(const float* __restrict__ A, const float* __restrict__ W,
                     float* __restrict__ Cq, float* __restrict__ Ck,
                     float* __restrict__ Cv) {
    extern __shared__ float sm[];
    const uint32_t smem_u = (uint32_t)__cvta_generic_to_shared(sm);
    const int tid = threadIdx.x, wid = tid >> 5, lane = tid & 31;
    const int g = lane >> 2, tg = lane & 3;
    const int m0 = blockIdx.y * BM;
    const int arr = blockIdx.x >> 2;                 // 0..2 : which weight/output
    const int nb  = (blockIdx.x & 3) * BN;           // column base within the array
    const float* B = W + (size_t)arr * DMOD * DMOD;  // Wq/Wk/Wv pre-rounded, contiguous
    float* C = (arr == 0) ? Cq : (arr == 1) ? Ck : Cv;
    const int wm = (wid & 1) * 64;
    const int wn = (wid >> 1) * 32;
    const int K = DMOD;

    float acc[4][4][4];
#pragma unroll
    for (int i = 0; i < 4; i++)
#pragma unroll
        for (int j = 0; j < 4; j++)
#pragma unroll
            for (int k = 0; k < 4; k++) acc[i][j][k] = 0.f;

    const int T = K / BK;
    gemm_load_stage<0>(A, B, DMOD, m0, nb, 0, K, smem_u);
    cp_commit();
    gemm_load_stage<0>(A, B, DMOD, m0, nb, BK, K, smem_u + STAGE_F * 4);
    cp_commit();

    int s = 0;
    for (int kt = 0; kt < T; kt++) {
        cp_wait1();
        __syncthreads();
        if (kt + 2 < T) {
            int s2 = (s + 2 >= STAGES) ? s + 2 - STAGES : s + 2;
            gemm_load_stage<0>(A, B, DMOD, m0, nb, (kt + 2) * BK, K,
                               smem_u + (uint32_t)s2 * STAGE_F * 4);
        }
        cp_commit();
        gemm_compute_stage(sm + s * STAGE_F, wm, wn, acc);
        s = (s + 1 == STAGES) ? 0 : s + 1;
    }

    // scatter to (B*H, TOK, DHD)
#pragma unroll
    for (int mt = 0; mt < 4; mt++) {
        const int r0 = m0 + wm + mt * 16 + g;
        const int r1 = r0 + 8;
        const int b0_ = r0 >> 11, n0_ = r0 & (TOK - 1);
        const int b1_ = r1 >> 11, n1_ = r1 & (TOK - 1);
#pragma unroll
        for (int nt = 0; nt < 4; nt++) {
            const int cl = nb + wn + nt * 8 + 2 * tg;
            const int hh = cl >> 6, dd = cl & (DHD - 1);
            float2 v0 = make_float2(acc[mt][nt][0], acc[mt][nt][1]);
            float2 v1 = make_float2(acc[mt][nt][2], acc[mt][nt][3]);
            *reinterpret_cast<float2*>(
                C + ((size_t)(b0_ * NH + hh) * TOK + n0_) * DHD + dd) = v0;
            *reinterpret_cast<float2*>(
                C + ((size_t)(b1_ * NH + hh) * TOK + n1_) * DHD + dd) = v1;
        }
    }
}

// ---------------- flash attention (per (b,h); BM=128, DH=64) ---------------
// Writes exact inter_out to Op (output) and tf32-rounded copy to Opr (GEMM A).
__global__ __launch_bounds__(256)
void flash_attn_kernel(const float* __restrict__ Q, const float* __restrict__ Kg,
                       const float* __restrict__ V, float* __restrict__ O,
                       float* __restrict__ Or) {
    extern __shared__ float sm[];
    float(*Ks)[DHD + 4] = reinterpret_cast<float(*)[DHD + 4]>(sm);
    float(*Vs)[DHD + 4] = reinterpret_cast<float(*)[DHD + 4]>(sm + 128 * (DHD + 4));

    const int tid = threadIdx.x, wid = tid >> 5, lane = tid & 31;
    const int g = lane >> 2, tg = lane & 3;
    const int bh = blockIdx.y;
    const int q0 = blockIdx.x * 128;
    const float* Qp = Q + (size_t)bh * TOK * DHD;
    const float* Kp = Kg + (size_t)bh * TOK * DHD;
    const float* Vp = V + (size_t)bh * TOK * DHD;
    float* Op  = O  + (size_t)bh * TOK * DHD;
    float* Opr = Or + (size_t)bh * TOK * DHD;
    const int wm = wid * 16;
    const int r0 = q0 + wm + g, r1 = r0 + 8;

    uint32_t qf[8][4];
#pragma unroll
    for (int ks = 0; ks < 8; ks++) {
        int c = ks * 8 + tg;
        qf[ks][0] = f2tf32(Qp[(size_t)r0 * DHD + c] * 0.125f);
        qf[ks][1] = f2tf32(Qp[(size_t)r1 * DHD + c] * 0.125f);
        qf[ks][2] = f2tf32(Qp[(size_t)r0 * DHD + c + 4] * 0.125f);
        qf[ks][3] = f2tf32(Qp[(size_t)r1 * DHD + c + 4] * 0.125f);
    }

    float m0 = -1e30f, m1 = -1e30f, l0 = 0.f, l1 = 0.f;
    float o[8][4];
#pragma unroll
    for (int i = 0; i < 8; i++)
#pragma unroll
        for (int j = 0; j < 4; j++) o[i][j] = 0.f;

    for (int j = 0; j < TOK; j += 128) {
        __syncthreads();
#pragma unroll
        for (int i = 0; i < 8; i++) {
            int s = tid + i * 256;
            int r = s >> 4, c = (s & 15) << 2;
            float4 kv = *reinterpret_cast<const float4*>(Kp + (size_t)(j + r) * DHD + c);
            float4 vv = *reinterpret_cast<const float4*>(Vp + (size_t)(j + r) * DHD + c);
            float4 kc = make_float4(f2tf32f(kv.x), f2tf32f(kv.y), f2tf32f(kv.z), f2tf32f(kv.w));
            float4 vc = make_float4(f2tf32f(vv.x), f2tf32f(vv.y), f2tf32f(vv.z), f2tf32f(vv.w));
            *reinterpret_cast<float4*>(&Ks[r][c]) = kc;
            *reinterpret_cast<float4*>(&Vs[r][c]) = vc;
        }
        __syncthreads();

        float sc[16][4];
#pragma unroll
        for (int nt = 0; nt < 16; nt++)
#pragma unroll
            for (int k4 = 0; k4 < 4; k4++) sc[nt][k4] = 0.f;
#pragma unroll
        for (int ks = 0; ks < 8; ks++) {
#pragma unroll
            for (int nt = 0; nt < 16; nt++) {
                uint32_t b0 = __float_as_uint(Ks[nt * 8 + g][ks * 8 + tg]);
                uint32_t b1 = __float_as_uint(Ks[nt * 8 + g][ks * 8 + tg + 4]);
                mma_tf32(sc[nt], qf[ks], b0, b1);
            }
        }

        float tm0 = -1e30f, tm1 = -1e30f;
#pragma unroll
        for (int nt = 0; nt < 16; nt++) {
            tm0 = fmaxf(tm0, fmaxf(sc[nt][0], sc[nt][1]));
            tm1 = fmaxf(tm1, fmaxf(sc[nt][2], sc[nt][3]));
        }
        tm0 = fmaxf(tm0, __shfl_xor_sync(0xffffffffu, tm0, 1));
        tm0 = fmaxf(tm0, __shfl_xor_sync(0xffffffffu, tm0, 2));
        tm1 = fmaxf(tm1, __shfl_xor_sync(0xffffffffu, tm1, 1));
        tm1 = fmaxf(tm1, __shfl_xor_sync(0xffffffffu, tm1, 2));
        const float nm0 = fmaxf(m0, tm0), nm1 = fmaxf(m1, tm1);
        const float a0 = __expf(m0 - nm0), a1 = __expf(m1 - nm1);
        float ts0 = 0.f, ts1 = 0.f;
#pragma unroll
        for (int nt = 0; nt < 16; nt++) {
            float p0 = __expf(sc[nt][0] - nm0);
            float p1 = __expf(sc[nt][1] - nm0);
            float p2 = __expf(sc[nt][2] - nm1);
            float p3 = __expf(sc[nt][3] - nm1);
            ts0 += p0 + p1; ts1 += p2 + p3;
            sc[nt][0] = f2tf32f(p0); sc[nt][1] = f2tf32f(p1);
            sc[nt][2] = f2tf32f(p2); sc[nt][3] = f2tf32f(p3);
        }
        ts0 += __shfl_xor_sync(0xffffffffu, ts0, 1);
        ts0 += __shfl_xor_sync(0xffffffffu, ts0, 2);
        ts1 += __shfl_xor_sync(0xffffffffu, ts1, 1);
        ts1 += __shfl_xor_sync(0xffffffffu, ts1, 2);
        l0 = l0 * a0 + ts0; l1 = l1 * a1 + ts1;
        m0 = nm0; m1 = nm1;
#pragma unroll
        for (int nt = 0; nt < 8; nt++) {
            o[nt][0] *= a0; o[nt][1] *= a0; o[nt][2] *= a1; o[nt][3] *= a1;
        }

        const int qb = lane & ~3;
        const int srcA = qb + (tg >> 1);
        const int srcB = srcA + 2;
        const bool odd = (tg & 1);
#pragma unroll
        for (int kt = 0; kt < 16; kt++) {
            float p0 = sc[kt][0], p1 = sc[kt][1], p2 = sc[kt][2], p3 = sc[kt][3];
            float e0 = __shfl_sync(0xffffffffu, p0, srcA);
            float e1 = __shfl_sync(0xffffffffu, p1, srcA);
            float e2 = __shfl_sync(0xffffffffu, p2, srcA);
            float e3 = __shfl_sync(0xffffffffu, p3, srcA);
            float h0 = __shfl_sync(0xffffffffu, p0, srcB);
            float h1 = __shfl_sync(0xffffffffu, p1, srcB);
            float h2 = __shfl_sync(0xffffffffu, p2, srcB);
            float h3 = __shfl_sync(0xffffffffu, p3, srcB);
            uint32_t af[4];
            af[0] = __float_as_uint(odd ? e1 : e0);
            af[1] = __float_as_uint(odd ? e3 : e2);
            af[2] = __float_as_uint(odd ? h1 : h0);
            af[3] = __float_as_uint(odd ? h3 : h2);
#pragma unroll
            for (int nt = 0; nt < 8; nt++) {
                uint32_t b0 = __float_as_uint(Vs[kt * 8 + tg][nt * 8 + g]);
                uint32_t b1 = __float_as_uint(Vs[kt * 8 + tg + 4][nt * 8 + g]);
                mma_tf32(o[nt], af, b0, b1);
            }
        }
    }

    const float il0 = 1.f / l0, il1 = 1.f / l1;
#pragma unroll
    for (int nt = 0; nt < 8; nt++) {
        int c = nt * 8 + 2 * tg;
        float2 v0 = make_float2(o[nt][0] * il0, o[nt][1] * il0);
        float2 v1 = make_float2(o[nt][2] * il1, o[nt][3] * il1);
        *reinterpret_cast<float2*>(Op + (size_t)r0 * DHD + c) = v0;
        *reinterpret_cast<float2*>(Op + (size_t)r1 * DHD + c) = v1;
        float2 r0v = make_float2(f2tf32f(v0.x), f2tf32f(v0.y));
        float2 r1v = make_float2(f2tf32f(v1.x), f2tf32f(v1.y));
        *reinterpret_cast<float2*>(Opr + (size_t)r0 * DHD + c) = r0v;
        *reinterpret_cast<float2*>(Opr + (size_t)r1 * DHD + c) = r1v;
    }
}

// ---------------- GEGLU (output tf32-rounded; it only feeds FF2 GEMM) ------
__global__ __launch_bounds__(256)
void geglu_kernel(const float* __restrict__ h, float* __restrict__ act) {
    const int idx = blockIdx.x * 256 + threadIdx.x;
    const int m = idx >> 10;
    const int c = (idx & 1023) << 2;
    const float4 a  = *reinterpret_cast<const float4*>(h + (size_t)m * (2 * FF) + c);
    const float4 gt = *reinterpret_cast<const float4*>(h + (size_t)m * (2 * FF) + FF + c);
    float4 o;
    o.x = f2tf32f(a.x * gelu_exact(gt.x));
    o.y = f2tf32f(a.y * gelu_exact(gt.y));
    o.z = f2tf32f(a.z * gelu_exact(gt.z));
    o.w = f2tf32f(a.w * gelu_exact(gt.w));
    *reinterpret_cast<float4*>(act + (size_t)m * FF + c) = o;
}

// ---------------- launch ---------------------------------------------------
extern "C" void kernel_launch(void* const* d_in, const int* in_sizes, int n_in,
                              void* d_out, int out_size) {
    (void)in_sizes; (void)n_in; (void)out_size;
    const float* x     = (const float*)d_in[0];
    const float* Wq    = (const float*)d_in[1];
    const float* Wk    = (const float*)d_in[2];
    const float* Wv    = (const float*)d_in[3];
    const float* Wo    = (const float*)d_in[4];
    const float* bo    = (const float*)d_in[5];
    const float* ln1_g = (const float*)d_in[6];
    const float* ln1_b = (const float*)d_in[7];
    const float* ln3_g = (const float*)d_in[8];
    const float* ln3_b = (const float*)d_in[9];
    const float* Wff1  = (const float*)d_in[10];
    const float* bff1  = (const float*)d_in[11];
    const float* Wff2  = (const float*)d_in[12];
    const float* bff2  = (const float*)d_in[13];

    float* out = (float*)d_out;
    const size_t SZ = (size_t)MROWS * DMOD;
    float* out_x  = out;            // x
    float* out_q  = out + SZ;       // q_bh
    float* out_k  = out + 2 * SZ;   // k_bh
    float* out_v  = out + 3 * SZ;   // v_bh
    float* out_io = out + 4 * SZ;   // inter_out
    float* out_xf = out + 5 * SZ;   // x_features

    float *x2, *xf2, *xfr, *ior, *hbuf, *actbuf, *wbuf;
    cudaGetSymbolAddress((void**)&x2,     g_x2);
    cudaGetSymbolAddress((void**)&xf2,    g_xf2);
    cudaGetSymbolAddress((void**)&xfr,    g_xfr);
    cudaGetSymbolAddress((void**)&ior,    g_ior);
    cudaGetSymbolAddress((void**)&hbuf,   g_h);
    cudaGetSymbolAddress((void**)&actbuf, g_act);
    cudaGetSymbolAddress((void**)&wbuf,   g_w);

    cudaFuncSetAttribute(gemm_qkv_kernel,
                         cudaFuncAttributeMaxDynamicSharedMemorySize, SMEM_GEMM);
    cudaFuncSetAttribute(gemm3_kernel<0>,
                         cudaFuncAttributeMaxDynamicSharedMemorySize, SMEM_GEMM);
    cudaFuncSetAttribute(gemm3_kernel<1>,
                         cudaFuncAttributeMaxDynamicSharedMemorySize, SMEM_GEMM);
    cudaFuncSetAttribute(flash_attn_kernel,
                         cudaFuncAttributeMaxDynamicSharedMemorySize,
                         2 * 128 * (DHD + 4) * (int)sizeof(float));

    const dim3 blk(GTH);

    // 0) pre-round all weights to tf32 (grouped launches)
    {
        const int n4_1m = (1024 * 1024) / 4;   // 262144
        cvt_tf32_kernel<<<(n4_1m + 255) / 256, 256>>>(
            (const float4*)Wq, (float4*)(wbuf + WOFF_Q), n4_1m);
        cvt_tf32_kernel<<<(n4_1m + 255) / 256, 256>>>(
            (const float4*)Wk, (float4*)(wbuf + WOFF_K), n4_1m);
        cvt_tf32_kernel<<<(n4_1m + 255) / 256, 256>>>(
            (const float4*)Wv, (float4*)(wbuf + WOFF_V), n4_1m);
        cvt_tf32_kernel<<<(n4_1m + 255) / 256, 256>>>(
            (const float4*)Wo, (float4*)(wbuf + WOFF_O), n4_1m);
        const int n4_ff1 = (8 * 1024 * 1024) / 4;
        cvt_tf32_kernel<<<(n4_ff1 + 255) / 256, 256>>>(
            (const float4*)Wff1, (float4*)(wbuf + WOFF_FF1), n4_ff1);
        const int n4_ff2 = (4 * 1024 * 1024) / 4;
        cvt_tf32_kernel<<<(n4_ff2 + 255) / 256, 256>>>(
            (const float4*)Wff2, (float4*)(wbuf + WOFF_FF2), n4_ff2);
    }

    // 1) LN1 -> x_features (exact) + rounded copy for GEMM A
    ln_kernel<<<MROWS, 256>>>(x, ln1_g, ln1_b, out_xf, xfr);

    // 2) fused QKV GEMM (N = 3072), scattered directly to (B*H, N, DH)
    gemm_qkv_kernel<<<dim3(3 * DMOD / BN, MROWS / BM), blk, SMEM_GEMM>>>(
        xfr, wbuf + WOFF_Q, out_q, out_k, out_v);

    // 3) attention -> inter_out (exact) + rounded copy
    const int smem_fa = 2 * 128 * (DHD + 4) * (int)sizeof(float);
    flash_attn_kernel<<<dim3(TOK / 128, NBAT * NH), 256, smem_fa>>>(
        out_q, out_k, out_v, out_io, ior);

    // 4) Wo GEMM (gather-A from rounded inter_out) + bo + residual x -> x2 (exact)
    gemm3_kernel<1><<<dim3(DMOD / BN, MROWS / BM), blk, SMEM_GEMM>>>(
        ior, wbuf + WOFF_O, x2, MROWS, DMOD, DMOD, bo, x);

    // 5) LN3 -> xf2 (rounded only; internal)
    ln_kernel<<<MROWS, 256>>>(x2, ln3_g, ln3_b, nullptr, xf2);

    // 6) FF1 GEMM (+bff1) -> h (exact; geglu needs exact gate)
    gemm3_kernel<0><<<dim3(2 * FF / BN, MROWS / BM), blk, SMEM_GEMM>>>(
        xf2, wbuf + WOFF_FF1, hbuf, MROWS, 2 * FF, DMOD, bff1, nullptr);

    // 7) GEGLU -> act (rounded)
    geglu_kernel<<<(MROWS * (FF / 4)) / 256, 256>>>(hbuf, actbuf);

    // 8) FF2 GEMM (+bff2) + residual x2 -> final x
    gemm3_kernel<0><<<dim3(DMOD / BN, MROWS / BM), blk, SMEM_GEMM>>>(
        actbuf, wbuf + WOFF_FF2, out_x, MROWS, DMOD, FF, bff2, x2);
}

// round 10
// speedup vs baseline: 1.0955x; 1.0327x over previous
#include <cuda_runtime.h>
#include <cstdint>
#include <cstdio>

#define TOK   2048
#define NBAT  2
#define NH    16
#define DHD   64
#define DMOD  1024
#define MROWS 4096   /* B*N */
#define FF    4096

// ---------------- scratch (static device globals; no runtime allocation) ---
__device__ float g_x2 [MROWS * DMOD];            // 16 MB : x after attn residual (exact)
__device__ float g_xf2[MROWS * DMOD];            // 16 MB : LN3 output (tf32-rounded)
__device__ float g_xfr[MROWS * DMOD];            // 16 MB : LN1 output (tf32-rounded)
__device__ float g_ior[MROWS * DMOD];            // 16 MB : inter_out (tf32-rounded)
__device__ float g_h  [(size_t)MROWS * 2 * FF];  // 128 MB: FF1 output (exact)
__device__ float g_act[(size_t)MROWS * FF];      // 64 MB : geglu output (tf32-rounded)
__device__ float g_w  [16 * 1024 * 1024];        // 64 MB : all weights, tf32-rounded
// offsets (floats) within g_w:
#define WOFF_Q    0
#define WOFF_K    (1024 * 1024)
#define WOFF_V    (2 * 1024 * 1024)
#define WOFF_O    (3 * 1024 * 1024)
#define WOFF_FF1  (4 * 1024 * 1024)
#define WOFF_FF2  (12 * 1024 * 1024)

// ---------------- helpers --------------------------------------------------
__device__ __forceinline__ uint32_t f2tf32(float x) {
    uint32_t t;
    asm("cvt.rna.tf32.f32 %0, %1;" : "=r"(t) : "f"(x));
    return t;
}
__device__ __forceinline__ float f2tf32f(float x) { return __uint_as_float(f2tf32(x)); }

__device__ __forceinline__ void mma_tf32(float c[4], const uint32_t a[4],
                                         uint32_t b0, uint32_t b1) {
    asm volatile(
        "mma.sync.aligned.m16n8k8.row.col.f32.tf32.tf32.f32 "
        "{%0,%1,%2,%3}, {%4,%5,%6,%7}, {%8,%9}, {%0,%1,%2,%3};\n"
        : "+f"(c[0]), "+f"(c[1]), "+f"(c[2]), "+f"(c[3])
        : "r"(a[0]), "r"(a[1]), "r"(a[2]), "r"(a[3]), "r"(b0), "r"(b1));
}

#define LDSM_X4(r0, r1, r2, r3, addr)                                         \
    asm volatile("ldmatrix.sync.aligned.m8n8.x4.shared.b16 {%0,%1,%2,%3}, [%4];" \
                 : "=r"(r0), "=r"(r1), "=r"(r2), "=r"(r3) : "r"(addr))

__device__ __forceinline__ void cp_async16(uint32_t dst, const void* src) {
    asm volatile("cp.async.cg.shared.global [%0], [%1], 16;\n" :: "r"(dst), "l"(src));
}
__device__ __forceinline__ void cp_commit() {
    asm volatile("cp.async.commit_group;\n" ::: "memory");
}
__device__ __forceinline__ void cp_wait1() {
    asm volatile("cp.async.wait_group 1;\n" ::: "memory");
}

__device__ __forceinline__ float gelu_exact(float x) {
    return 0.5f * x * (1.0f + erff(x * 0.70710678118654752f));
}

// ------------ one-shot weight pre-rounding (all 16M floats, one launch) -----
__global__ __launch_bounds__(256)
void cvt_weights_kernel(const float4* __restrict__ wq, const float4* __restrict__ wk,
                        const float4* __restrict__ wv, const float4* __restrict__ wo,
                        const float4* __restrict__ wff1, const float4* __restrict__ wff2,
                        float4* __restrict__ dst) {
    const int Q4 = (1024 * 1024) / 4;            // 262144 float4 per 1M floats
    int i = blockIdx.x * 256 + threadIdx.x;      // 0 .. 4M-1 float4
    const float4* src;
    int off;
    if      (i <      Q4) { src = wq;   off = 0;      }
    else if (i <  2 * Q4) { src = wk;   off = Q4;     }
    else if (i <  3 * Q4) { src = wv;   off = 2 * Q4; }
    else if (i <  4 * Q4) { src = wo;   off = 3 * Q4; }
    else if (i < 12 * Q4) { src = wff1; off = 4 * Q4; }
    else                  { src = wff2; off = 12 * Q4;}
    float4 v = src[i - off];
    dst[i] = make_float4(f2tf32f(v.x), f2tf32f(v.y), f2tf32f(v.z), f2tf32f(v.w));
}

// ---------------- LayerNorm (one block per row of 1024) --------------------
// y: exact output (nullable). yr: tf32-rounded output (nullable).
__global__ __launch_bounds__(256)
void ln_kernel(const float* __restrict__ x, const float* __restrict__ gw,
               const float* __restrict__ bw, float* __restrict__ y,
               float* __restrict__ yr) {
    __shared__ float red[16];
    const int row = blockIdx.x;
    const int tid = threadIdx.x;
    const float4 v = reinterpret_cast<const float4*>(x + (size_t)row * DMOD)[tid];
    float s  = v.x + v.y + v.z + v.w;
    float ss = v.x * v.x + v.y * v.y + v.z * v.z + v.w * v.w;
#pragma unroll
    for (int o = 16; o > 0; o >>= 1) {
        s  += __shfl_xor_sync(0xffffffffu, s,  o);
        ss += __shfl_xor_sync(0xffffffffu, ss, o);
    }
    if ((tid & 31) == 0) { red[tid >> 5] = s; red[8 + (tid >> 5)] = ss; }
    __syncthreads();
    float ts = 0.f, tss = 0.f;
#pragma unroll
    for (int w = 0; w < 8; w++) { ts += red[w]; tss += red[8 + w]; }
    const float mu  = ts * (1.0f / DMOD);
    const float var = tss * (1.0f / DMOD) - mu * mu;
    const float rs  = rsqrtf(var + 1e-5f);
    const float4 gv = reinterpret_cast<const float4*>(gw)[tid];
    const float4 bv = reinterpret_cast<const float4*>(bw)[tid];
    float4 o;
    o.x = (v.x - mu) * rs * gv.x + bv.x;
    o.y = (v.y - mu) * rs * gv.y + bv.y;
    o.z = (v.z - mu) * rs * gv.z + bv.z;
    o.w = (v.w - mu) * rs * gv.w + bv.w;
    if (y)  reinterpret_cast<float4*>(y  + (size_t)row * DMOD)[tid] = o;
    if (yr) {
        float4 r = make_float4(f2tf32f(o.x), f2tf32f(o.y), f2tf32f(o.z), f2tf32f(o.w));
        reinterpret_cast<float4*>(yr + (size_t)row * DMOD)[tid] = r;
    }
}

// -- TF32 GEMM v5: CTA 128x256, 512 thr, warp 64x32, cp.async 3-stage, LDSM A
constexpr int BM = 128, BN = 256, BK = 32, STAGES = 3;
constexpr int GTH = 512;                                       // GEMM threads
constexpr int LDA_S = 36, LDB_S = 264;
constexpr int STAGE_F = BM * LDA_S + BK * LDB_S;               // 13056 floats
constexpr int SMEM_GEMM = STAGES * STAGE_F * 4;                // 156672 bytes

// AMODE 0: A row-major [M][K].  AMODE 1: A gathered from inter_out (B,H,TOK,DHD).
template <int AMODE>
struct ALoader {
    static __device__ __forceinline__ const float* ptr(const float* A, int gm, int gk, int K) {
        if (AMODE == 0) return A + (size_t)gm * K + gk;
        int bb = gm >> 11, nn = gm & (TOK - 1);
        int hh = gk >> 6,  dd = gk & (DHD - 1);
        return A + (((size_t)(bb * NH + hh) * TOK + nn) * DHD + dd);
    }
};

template <int AMODE>
__device__ __forceinline__ void gemm_load_stage(
    const float* __restrict__ A, const float* __restrict__ B, int ldb,
    int m0, int nb, int kb, int K, uint32_t smem_stage) {
#pragma unroll
    for (int i = 0; i < 2; i++) {                // A: 128x32 = 1024 chunks / 512 thr
        int c = i * GTH + threadIdx.x;
        int row = c >> 3, kc = (c & 7) << 2;
        const float* src = ALoader<AMODE>::ptr(A, m0 + row, kb + kc, K);
        cp_async16(smem_stage + (uint32_t)(row * LDA_S + kc) * 4u, src);
    }
    const uint32_t bs = smem_stage + (uint32_t)(BM * LDA_S) * 4u;
#pragma unroll
    for (int i = 0; i < 4; i++) {                // B: 32x256 = 2048 chunks / 512 thr
        int c = i * GTH + threadIdx.x;
        int row = c >> 6, col = (c & 63) << 2;
        cp_async16(bs + (uint32_t)(row * LDB_S + col) * 4u,
                   B + (size_t)(kb + row) * ldb + nb + col);
    }
}

// A fragments via ldmatrix.x4 (one per mt per kk); B via LDS.32.
__device__ __forceinline__ void gemm_compute_stage(
    uint32_t st_u, const float* __restrict__ st, int wm, int wn,
    float acc[4][4][4]) {
    const int lane = threadIdx.x & 31;
    const int g = lane >> 2, tg = lane & 3;
    // ldmatrix row/col per-thread address (bytes), matrix layout of m16n8k8 A frag
    const uint32_t a_base = st_u +
        (uint32_t)((wm + (lane & 15)) * LDA_S + ((lane >> 4) << 2)) * 4u;
    const float* Bs = st + BM * LDA_S;
#pragma unroll
    for (int kk = 0; kk < BK; kk += 8) {
        uint32_t af[4][4];
#pragma unroll
        for (int mt = 0; mt < 4; mt++) {
            LDSM_X4(af[mt][0], af[mt][1], af[mt][2], af[mt][3],
                    a_base + (uint32_t)(mt * 16 * LDA_S + kk) * 4u);
        }
        uint32_t bf[4][2];
#pragma unroll
        for (int nt = 0; nt < 4; nt++) {
            const float* br = Bs + (kk + tg) * LDB_S + wn + nt * 8 + g;
            bf[nt][0] = __float_as_uint(br[0]);
            bf[nt][1] = __float_as_uint(br[4 * LDB_S]);
        }
#pragma unroll
        for (int mt = 0; mt < 4; mt++)
#pragma unroll
            for (int nt = 0; nt < 4; nt++)
                mma_tf32(acc[mt][nt], af[mt], bf[nt][0], bf[nt][1]);
    }
}

// ---- standard output: C row-major (ldc = N), optional bias + residual -----
template <int AMODE>
__global__ __launch_bounds__(GTH, 1)
void gemm3_kernel(const float* __restrict__ A, const float* __restrict__ B,
                  float* __restrict__ C, int M, int N, int K,
                  const float* __restrict__ bias, const float* __restrict__ res) {
    extern __shared__ float sm[];
    const uint32_t smem_u = (uint32_t)__cvta_generic_to_shared(sm);
    const int tid = threadIdx.x, wid = tid >> 5, lane = tid & 31;
    const int g = lane >> 2, tg = lane & 3;
    const int m0 = blockIdx.y * BM;
    const int n0 = blockIdx.x * BN;
    const int wm = (wid & 1) * 64;     // 2 warp-rows of 64
    const int wn = (wid >> 1) * 32;    // 8 warp-cols of 32

    float acc[4][4][4];
#pragma unroll
    for (int i = 0; i < 4; i++)
#pragma unroll
        for (int j = 0; j < 4; j++)
#pragma unroll
            for (int k = 0; k < 4; k++) acc[i][j][k] = 0.f;

    const int T = K / BK;
    gemm_load_stage<AMODE>(A, B, N, m0, n0, 0, K, smem_u);
    cp_commit();
    gemm_load_stage<AMODE>(A, B, N, m0, n0, BK, K, smem_u + STAGE_F * 4);
    cp_commit();

    int s = 0;
    for (int kt = 0; kt < T; kt++) {
        cp_wait1();
        __syncthreads();
        if (kt + 2 < T) {
            int s2 = (s + 2 >= STAGES) ? s + 2 - STAGES : s + 2;
            gemm_load_stage<AMODE>(A, B, N, m0, n0, (kt + 2) * BK, K,
                                   smem_u + (uint32_t)s2 * STAGE_F * 4);
        }
        cp_commit();
        gemm_compute_stage(smem_u + (uint32_t)s * STAGE_F * 4, sm + s * STAGE_F,
                           wm, wn, acc);
        s = (s + 1 == STAGES) ? 0 : s + 1;
    }

#pragma unroll
    for (int mt = 0; mt < 4; mt++) {
        const int r0 = m0 + wm + mt * 16 + g;
        const int r1 = r0 + 8;
#pragma unroll
        for (int nt = 0; nt < 4; nt++) {
            const int c = n0 + wn + nt * 8 + 2 * tg;
            float2 v0 = make_float2(acc[mt][nt][0], acc[mt][nt][1]);
            float2 v1 = make_float2(acc[mt][nt][2], acc[mt][nt][3]);
            if (bias) {
                float2 bb = *reinterpret_cast<const float2*>(bias + c);
                v0.x += bb.x; v0.y += bb.y; v1.x += bb.x; v1.y += bb.y;
            }
            if (res) {
                float2 q0r = *reinterpret_cast<const float2*>(res + (size_t)r0 * N + c);
                float2 q1r = *reinterpret_cast<const float2*>(res + (size_t)r1 * N + c);
                v0.x += q0r.x; v0.y += q0r.y; v1.x += q1r.x; v1.y += q1r.y;
            }
            *reinterpret_cast<float2*>(C + (size_t)r0 * N + c) = v0;
            *reinterpret_cast<float2*>(C + (size_t)r1 * N + c) = v1;
        }
    }
}

// ---- fused QKV: one GEMM over N=3072, scatter into q_bh/k_bh/v_bh ---------
__global__ __launch_bounds__(GTH, 1)
void gemm_qkv_kernel(const float* __restrict__ A, const float* __restrict__ W,
                     float* __restrict__ Cq, float* __restrict__ Ck,
                     float* __restrict__ Cv) {
    extern __shared__ float sm[];
    const uint32_t smem_u = (uint32_t)__cvta_generic_to_shared(sm);
    const int tid = threadIdx.x, wid = tid >> 5, lane = tid & 31;
    const int g = lane >> 2, tg = lane & 3;
    const int m0 = blockIdx.y * BM;
    const int arr = blockIdx.x >> 2;                 // 0..2 : which weight/output
    const int nb  = (blockIdx.x & 3) * BN;           // column base within the array
    const float* B = W + (size_t)arr * DMOD * DMOD;  // Wq/Wk/Wv pre-rounded, contiguous
    float* C = (arr == 0) ? Cq : (arr == 1) ? Ck : Cv;
    const int wm = (wid & 1) * 64;
    const int wn = (wid >> 1) * 32;
    const int K = DMOD;

    float acc[4][4][4];
#pragma unroll
    for (int i = 0; i < 4; i++)
#pragma unroll
        for (int j = 0; j < 4; j++)
#pragma unroll
            for (int k = 0; k < 4; k++) acc[i][j][k] = 0.f;

    const int T = K / BK;
    gemm_load_stage<0>(A, B, DMOD, m0, nb, 0, K, smem_u);
    cp_commit();
    gemm_load_stage<0>(A, B, DMOD, m0, nb, BK, K, smem_u + STAGE_F * 4);
    cp_commit();

    int s = 0;
    for (int kt = 0; kt < T; kt++) {
        cp_wait1();
        __syncthreads();
        if (kt + 2 < T) {
            int s2 = (s + 2 >= STAGES) ? s + 2 - STAGES : s + 2;
            gemm_load_stage<0>(A, B, DMOD, m0, nb, (kt + 2) * BK, K,
                               smem_u + (uint32_t)s2 * STAGE_F * 4);
        }
        cp_commit();
        gemm_compute_stage(smem_u + (uint32_t)s * STAGE_F * 4, sm + s * STAGE_F,
                           wm, wn, acc);
        s = (s + 1 == STAGES) ? 0 : s + 1;
    }

    // scatter to (B*H, TOK, DHD)
#pragma unroll
    for (int mt = 0; mt < 4; mt++) {
        const int r0 = m0 + wm + mt * 16 + g;
        const int r1 = r0 + 8;
        const int b0_ = r0 >> 11, n0_ = r0 & (TOK - 1);
        const int b1_ = r1 >> 11, n1_ = r1 & (TOK - 1);
#pragma unroll
        for (int nt = 0; nt < 4; nt++) {
            const int cl = nb + wn + nt * 8 + 2 * tg;
            const int hh = cl >> 6, dd = cl & (DHD - 1);
            float2 v0 = make_float2(acc[mt][nt][0], acc[mt][nt][1]);
            float2 v1 = make_float2(acc[mt][nt][2], acc[mt][nt][3]);
            *reinterpret_cast<float2*>(
                C + ((size_t)(b0_ * NH + hh) * TOK + n0_) * DHD + dd) = v0;
            *reinterpret_cast<float2*>(
                C + ((size_t)(b1_ * NH + hh) * TOK + n1_) * DHD + dd) = v1;
        }
    }
}

// ---------------- flash attention (per (b,h); BM=128, DH=64) ---------------
// Writes exact inter_out to Op (output) and tf32-rounded copy to Opr (GEMM A).
__global__ __launch_bounds__(256)
void flash_attn_kernel(const float* __restrict__ Q, const float* __restrict__ Kg,
                       const float* __restrict__ V, float* __restrict__ O,
                       float* __restrict__ Or) {
    extern __shared__ float sm[];
    float(*Ks)[DHD + 4] = reinterpret_cast<float(*)[DHD + 4]>(sm);
    float(*Vs)[DHD + 4] = reinterpret_cast<float(*)[DHD + 4]>(sm + 128 * (DHD + 4));

    const int tid = threadIdx.x, wid = tid >> 5, lane = tid & 31;
    const int g = lane >> 2, tg = lane & 3;
    const int bh = blockIdx.y;
    const int q0 = blockIdx.x * 128;
    const float* Qp = Q + (size_t)bh * TOK * DHD;
    const float* Kp = Kg + (size_t)bh * TOK * DHD;
    const float* Vp = V + (size_t)bh * TOK * DHD;
    float* Op  = O  + (size_t)bh * TOK * DHD;
    float* Opr = Or + (size_t)bh * TOK * DHD;
    const int wm = wid * 16;
    const int r0 = q0 + wm + g, r1 = r0 + 8;

    uint32_t qf[8][4];
#pragma unroll
    for (int ks = 0; ks < 8; ks++) {
        int c = ks * 8 + tg;
        qf[ks][0] = f2tf32(Qp[(size_t)r0 * DHD + c] * 0.125f);
        qf[ks][1] = f2tf32(Qp[(size_t)r1 * DHD + c] * 0.125f);
        qf[ks][2] = f2tf32(Qp[(size_t)r0 * DHD + c + 4] * 0.125f);
        qf[ks][3] = f2tf32(Qp[(size_t)r1 * DHD + c + 4] * 0.125f);
    }

    float m0 = -1e30f, m1 = -1e30f, l0 = 0.f, l1 = 0.f;
    float o[8][4];
#pragma unroll
    for (int i = 0; i < 8; i++)
#pragma unroll
        for (int j = 0; j < 4; j++) o[i][j] = 0.f;

    for (int j = 0; j < TOK; j += 128) {
        __syncthreads();
#pragma unroll
        for (int i = 0; i < 8; i++) {
            int s = tid + i * 256;
            int r = s >> 4, c = (s & 15) << 2;
            float4 kv = *reinterpret_cast<const float4*>(Kp + (size_t)(j + r) * DHD + c);
            float4 vv = *reinterpret_cast<const float4*>(Vp + (size_t)(j + r) * DHD + c);
            float4 kc = make_float4(f2tf32f(kv.x), f2tf32f(kv.y), f2tf32f(kv.z), f2tf32f(kv.w));
            float4 vc = make_float4(f2tf32f(vv.x), f2tf32f(vv.y), f2tf32f(vv.z), f2tf32f(vv.w));
            *reinterpret_cast<float4*>(&Ks[r][c]) = kc;
            *reinterpret_cast<float4*>(&Vs[r][c]) = vc;
        }
        __syncthreads();

        float sc[16][4];
#pragma unroll
        for (int nt = 0; nt < 16; nt++)
#pragma unroll
            for (int k4 = 0; k4 < 4; k4++) sc[nt][k4] = 0.f;
#pragma unroll
        for (int ks = 0; ks < 8; ks++) {
#pragma unroll
            for (int nt = 0; nt < 16; nt++) {
                uint32_t b0 = __float_as_uint(Ks[nt * 8 + g][ks * 8 + tg]);
                uint32_t b1 = __float_as_uint(Ks[nt * 8 + g][ks * 8 + tg + 4]);
                mma_tf32(sc[nt], qf[ks], b0, b1);
            }
        }

        float tm0 = -1e30f, tm1 = -1e30f;
#pragma unroll
        for (int nt = 0; nt < 16; nt++) {
            tm0 = fmaxf(tm0, fmaxf(sc[nt][0], sc[nt][1]));
            tm1 = fmaxf(tm1, fmaxf(sc[nt][2], sc[nt][3]));
        }
        tm0 = fmaxf(tm0, __shfl_xor_sync(0xffffffffu, tm0, 1));
        tm0 = fmaxf(tm0, __shfl_xor_sync(0xffffffffu, tm0, 2));
        tm1 = fmaxf(tm1, __shfl_xor_sync(0xffffffffu, tm1, 1));
        tm1 = fmaxf(tm1, __shfl_xor_sync(0xffffffffu, tm1, 2));
        const float nm0 = fmaxf(m0, tm0), nm1 = fmaxf(m1, tm1);
        const float a0 = __expf(m0 - nm0), a1 = __expf(m1 - nm1);
        float ts0 = 0.f, ts1 = 0.f;
#pragma unroll
        for (int nt = 0; nt < 16; nt++) {
            float p0 = __expf(sc[nt][0] - nm0);
            float p1 = __expf(sc[nt][1] - nm0);
            float p2 = __expf(sc[nt][2] - nm1);
            float p3 = __expf(sc[nt][3] - nm1);
            ts0 += p0 + p1; ts1 += p2 + p3;
            sc[nt][0] = f2tf32f(p0); sc[nt][1] = f2tf32f(p1);
            sc[nt][2] = f2tf32f(p2); sc[nt][3] = f2tf32f(p3);
        }
        ts0 += __shfl_xor_sync(0xffffffffu, ts0, 1);
        ts0 += __shfl_xor_sync(0xffffffffu, ts0, 2);
        ts1 += __shfl_xor_sync(0xffffffffu, ts1, 1);
        ts1 += __shfl_xor_sync(0xffffffffu, ts1, 2);
        l0 = l0 * a0 + ts0; l1 = l1 * a1 + ts1;
        m0 = nm0; m1 = nm1;
#pragma unroll
        for (int nt = 0; nt < 8; nt++) {
            o[nt][0] *= a0; o[nt][1] *= a0; o[nt][2] *= a1; o[nt][3] *= a1;
        }

        const int qb = lane & ~3;
        const int srcA = qb + (tg >> 1);
        const int srcB = srcA + 2;
        const bool odd = (tg & 1);
#pragma unroll
        for (int kt = 0; kt < 16; kt++) {
            float p0 = sc[kt][0], p1 = sc[kt][1], p2 = sc[kt][2], p3 = sc[kt][3];
            float e0 = __shfl_sync(0xffffffffu, p0, srcA);
            float e1 = __shfl_sync(0xffffffffu, p1, srcA);
            float e2 = __shfl_sync(0xffffffffu, p2, srcA);
            float e3 = __shfl_sync(0xffffffffu, p3, srcA);
            float h0 = __shfl_sync(0xffffffffu, p0, srcB);
            float h1 = __shfl_sync(0xffffffffu, p1, srcB);
            float h2 = __shfl_sync(0xffffffffu, p2, srcB);
            float h3 = __shfl_sync(0xffffffffu, p3, srcB);
            uint32_t af[4];
            af[0] = __float_as_uint(odd ? e1 : e0);
            af[1] = __float_as_uint(odd ? e3 : e2);
            af[2] = __float_as_uint(odd ? h1 : h0);
            af[3] = __float_as_uint(odd ? h3 : h2);
#pragma unroll
            for (int nt = 0; nt < 8; nt++) {
                uint32_t b0 = __float_as_uint(Vs[kt * 8 + tg][nt * 8 + g]);
                uint32_t b1 = __float_as_uint(Vs[kt * 8 + tg + 4][nt * 8 + g]);
                mma_tf32(o[nt], af, b0, b1);
            }
        }
    }

    const float il0 = 1.f / l0, il1 = 1.f / l1;
#pragma unroll
    for (int nt = 0; nt < 8; nt++) {
        int c = nt * 8 + 2 * tg;
        float2 v0 = make_float2(o[nt][0] * il0, o[nt][1] * il0);
        float2 v1 = make_float2(o[nt][2] * il1, o[nt][3] * il1);
        *reinterpret_cast<float2*>(Op + (size_t)r0 * DHD + c) = v0;
        *reinterpret_cast<float2*>(Op + (size_t)r1 * DHD + c) = v1;
        float2 r0v = make_float2(f2tf32f(v0.x), f2tf32f(v0.y));
        float2 r1v = make_float2(f2tf32f(v1.x), f2tf32f(v1.y));
        *reinterpret_cast<float2*>(Opr + (size_t)r0 * DHD + c) = r0v;
        *reinterpret_cast<float2*>(Opr + (size_t)r1 * DHD + c) = r1v;
    }
}

// ---------------- GEGLU (output tf32-rounded; it only feeds FF2 GEMM) ------
__global__ __launch_bounds__(256)
void geglu_kernel(const float* __restrict__ h, float* __restrict__ act) {
    const int idx = blockIdx.x * 256 + threadIdx.x;
    const int m = idx >> 10;
    const int c = (idx & 1023) << 2;
    const float4 a  = *reinterpret_cast<const float4*>(h + (size_t)m * (2 * FF) + c);
    const float4 gt = *reinterpret_cast<const float4*>(h + (size_t)m * (2 * FF) + FF + c);
    float4 o;
    o.x = f2tf32f(a.x * gelu_exact(gt.x));
    o.y = f2tf32f(a.y * gelu_exact(gt.y));
    o.z = f2tf32f(a.z * gelu_exact(gt.z));
    o.w = f2tf32f(a.w * gelu_exact(gt.w));
    *reinterpret_cast<float4*>(act + (size_t)m * FF + c) = o;
}

// ---------------- launch ---------------------------------------------------
extern "C" void kernel_launch(void* const* d_in, const int* in_sizes, int n_in,
                              void* d_out, int out_size) {
    (void)in_sizes; (void)n_in; (void)out_size;
    const float* x     = (const float*)d_in[0];
    const float* Wq    = (const float*)d_in[1];
    const float* Wk    = (const float*)d_in[2];
    const float* Wv    = (const float*)d_in[3];
    const float* Wo    = (const float*)d_in[4];
    const float* bo    = (const float*)d_in[5];
    const float* ln1_g = (const float*)d_in[6];
    const float* ln1_b = (const float*)d_in[7];
    const float* ln3_g = (const float*)d_in[8];
    const float* ln3_b = (const float*)d_in[9];
    const float* Wff1  = (const float*)d_in[10];
    const float* bff1  = (const float*)d_in[11];
    const float* Wff2  = (const float*)d_in[12];
    const float* bff2  = (const float*)d_in[13];

    float* out = (float*)d_out;
    const size_t SZ = (size_t)MROWS * DMOD;
    float* out_x  = out;            // x
    float* out_q  = out + SZ;       // q_bh
    float* out_k  = out + 2 * SZ;   // k_bh
    float* out_v  = out + 3 * SZ;   // v_bh
    float* out_io = out + 4 * SZ;   // inter_out
    float* out_xf = out + 5 * SZ;   // x_features

    float *x2, *xf2, *xfr, *ior, *hbuf, *actbuf, *wbuf;
    cudaGetSymbolAddress((void**)&x2,     g_x2);
    cudaGetSymbolAddress((void**)&xf2,    g_xf2);
    cudaGetSymbolAddress((void**)&xfr,    g_xfr);
    cudaGetSymbolAddress((void**)&ior,    g_ior);
    cudaGetSymbolAddress((void**)&hbuf,   g_h);
    cudaGetSymbolAddress((void**)&actbuf, g_act);
    cudaGetSymbolAddress((void**)&wbuf,   g_w);

    cudaFuncSetAttribute(gemm_qkv_kernel,
                         cudaFuncAttributeMaxDynamicSharedMemorySize, SMEM_GEMM);
    cudaFuncSetAttribute(gemm3_kernel<0>,
                         cudaFuncAttributeMaxDynamicSharedMemorySize, SMEM_GEMM);
    cudaFuncSetAttribute(gemm3_kernel<1>,
                         cudaFuncAttributeMaxDynamicSharedMemorySize, SMEM_GEMM);
    cudaFuncSetAttribute(flash_attn_kernel,
                         cudaFuncAttributeMaxDynamicSharedMemorySize,
                         2 * 128 * (DHD + 4) * (int)sizeof(float));

    const dim3 blk(GTH);

    // 0) pre-round all weights to tf32, single launch (16M floats = 4M float4)
    cvt_weights_kernel<<<(16 * 1024 * 1024 / 4) / 256, 256>>>(
        (const float4*)Wq, (const float4*)Wk, (const float4*)Wv, (const float4*)Wo,
        (const float4*)Wff1, (const float4*)Wff2, (float4*)wbuf);

    // 1) LN1 -> x_features (exact) + rounded copy for GEMM A
    ln_kernel<<<MROWS, 256>>>(x, ln1_g, ln1_b, out_xf, xfr);

    // 2) fused QKV GEMM (N = 3072), scattered directly to (B*H, N, DH)
    gemm_qkv_kernel<<<dim3(3 * DMOD / BN, MROWS / BM), blk, SMEM_GEMM>>>(
        xfr, wbuf + WOFF_Q, out_q, out_k, out_v);

    // 3) attention -> inter_out (exact) + rounded copy
    const int smem_fa = 2 * 128 * (DHD + 4) * (int)sizeof(float);
    flash_attn_kernel<<<dim3(TOK / 128, NBAT * NH), 256, smem_fa>>>(
        out_q, out_k, out_v, out_io, ior);

    // 4) Wo GEMM (gather-A from rounded inter_out) + bo + residual x -> x2 (exact)
    gemm3_kernel<1><<<dim3(DMOD / BN, MROWS / BM), blk, SMEM_GEMM>>>(
        ior, wbuf + WOFF_O, x2, MROWS, DMOD, DMOD, bo, x);

    // 5) LN3 -> xf2 (rounded only; internal)
    ln_kernel<<<MROWS, 256>>>(x2, ln3_g, ln3_b, nullptr, xf2);

    // 6) FF1 GEMM (+bff1) -> h (exact; geglu needs exact gate)
    gemm3_kernel<0><<<dim3(2 * FF / BN, MROWS / BM), blk, SMEM_GEMM>>>(
        xf2, wbuf + WOFF_FF1, hbuf, MROWS, 2 * FF, DMOD, bff1, nullptr);

    // 7) GEGLU -> act (rounded)
    geglu_kernel<<<(MROWS * (FF / 4)) / 256, 256>>>(hbuf, actbuf);

    // 8) FF2 GEMM (+bff2) + residual x2 -> final x
    gemm3_kernel<0><<<dim3(DMOD / BN, MROWS / BM), blk, SMEM_GEMM>>>(
        actbuf, wbuf + WOFF_FF2, out_x, MROWS, DMOD, FF, bff2, x2);
}

// round 11
// speedup vs baseline: 1.1040x; 1.0078x over previous
#include <cuda_runtime.h>
#include <cstdint>
#include <cstdio>

#define TOK   2048
#define NBAT  2
#define NH    16
#define DHD   64
#define DMOD  1024
#define MROWS 4096   /* B*N */
#define FF    4096

// ---------------- scratch (static device globals; no runtime allocation) ---
__device__ float g_x2 [MROWS * DMOD];            // 16 MB : x after attn residual (exact)
__device__ float g_xf2[MROWS * DMOD];            // 16 MB : LN3 output (tf32-rounded)
__device__ float g_xfr[MROWS * DMOD];            // 16 MB : LN1 output (tf32-rounded)
__device__ float g_ior[MROWS * DMOD];            // 16 MB : inter_out (tf32-rounded)
__device__ float g_kr [MROWS * DMOD];            // 16 MB : k_bh tf32-rounded
__device__ float g_vr [MROWS * DMOD];            // 16 MB : v_bh tf32-rounded
__device__ float g_h  [(size_t)MROWS * 2 * FF];  // 128 MB: FF1 output (exact)
__device__ float g_act[(size_t)MROWS * FF];      // 64 MB : geglu output (tf32-rounded)
__device__ float g_w  [16 * 1024 * 1024];        // 64 MB : all weights, tf32-rounded
// offsets (floats) within g_w:
#define WOFF_Q    0
#define WOFF_K    (1024 * 1024)
#define WOFF_V    (2 * 1024 * 1024)
#define WOFF_O    (3 * 1024 * 1024)
#define WOFF_FF1  (4 * 1024 * 1024)
#define WOFF_FF2  (12 * 1024 * 1024)

// ---------------- helpers --------------------------------------------------
__device__ __forceinline__ uint32_t f2tf32(float x) {
    uint32_t t;
    asm("cvt.rna.tf32.f32 %0, %1;" : "=r"(t) : "f"(x));
    return t;
}
__device__ __forceinline__ float f2tf32f(float x) { return __uint_as_float(f2tf32(x)); }

__device__ __forceinline__ void mma_tf32(float c[4], const uint32_t a[4],
                                         uint32_t b0, uint32_t b1) {
    asm volatile(
        "mma.sync.aligned.m16n8k8.row.col.f32.tf32.tf32.f32 "
        "{%0,%1,%2,%3}, {%4,%5,%6,%7}, {%8,%9}, {%0,%1,%2,%3};\n"
        : "+f"(c[0]), "+f"(c[1]), "+f"(c[2]), "+f"(c[3])
        : "r"(a[0]), "r"(a[1]), "r"(a[2]), "r"(a[3]), "r"(b0), "r"(b1));
}

#define LDSM_X4(r0, r1, r2, r3, addr)                                         \
    asm volatile("ldmatrix.sync.aligned.m8n8.x4.shared.b16 {%0,%1,%2,%3}, [%4];" \
                 : "=r"(r0), "=r"(r1), "=r"(r2), "=r"(r3) : "r"(addr))

__device__ __forceinline__ void cp_async16(uint32_t dst, const void* src) {
    asm volatile("cp.async.cg.shared.global [%0], [%1], 16;\n" :: "r"(dst), "l"(src));
}
__device__ __forceinline__ void cp_commit() {
    asm volatile("cp.async.commit_group;\n" ::: "memory");
}
__device__ __forceinline__ void cp_wait1() {
    asm volatile("cp.async.wait_group 1;\n" ::: "memory");
}
__device__ __forceinline__ void cp_wait0() {
    asm volatile("cp.async.wait_group 0;\n" ::: "memory");
}

__device__ __forceinline__ float gelu_exact(float x) {
    return 0.5f * x * (1.0f + erff(x * 0.70710678118654752f));
}

// ------------ one-shot weight pre-rounding (all 16M floats, one launch) -----
__global__ __launch_bounds__(256)
void cvt_weights_kernel(const float4* __restrict__ wq, const float4* __restrict__ wk,
                        const float4* __restrict__ wv, const float4* __restrict__ wo,
                        const float4* __restrict__ wff1, const float4* __restrict__ wff2,
                        float4* __restrict__ dst) {
    const int Q4 = (1024 * 1024) / 4;            // 262144 float4 per 1M floats
    int i = blockIdx.x * 256 + threadIdx.x;      // 0 .. 4M-1 float4
    const float4* src;
    int off;
    if      (i <      Q4) { src = wq;   off = 0;      }
    else if (i <  2 * Q4) { src = wk;   off = Q4;     }
    else if (i <  3 * Q4) { src = wv;   off = 2 * Q4; }
    else if (i <  4 * Q4) { src = wo;   off = 3 * Q4; }
    else if (i < 12 * Q4) { src = wff1; off = 4 * Q4; }
    else                  { src = wff2; off = 12 * Q4;}
    float4 v = src[i - off];
    dst[i] = make_float4(f2tf32f(v.x), f2tf32f(v.y), f2tf32f(v.z), f2tf32f(v.w));
}

// ---------------- LayerNorm (one block per row of 1024) --------------------
// y: exact output (nullable). yr: tf32-rounded output (nullable).
__global__ __launch_bounds__(256)
void ln_kernel(const float* __restrict__ x, const float* __restrict__ gw,
               const float* __restrict__ bw, float* __restrict__ y,
               float* __restrict__ yr) {
    __shared__ float red[16];
    const int row = blockIdx.x;
    const int tid = threadIdx.x;
    const float4 v = reinterpret_cast<const float4*>(x + (size_t)row * DMOD)[tid];
    float s  = v.x + v.y + v.z + v.w;
    float ss = v.x * v.x + v.y * v.y + v.z * v.z + v.w * v.w;
#pragma unroll
    for (int o = 16; o > 0; o >>= 1) {
        s  += __shfl_xor_sync(0xffffffffu, s,  o);
        ss += __shfl_xor_sync(0xffffffffu, ss, o);
    }
    if ((tid & 31) == 0) { red[tid >> 5] = s; red[8 + (tid >> 5)] = ss; }
    __syncthreads();
    float ts = 0.f, tss = 0.f;
#pragma unroll
    for (int w = 0; w < 8; w++) { ts += red[w]; tss += red[8 + w]; }
    const float mu  = ts * (1.0f / DMOD);
    const float var = tss * (1.0f / DMOD) - mu * mu;
    const float rs  = rsqrtf(var + 1e-5f);
    const float4 gv = reinterpret_cast<const float4*>(gw)[tid];
    const float4 bv = reinterpret_cast<const float4*>(bw)[tid];
    float4 o;
    o.x = (v.x - mu) * rs * gv.x + bv.x;
    o.y = (v.y - mu) * rs * gv.y + bv.y;
    o.z = (v.z - mu) * rs * gv.z + bv.z;
    o.w = (v.w - mu) * rs * gv.w + bv.w;
    if (y)  reinterpret_cast<float4*>(y  + (size_t)row * DMOD)[tid] = o;
    if (yr) {
        float4 r = make_float4(f2tf32f(o.x), f2tf32f(o.y), f2tf32f(o.z), f2tf32f(o.w));
        reinterpret_cast<float4*>(yr + (size_t)row * DMOD)[tid] = r;
    }
}

// -- TF32 GEMM v5: CTA 128x256, 512 thr, warp 64x32, cp.async 3-stage, LDSM A
constexpr int BM = 128, BN = 256, BK = 32, STAGES = 3;
constexpr int GTH = 512;                                       // GEMM threads
constexpr int LDA_S = 36, LDB_S = 264;
constexpr int STAGE_F = BM * LDA_S + BK * LDB_S;               // 13056 floats
constexpr int SMEM_GEMM = STAGES * STAGE_F * 4;                // 156672 bytes

// AMODE 0: A row-major [M][K].  AMODE 1: A gathered from inter_out (B,H,TOK,DHD).
template <int AMODE>
struct ALoader {
    static __device__ __forceinline__ const float* ptr(const float* A, int gm, int gk, int K) {
        if (AMODE == 0) return A + (size_t)gm * K + gk;
        int bb = gm >> 11, nn = gm & (TOK - 1);
        int hh = gk >> 6,  dd = gk & (DHD - 1);
        return A + (((size_t)(bb * NH + hh) * TOK + nn) * DHD + dd);
    }
};

template <int AMODE>
__device__ __forceinline__ void gemm_load_stage(
    const float* __restrict__ A, const float* __restrict__ B, int ldb,
    int m0, int nb, int kb, int K, uint32_t smem_stage) {
#pragma unroll
    for (int i = 0; i < 2; i++) {                // A: 128x32 = 1024 chunks / 512 thr
        int c = i * GTH + threadIdx.x;
        int row = c >> 3, kc = (c & 7) << 2;
        const float* src = ALoader<AMODE>::ptr(A, m0 + row, kb + kc, K);
        cp_async16(smem_stage + (uint32_t)(row * LDA_S + kc) * 4u, src);
    }
    const uint32_t bs = smem_stage + (uint32_t)(BM * LDA_S) * 4u;
#pragma unroll
    for (int i = 0; i < 4; i++) {                // B: 32x256 = 2048 chunks / 512 thr
        int c = i * GTH + threadIdx.x;
        int row = c >> 6, col = (c & 63) << 2;
        cp_async16(bs + (uint32_t)(row * LDB_S + col) * 4u,
                   B + (size_t)(kb + row) * ldb + nb + col);
    }
}

// A fragments via ldmatrix.x4 (one per mt per kk); B via LDS.32.
__device__ __forceinline__ void gemm_compute_stage(
    uint32_t st_u, const float* __restrict__ st, int wm, int wn,
    float acc[4][4][4]) {
    const int lane = threadIdx.x & 31;
    const int g = lane >> 2, tg = lane & 3;
    // ldmatrix row/col per-thread address (bytes), matrix layout of m16n8k8 A frag
    const uint32_t a_base = st_u +
        (uint32_t)((wm + (lane & 15)) * LDA_S + ((lane >> 4) << 2)) * 4u;
    const float* Bs = st + BM * LDA_S;
#pragma unroll
    for (int kk = 0; kk < BK; kk += 8) {
        uint32_t af[4][4];
#pragma unroll
        for (int mt = 0; mt < 4; mt++) {
            LDSM_X4(af[mt][0], af[mt][1], af[mt][2], af[mt][3],
                    a_base + (uint32_t)(mt * 16 * LDA_S + kk) * 4u);
        }
        uint32_t bf[4][2];
#pragma unroll
        for (int nt = 0; nt < 4; nt++) {
            const float* br = Bs + (kk + tg) * LDB_S + wn + nt * 8 + g;
            bf[nt][0] = __float_as_uint(br[0]);
            bf[nt][1] = __float_as_uint(br[4 * LDB_S]);
        }
#pragma unroll
        for (int mt = 0; mt < 4; mt++)
#pragma unroll
            for (int nt = 0; nt < 4; nt++)
                mma_tf32(acc[mt][nt], af[mt], bf[nt][0], bf[nt][1]);
    }
}

// ---- standard output: C row-major (ldc = N), optional bias + residual -----
template <int AMODE>
__global__ __launch_bounds__(GTH, 1)
void gemm3_kernel(const float* __restrict__ A, const float* __restrict__ B,
                  float* __restrict__ C, int M, int N, int K,
                  const float* __restrict__ bias, const float* __restrict__ res) {
    extern __shared__ float sm[];
    const uint32_t smem_u = (uint32_t)__cvta_generic_to_shared(sm);
    const int tid = threadIdx.x, wid = tid >> 5, lane = tid & 31;
    const int g = lane >> 2, tg = lane & 3;
    const int m0 = blockIdx.y * BM;
    const int n0 = blockIdx.x * BN;
    const int wm = (wid & 1) * 64;     // 2 warp-rows of 64
    const int wn = (wid >> 1) * 32;    // 8 warp-cols of 32

    float acc[4][4][4];
#pragma unroll
    for (int i = 0; i < 4; i++)
#pragma unroll
        for (int j = 0; j < 4; j++)
#pragma unroll
            for (int k = 0; k < 4; k++) acc[i][j][k] = 0.f;

    const int T = K / BK;
    gemm_load_stage<AMODE>(A, B, N, m0, n0, 0, K, smem_u);
    cp_commit();
    gemm_load_stage<AMODE>(A, B, N, m0, n0, BK, K, smem_u + STAGE_F * 4);
    cp_commit();

    int s = 0;
    for (int kt = 0; kt < T; kt++) {
        cp_wait1();
        __syncthreads();
        if (kt + 2 < T) {
            int s2 = (s + 2 >= STAGES) ? s + 2 - STAGES : s + 2;
            gemm_load_stage<AMODE>(A, B, N, m0, n0, (kt + 2) * BK, K,
                                   smem_u + (uint32_t)s2 * STAGE_F * 4);
        }
        cp_commit();
        gemm_compute_stage(smem_u + (uint32_t)s * STAGE_F * 4, sm + s * STAGE_F,
                           wm, wn, acc);
        s = (s + 1 == STAGES) ? 0 : s + 1;
    }

#pragma unroll
    for (int mt = 0; mt < 4; mt++) {
        const int r0 = m0 + wm + mt * 16 + g;
        const int r1 = r0 + 8;
#pragma unroll
        for (int nt = 0; nt < 4; nt++) {
            const int c = n0 + wn + nt * 8 + 2 * tg;
            float2 v0 = make_float2(acc[mt][nt][0], acc[mt][nt][1]);
            float2 v1 = make_float2(acc[mt][nt][2], acc[mt][nt][3]);
            if (bias) {
                float2 bb = *reinterpret_cast<const float2*>(bias + c);
                v0.x += bb.x; v0.y += bb.y; v1.x += bb.x; v1.y += bb.y;
            }
            if (res) {
                float2 q0r = *reinterpret_cast<const float2*>(res + (size_t)r0 * N + c);
                float2 q1r = *reinterpret_cast<const float2*>(res + (size_t)r1 * N + c);
                v0.x += q0r.x; v0.y += q0r.y; v1.x += q1r.x; v1.y += q1r.y;
            }
            *reinterpret_cast<float2*>(C + (size_t)r0 * N + c) = v0;
            *reinterpret_cast<float2*>(C + (size_t)r1 * N + c) = v1;
        }
    }
}

// ---- fused QKV: one GEMM over N=3072, scatter into q_bh/k_bh/v_bh ---------
// Also writes tf32-rounded copies of k/v (for flash's cp.async path).
__global__ __launch_bounds__(GTH, 1)
void gemm_qkv_kernel(const float* __restrict__ A, const float* __restrict__ W,
                     float* __restrict__ Cq, float* __restrict__ Ck,
                     float* __restrict__ Cv, float* __restrict__ Ckr,
                     float* __restrict__ Cvr) {
    extern __shared__ float sm[];
    const uint32_t smem_u = (uint32_t)__cvta_generic_to_shared(sm);
    const int tid = threadIdx.x, wid = tid >> 5, lane = tid & 31;
    const int g = lane >> 2, tg = lane & 3;
    const int m0 = blockIdx.y * BM;
    const int arr = blockIdx.x >> 2;                 // 0..2 : which weight/output
    const int nb  = (blockIdx.x & 3) * BN;           // column base within the array
    const float* B = W + (size_t)arr * DMOD * DMOD;  // Wq/Wk/Wv pre-rounded, contiguous
    float* C  = (arr == 0) ? Cq : (arr == 1) ? Ck : Cv;
    float* Cr = (arr == 1) ? Ckr : (arr == 2) ? Cvr : nullptr;
    const int wm = (wid & 1) * 64;
    const int wn = (wid >> 1) * 32;
    const int K = DMOD;

    float acc[4][4][4];
#pragma unroll
    for (int i = 0; i < 4; i++)
#pragma unroll
        for (int j = 0; j < 4; j++)
#pragma unroll
            for (int k = 0; k < 4; k++) acc[i][j][k] = 0.f;

    const int T = K / BK;
    gemm_load_stage<0>(A, B, DMOD, m0, nb, 0, K, smem_u);
    cp_commit();
    gemm_load_stage<0>(A, B, DMOD, m0, nb, BK, K, smem_u + STAGE_F * 4);
    cp_commit();

    int s = 0;
    for (int kt = 0; kt < T; kt++) {
        cp_wait1();
        __syncthreads();
        if (kt + 2 < T) {
            int s2 = (s + 2 >= STAGES) ? s + 2 - STAGES : s + 2;
            gemm_load_stage<0>(A, B, DMOD, m0, nb, (kt + 2) * BK, K,
                               smem_u + (uint32_t)s2 * STAGE_F * 4);
        }
        cp_commit();
        gemm_compute_stage(smem_u + (uint32_t)s * STAGE_F * 4, sm + s * STAGE_F,
                           wm, wn, acc);
        s = (s + 1 == STAGES) ? 0 : s + 1;
    }

    // scatter to (B*H, TOK, DHD)
#pragma unroll
    for (int mt = 0; mt < 4; mt++) {
        const int r0 = m0 + wm + mt * 16 + g;
        const int r1 = r0 + 8;
        const int b0_ = r0 >> 11, n0_ = r0 & (TOK - 1);
        const int b1_ = r1 >> 11, n1_ = r1 & (TOK - 1);
#pragma unroll
        for (int nt = 0; nt < 4; nt++) {
            const int cl = nb + wn + nt * 8 + 2 * tg;
            const int hh = cl >> 6, dd = cl & (DHD - 1);
            const size_t o0 = ((size_t)(b0_ * NH + hh) * TOK + n0_) * DHD + dd;
            const size_t o1 = ((size_t)(b1_ * NH + hh) * TOK + n1_) * DHD + dd;
            float2 v0 = make_float2(acc[mt][nt][0], acc[mt][nt][1]);
            float2 v1 = make_float2(acc[mt][nt][2], acc[mt][nt][3]);
            *reinterpret_cast<float2*>(C + o0) = v0;
            *reinterpret_cast<float2*>(C + o1) = v1;
            if (Cr) {
                float2 r0v = make_float2(f2tf32f(v0.x), f2tf32f(v0.y));
                float2 r1v = make_float2(f2tf32f(v1.x), f2tf32f(v1.y));
                *reinterpret_cast<float2*>(Cr + o0) = r0v;
                *reinterpret_cast<float2*>(Cr + o1) = r1v;
            }
        }
    }
}

// ---------------- flash attention v2: cp.async K/V + LDSM K-frags -----------
// K/V read from PRE-ROUNDED copies; 2-stage cp.async pipeline; LDSM B-frags.
constexpr int FA_LDK = DHD + 4;                     // 68 floats/row
constexpr int FA_TILE_F = 128 * FA_LDK;             // one array, one stage
constexpr int FA_STAGE_F = 2 * FA_TILE_F;           // K + V
constexpr int SMEM_FA = 2 * FA_STAGE_F * 4;         // 139264 bytes

__global__ __launch_bounds__(256)
void flash_attn_kernel(const float* __restrict__ Q, const float* __restrict__ Kr,
                       const float* __restrict__ Vr, float* __restrict__ O,
                       float* __restrict__ Or) {
    extern __shared__ float sm[];
    const uint32_t smem_u = (uint32_t)__cvta_generic_to_shared(sm);

    const int tid = threadIdx.x, wid = tid >> 5, lane = tid & 31;
    const int g = lane >> 2, tg = lane & 3;
    const int bh = blockIdx.y;
    const int q0 = blockIdx.x * 128;
    const float* Qp = Q  + (size_t)bh * TOK * DHD;
    const float* Kp = Kr + (size_t)bh * TOK * DHD;
    const float* Vp = Vr + (size_t)bh * TOK * DHD;
    float* Op  = O  + (size_t)bh * TOK * DHD;
    float* Opr = Or + (size_t)bh * TOK * DHD;
    const int wm = wid * 16;
    const int r0 = q0 + wm + g, r1 = r0 + 8;

    // Q fragments (scaled by 1/8 exact, tf32-rounded)
    uint32_t qf[8][4];
#pragma unroll
    for (int ks = 0; ks < 8; ks++) {
        int c = ks * 8 + tg;
        qf[ks][0] = f2tf32(Qp[(size_t)r0 * DHD + c] * 0.125f);
        qf[ks][1] = f2tf32(Qp[(size_t)r1 * DHD + c] * 0.125f);
        qf[ks][2] = f2tf32(Qp[(size_t)r0 * DHD + c + 4] * 0.125f);
        qf[ks][3] = f2tf32(Qp[(size_t)r1 * DHD + c + 4] * 0.125f);
    }

    // per-lane ldmatrix offset for K-fragments:
    // lane l -> token (l&7) + ((l>>4)&1)*8 ; k-half ((l>>3)&1)*4
    const uint32_t lds_off =
        (uint32_t)((((lane & 7) + ((lane >> 4) & 1) * 8) * FA_LDK +
                    ((lane >> 3) & 1) * 4)) * 4u;

    float m0 = -1e30f, m1 = -1e30f, l0 = 0.f, l1 = 0.f;
    float o[8][4];
#pragma unroll
    for (int i = 0; i < 8; i++)
#pragma unroll
        for (int j = 0; j < 4; j++) o[i][j] = 0.f;

    auto loadKV = [&](int j, int st) {
        const uint32_t kd = smem_u + (uint32_t)st * FA_STAGE_F * 4u;
        const uint32_t vd = kd + (uint32_t)FA_TILE_F * 4u;
#pragma unroll
        for (int i = 0; i < 8; i++) {
            int s = tid + i * 256;
            int r = s >> 4, c = (s & 15) << 2;
            cp_async16(kd + (uint32_t)(r * FA_LDK + c) * 4u,
                       Kp + (size_t)(j + r) * DHD + c);
            cp_async16(vd + (uint32_t)(r * FA_LDK + c) * 4u,
                       Vp + (size_t)(j + r) * DHD + c);
        }
    };

    loadKV(0, 0);
    cp_commit();

    const int NT = TOK / 128;
    for (int jt = 0; jt < NT; jt++) {
        if (jt + 1 < NT) {
            loadKV((jt + 1) * 128, (jt + 1) & 1);
            cp_commit();
            cp_wait1();
        } else {
            cp_wait0();
        }
        __syncthreads();

        const int st = jt & 1;
        const uint32_t ks_u = smem_u + (uint32_t)st * FA_STAGE_F * 4u;
        const float* Vs = sm + st * FA_STAGE_F + FA_TILE_F;

        // S = (Q/8) K^T : B-frags via ldmatrix
        float sc[16][4];
#pragma unroll
        for (int nt = 0; nt < 16; nt++)
#pragma unroll
            for (int k4 = 0; k4 < 4; k4++) sc[nt][k4] = 0.f;
#pragma unroll
        for (int ks = 0; ks < 8; ks++) {
            const uint32_t kaddr = ks_u + (uint32_t)(ks * 8) * 4u + lds_off;
#pragma unroll
            for (int nt4 = 0; nt4 < 4; nt4++) {
                uint32_t bf[4][2];
                LDSM_X4(bf[0][0], bf[0][1], bf[1][0], bf[1][1],
                        kaddr + (uint32_t)(nt4 * 32 * FA_LDK) * 4u);
                LDSM_X4(bf[2][0], bf[2][1], bf[3][0], bf[3][1],
                        kaddr + (uint32_t)((nt4 * 32 + 16) * FA_LDK) * 4u);
#pragma unroll
                for (int c4 = 0; c4 < 4; c4++)
                    mma_tf32(sc[nt4 * 4 + c4], qf[ks], bf[c4][0], bf[c4][1]);
            }
        }

        // online softmax
        float tm0 = -1e30f, tm1 = -1e30f;
#pragma unroll
        for (int nt = 0; nt < 16; nt++) {
            tm0 = fmaxf(tm0, fmaxf(sc[nt][0], sc[nt][1]));
            tm1 = fmaxf(tm1, fmaxf(sc[nt][2], sc[nt][3]));
        }
        tm0 = fmaxf(tm0, __shfl_xor_sync(0xffffffffu, tm0, 1));
        tm0 = fmaxf(tm0, __shfl_xor_sync(0xffffffffu, tm0, 2));
        tm1 = fmaxf(tm1, __shfl_xor_sync(0xffffffffu, tm1, 1));
        tm1 = fmaxf(tm1, __shfl_xor_sync(0xffffffffu, tm1, 2));
        const float nm0 = fmaxf(m0, tm0), nm1 = fmaxf(m1, tm1);
        const float a0 = __expf(m0 - nm0), a1 = __expf(m1 - nm1);
        float ts0 = 0.f, ts1 = 0.f;
#pragma unroll
        for (int nt = 0; nt < 16; nt++) {
            float p0 = __expf(sc[nt][0] - nm0);
            float p1 = __expf(sc[nt][1] - nm0);
            float p2 = __expf(sc[nt][2] - nm1);
            float p3 = __expf(sc[nt][3] - nm1);
            ts0 += p0 + p1; ts1 += p2 + p3;
            sc[nt][0] = f2tf32f(p0); sc[nt][1] = f2tf32f(p1);
            sc[nt][2] = f2tf32f(p2); sc[nt][3] = f2tf32f(p3);
        }
        ts0 += __shfl_xor_sync(0xffffffffu, ts0, 1);
        ts0 += __shfl_xor_sync(0xffffffffu, ts0, 2);
        ts1 += __shfl_xor_sync(0xffffffffu, ts1, 1);
        ts1 += __shfl_xor_sync(0xffffffffu, ts1, 2);
        l0 = l0 * a0 + ts0; l1 = l1 * a1 + ts1;
        m0 = nm0; m1 = nm1;
#pragma unroll
        for (int nt = 0; nt < 8; nt++) {
            o[nt][0] *= a0; o[nt][1] *= a0; o[nt][2] *= a1; o[nt][3] *= a1;
        }

        // O += P @ V  (C-frag -> A-frag remap via quad shuffles)
        const int qb = lane & ~3;
        const int srcA = qb + (tg >> 1);
        const int srcB = srcA + 2;
        const bool odd = (tg & 1);
#pragma unroll
        for (int kt = 0; kt < 16; kt++) {
            float p0 = sc[kt][0], p1 = sc[kt][1], p2 = sc[kt][2], p3 = sc[kt][3];
            float e0 = __shfl_sync(0xffffffffu, p0, srcA);
            float e1 = __shfl_sync(0xffffffffu, p1, srcA);
            float e2 = __shfl_sync(0xffffffffu, p2, srcA);
            float e3 = __shfl_sync(0xffffffffu, p3, srcA);
            float h0 = __shfl_sync(0xffffffffu, p0, srcB);
            float h1 = __shfl_sync(0xffffffffu, p1, srcB);
            float h2 = __shfl_sync(0xffffffffu, p2, srcB);
            float h3 = __shfl_sync(0xffffffffu, p3, srcB);
            uint32_t af[4];
            af[0] = __float_as_uint(odd ? e1 : e0);
            af[1] = __float_as_uint(odd ? e3 : e2);
            af[2] = __float_as_uint(odd ? h1 : h0);
            af[3] = __float_as_uint(odd ? h3 : h2);
#pragma unroll
            for (int nt = 0; nt < 8; nt++) {
                uint32_t b0 = __float_as_uint(Vs[(kt * 8 + tg) * FA_LDK + nt * 8 + g]);
                uint32_t b1 = __float_as_uint(Vs[(kt * 8 + tg + 4) * FA_LDK + nt * 8 + g]);
                mma_tf32(o[nt], af, b0, b1);
            }
        }
        __syncthreads();
    }

    const float il0 = 1.f / l0, il1 = 1.f / l1;
#pragma unroll
    for (int nt = 0; nt < 8; nt++) {
        int c = nt * 8 + 2 * tg;
        float2 v0 = make_float2(o[nt][0] * il0, o[nt][1] * il0);
        float2 v1 = make_float2(o[nt][2] * il1, o[nt][3] * il1);
        *reinterpret_cast<float2*>(Op + (size_t)r0 * DHD + c) = v0;
        *reinterpret_cast<float2*>(Op + (size_t)r1 * DHD + c) = v1;
        float2 r0v = make_float2(f2tf32f(v0.x), f2tf32f(v0.y));
        float2 r1v = make_float2(f2tf32f(v1.x), f2tf32f(v1.y));
        *reinterpret_cast<float2*>(Opr + (size_t)r0 * DHD + c) = r0v;
        *reinterpret_cast<float2*>(Opr + (size_t)r1 * DHD + c) = r1v;
    }
}

// ---------------- GEGLU (output tf32-rounded; it only feeds FF2 GEMM) ------
__global__ __launch_bounds__(256)
void geglu_kernel(const float* __restrict__ h, float* __restrict__ act) {
    const int idx = blockIdx.x * 256 + threadIdx.x;
    const int m = idx >> 10;
    const int c = (idx & 1023) << 2;
    const float4 a  = *reinterpret_cast<const float4*>(h + (size_t)m * (2 * FF) + c);
    const float4 gt = *reinterpret_cast<const float4*>(h + (size_t)m * (2 * FF) + FF + c);
    float4 o;
    o.x = f2tf32f(a.x * gelu_exact(gt.x));
    o.y = f2tf32f(a.y * gelu_exact(gt.y));
    o.z = f2tf32f(a.z * gelu_exact(gt.z));
    o.w = f2tf32f(a.w * gelu_exact(gt.w));
    *reinterpret_cast<float4*>(act + (size_t)m * FF + c) = o;
}

// ---------------- launch ---------------------------------------------------
extern "C" void kernel_launch(void* const* d_in, const int* in_sizes, int n_in,
                              void* d_out, int out_size) {
    (void)in_sizes; (void)n_in; (void)out_size;
    const float* x     = (const float*)d_in[0];
    const float* Wq    = (const float*)d_in[1];
    const float* Wk    = (const float*)d_in[2];
    const float* Wv    = (const float*)d_in[3];
    const float* Wo    = (const float*)d_in[4];
    const float* bo    = (const float*)d_in[5];
    const float* ln1_g = (const float*)d_in[6];
    const float* ln1_b = (const float*)d_in[7];
    const float* ln3_g = (const float*)d_in[8];
    const float* ln3_b = (const float*)d_in[9];
    const float* Wff1  = (const float*)d_in[10];
    const float* bff1  = (const float*)d_in[11];
    const float* Wff2  = (const float*)d_in[12];
    const float* bff2  = (const float*)d_in[13];

    float* out = (float*)d_out;
    const size_t SZ = (size_t)MROWS * DMOD;
    float* out_x  = out;            // x
    float* out_q  = out + SZ;       // q_bh
    float* out_k  = out + 2 * SZ;   // k_bh
    float* out_v  = out + 3 * SZ;   // v_bh
    float* out_io = out + 4 * SZ;   // inter_out
    float* out_xf = out + 5 * SZ;   // x_features

    float *x2, *xf2, *xfr, *ior, *kr, *vr, *hbuf, *actbuf, *wbuf;
    cudaGetSymbolAddress((void**)&x2,     g_x2);
    cudaGetSymbolAddress((void**)&xf2,    g_xf2);
    cudaGetSymbolAddress((void**)&xfr,    g_xfr);
    cudaGetSymbolAddress((void**)&ior,    g_ior);
    cudaGetSymbolAddress((void**)&kr,     g_kr);
    cudaGetSymbolAddress((void**)&vr,     g_vr);
    cudaGetSymbolAddress((void**)&hbuf,   g_h);
    cudaGetSymbolAddress((void**)&actbuf, g_act);
    cudaGetSymbolAddress((void**)&wbuf,   g_w);

    cudaFuncSetAttribute(gemm_qkv_kernel,
                         cudaFuncAttributeMaxDynamicSharedMemorySize, SMEM_GEMM);
    cudaFuncSetAttribute(gemm3_kernel<0>,
                         cudaFuncAttributeMaxDynamicSharedMemorySize, SMEM_GEMM);
    cudaFuncSetAttribute(gemm3_kernel<1>,
                         cudaFuncAttributeMaxDynamicSharedMemorySize, SMEM_GEMM);
    cudaFuncSetAttribute(flash_attn_kernel,
                         cudaFuncAttributeMaxDynamicSharedMemorySize, SMEM_FA);

    const dim3 blk(GTH);

    // 0) pre-round all weights to tf32, single launch (16M floats = 4M float4)
    cvt_weights_kernel<<<(16 * 1024 * 1024 / 4) / 256, 256>>>(
        (const float4*)Wq, (const float4*)Wk, (const float4*)Wv, (const float4*)Wo,
        (const float4*)Wff1, (const float4*)Wff2, (float4*)wbuf);

    // 1) LN1 -> x_features (exact) + rounded copy for GEMM A
    ln_kernel<<<MROWS, 256>>>(x, ln1_g, ln1_b, out_xf, xfr);

    // 2) fused QKV GEMM; exact q/k/v to d_out, rounded k/v copies for flash
    gemm_qkv_kernel<<<dim3(3 * DMOD / BN, MROWS / BM), blk, SMEM_GEMM>>>(
        xfr, wbuf + WOFF_Q, out_q, out_k, out_v, kr, vr);

    // 3) attention -> inter_out (exact) + rounded copy
    flash_attn_kernel<<<dim3(TOK / 128, NBAT * NH), 256, SMEM_FA>>>(
        out_q, kr, vr, out_io, ior);

    // 4) Wo GEMM (gather-A from rounded inter_out) + bo + residual x -> x2 (exact)
    gemm3_kernel<1><<<dim3(DMOD / BN, MROWS / BM), blk, SMEM_GEMM>>>(
        ior, wbuf + WOFF_O, x2, MROWS, DMOD, DMOD, bo, x);

    // 5) LN3 -> xf2 (rounded only; internal)
    ln_kernel<<<MROWS, 256>>>(x2, ln3_g, ln3_b, nullptr, xf2);

    // 6) FF1 GEMM (+bff1) -> h (exact; geglu needs exact gate)
    gemm3_kernel<0><<<dim3(2 * FF / BN, MROWS / BM), blk, SMEM_GEMM>>>(
        xf2, wbuf + WOFF_FF1, hbuf, MROWS, 2 * FF, DMOD, bff1, nullptr);

    // 7) GEGLU -> act (rounded)
    geglu_kernel<<<(MROWS * (FF / 4)) / 256, 256>>>(hbuf, actbuf);

    // 8) FF2 GEMM (+bff2) + residual x2 -> final x
    gemm3_kernel<0><<<dim3(DMOD / BN, MROWS / BM), blk, SMEM_GEMM>>>(
        actbuf, wbuf + WOFF_FF2, out_x, MROWS, DMOD, FF, bff2, x2);
}

// round 12
// speedup vs baseline: 1.1278x; 1.0216x over previous
#include <cuda_runtime.h>
#include <cstdint>
#include <cstdio>

#define TOK   2048
#define NBAT  2
#define NH    16
#define DHD   64
#define DMOD  1024
#define MROWS 4096   /* B*N */
#define FF    4096

// ---------------- scratch (static device globals; no runtime allocation) ---
__device__ float g_x2 [MROWS * DMOD];            // 16 MB : x after attn residual (exact)
__device__ float g_xf2[MROWS * DMOD];            // 16 MB : LN3 output (tf32-rounded)
__device__ float g_xfr[MROWS * DMOD];            // 16 MB : LN1 output (tf32-rounded)
__device__ float g_ior[MROWS * DMOD];            // 16 MB : inter_out (tf32-rounded)
__device__ float g_kr [MROWS * DMOD];            // 16 MB : k_bh tf32-rounded
__device__ float g_vtr[MROWS * DMOD];            // 16 MB : v_bh tf32-rounded TRANSPOSED [bh][dh][tok]
__device__ float g_h  [(size_t)MROWS * 2 * FF];  // 128 MB: FF1 output (exact)
__device__ float g_act[(size_t)MROWS * FF];      // 64 MB : geglu output (tf32-rounded)
__device__ float g_w  [16 * 1024 * 1024];        // 64 MB : all weights, tf32-rounded
// offsets (floats) within g_w:
#define WOFF_Q    0
#define WOFF_K    (1024 * 1024)
#define WOFF_V    (2 * 1024 * 1024)
#define WOFF_O    (3 * 1024 * 1024)
#define WOFF_FF1  (4 * 1024 * 1024)
#define WOFF_FF2  (12 * 1024 * 1024)

// ---------------- helpers --------------------------------------------------
__device__ __forceinline__ uint32_t f2tf32(float x) {
    uint32_t t;
    asm("cvt.rna.tf32.f32 %0, %1;" : "=r"(t) : "f"(x));
    return t;
}
__device__ __forceinline__ float f2tf32f(float x) { return __uint_as_float(f2tf32(x)); }

__device__ __forceinline__ void mma_tf32(float c[4], const uint32_t a[4],
                                         uint32_t b0, uint32_t b1) {
    asm volatile(
        "mma.sync.aligned.m16n8k8.row.col.f32.tf32.tf32.f32 "
        "{%0,%1,%2,%3}, {%4,%5,%6,%7}, {%8,%9}, {%0,%1,%2,%3};\n"
        : "+f"(c[0]), "+f"(c[1]), "+f"(c[2]), "+f"(c[3])
        : "r"(a[0]), "r"(a[1]), "r"(a[2]), "r"(a[3]), "r"(b0), "r"(b1));
}

#define LDSM_X4(r0, r1, r2, r3, addr)                                         \
    asm volatile("ldmatrix.sync.aligned.m8n8.x4.shared.b16 {%0,%1,%2,%3}, [%4];" \
                 : "=r"(r0), "=r"(r1), "=r"(r2), "=r"(r3) : "r"(addr))

#define STS64(addr, v0, v1)                                                   \
    asm volatile("st.shared.v2.f32 [%0], {%1, %2};" :: "r"(addr), "f"(v0), "f"(v1))

__device__ __forceinline__ void cp_async16(uint32_t dst, const void* src) {
    asm volatile("cp.async.cg.shared.global [%0], [%1], 16;\n" :: "r"(dst), "l"(src));
}
__device__ __forceinline__ void cp_commit() {
    asm volatile("cp.async.commit_group;\n" ::: "memory");
}
__device__ __forceinline__ void cp_wait1() {
    asm volatile("cp.async.wait_group 1;\n" ::: "memory");
}
__device__ __forceinline__ void cp_wait0() {
    asm volatile("cp.async.wait_group 0;\n" ::: "memory");
}

__device__ __forceinline__ float gelu_exact(float x) {
    return 0.5f * x * (1.0f + erff(x * 0.70710678118654752f));
}

// ------------ one-shot weight pre-rounding (all 16M floats, one launch) -----
__global__ __launch_bounds__(256)
void cvt_weights_kernel(const float4* __restrict__ wq, const float4* __restrict__ wk,
                        const float4* __restrict__ wv, const float4* __restrict__ wo,
                        const float4* __restrict__ wff1, const float4* __restrict__ wff2,
                        float4* __restrict__ dst) {
    const int Q4 = (1024 * 1024) / 4;            // 262144 float4 per 1M floats
    int i = blockIdx.x * 256 + threadIdx.x;      // 0 .. 4M-1 float4
    const float4* src;
    int off;
    if      (i <      Q4) { src = wq;   off = 0;      }
    else if (i <  2 * Q4) { src = wk;   off = Q4;     }
    else if (i <  3 * Q4) { src = wv;   off = 2 * Q4; }
    else if (i <  4 * Q4) { src = wo;   off = 3 * Q4; }
    else if (i < 12 * Q4) { src = wff1; off = 4 * Q4; }
    else                  { src = wff2; off = 12 * Q4;}
    float4 v = src[i - off];
    dst[i] = make_float4(f2tf32f(v.x), f2tf32f(v.y), f2tf32f(v.z), f2tf32f(v.w));
}

// ---------------- LayerNorm (one block per row of 1024) --------------------
__global__ __launch_bounds__(256)
void ln_kernel(const float* __restrict__ x, const float* __restrict__ gw,
               const float* __restrict__ bw, float* __restrict__ y,
               float* __restrict__ yr) {
    __shared__ float red[16];
    const int row = blockIdx.x;
    const int tid = threadIdx.x;
    const float4 v = reinterpret_cast<const float4*>(x + (size_t)row * DMOD)[tid];
    float s  = v.x + v.y + v.z + v.w;
    float ss = v.x * v.x + v.y * v.y + v.z * v.z + v.w * v.w;
#pragma unroll
    for (int o = 16; o > 0; o >>= 1) {
        s  += __shfl_xor_sync(0xffffffffu, s,  o);
        ss += __shfl_xor_sync(0xffffffffu, ss, o);
    }
    if ((tid & 31) == 0) { red[tid >> 5] = s; red[8 + (tid >> 5)] = ss; }
    __syncthreads();
    float ts = 0.f, tss = 0.f;
#pragma unroll
    for (int w = 0; w < 8; w++) { ts += red[w]; tss += red[8 + w]; }
    const float mu  = ts * (1.0f / DMOD);
    const float var = tss * (1.0f / DMOD) - mu * mu;
    const float rs  = rsqrtf(var + 1e-5f);
    const float4 gv = reinterpret_cast<const float4*>(gw)[tid];
    const float4 bv = reinterpret_cast<const float4*>(bw)[tid];
    float4 o;
    o.x = (v.x - mu) * rs * gv.x + bv.x;
    o.y = (v.y - mu) * rs * gv.y + bv.y;
    o.z = (v.z - mu) * rs * gv.z + bv.z;
    o.w = (v.w - mu) * rs * gv.w + bv.w;
    if (y)  reinterpret_cast<float4*>(y  + (size_t)row * DMOD)[tid] = o;
    if (yr) {
        float4 r = make_float4(f2tf32f(o.x), f2tf32f(o.y), f2tf32f(o.z), f2tf32f(o.w));
        reinterpret_cast<float4*>(yr + (size_t)row * DMOD)[tid] = r;
    }
}

// -- TF32 GEMM v5: CTA 128x256, 512 thr, warp 64x32, cp.async 3-stage, LDSM A
constexpr int BM = 128, BN = 256, BK = 32, STAGES = 3;
constexpr int GTH = 512;                                       // GEMM threads
constexpr int LDA_S = 36, LDB_S = 264;
constexpr int STAGE_F = BM * LDA_S + BK * LDB_S;               // 13056 floats
constexpr int SMEM_GEMM = STAGES * STAGE_F * 4;                // 156672 bytes

// AMODE 0: A row-major [M][K].  AMODE 1: A gathered from inter_out (B,H,TOK,DHD).
template <int AMODE>
struct ALoader {
    static __device__ __forceinline__ const float* ptr(const float* A, int gm, int gk, int K) {
        if (AMODE == 0) return A + (size_t)gm * K + gk;
        int bb = gm >> 11, nn = gm & (TOK - 1);
        int hh = gk >> 6,  dd = gk & (DHD - 1);
        return A + (((size_t)(bb * NH + hh) * TOK + nn) * DHD + dd);
    }
};

template <int AMODE>
__device__ __forceinline__ void gemm_load_stage(
    const float* __restrict__ A, const float* __restrict__ B, int ldb,
    int m0, int nb, int kb, int K, uint32_t smem_stage) {
#pragma unroll
    for (int i = 0; i < 2; i++) {                // A: 128x32 = 1024 chunks / 512 thr
        int c = i * GTH + threadIdx.x;
        int row = c >> 3, kc = (c & 7) << 2;
        const float* src = ALoader<AMODE>::ptr(A, m0 + row, kb + kc, K);
        cp_async16(smem_stage + (uint32_t)(row * LDA_S + kc) * 4u, src);
    }
    const uint32_t bs = smem_stage + (uint32_t)(BM * LDA_S) * 4u;
#pragma unroll
    for (int i = 0; i < 4; i++) {                // B: 32x256 = 2048 chunks / 512 thr
        int c = i * GTH + threadIdx.x;
        int row = c >> 6, col = (c & 63) << 2;
        cp_async16(bs + (uint32_t)(row * LDB_S + col) * 4u,
                   B + (size_t)(kb + row) * ldb + nb + col);
    }
}

// A fragments via ldmatrix.x4 (one per mt per kk); B via LDS.32.
__device__ __forceinline__ void gemm_compute_stage(
    uint32_t st_u, const float* __restrict__ st, int wm, int wn,
    float acc[4][4][4]) {
    const int lane = threadIdx.x & 31;
    const int g = lane >> 2, tg = lane & 3;
    const uint32_t a_base = st_u +
        (uint32_t)((wm + (lane & 15)) * LDA_S + ((lane >> 4) << 2)) * 4u;
    const float* Bs = st + BM * LDA_S;
#pragma unroll
    for (int kk = 0; kk < BK; kk += 8) {
        uint32_t af[4][4];
#pragma unroll
        for (int mt = 0; mt < 4; mt++) {
            LDSM_X4(af[mt][0], af[mt][1], af[mt][2], af[mt][3],
                    a_base + (uint32_t)(mt * 16 * LDA_S + kk) * 4u);
        }
        uint32_t bf[4][2];
#pragma unroll
        for (int nt = 0; nt < 4; nt++) {
            const float* br = Bs + (kk + tg) * LDB_S + wn + nt * 8 + g;
            bf[nt][0] = __float_as_uint(br[0]);
            bf[nt][1] = __float_as_uint(br[4 * LDB_S]);
        }
#pragma unroll
        for (int mt = 0; mt < 4; mt++)
#pragma unroll
            for (int nt = 0; nt < 4; nt++)
                mma_tf32(acc[mt][nt], af[mt], bf[nt][0], bf[nt][1]);
    }
}

// ---- standard output: C row-major (ldc = N), optional bias + residual -----
template <int AMODE>
__global__ __launch_bounds__(GTH, 1)
void gemm3_kernel(const float* __restrict__ A, const float* __restrict__ B,
                  float* __restrict__ C, int M, int N, int K,
                  const float* __restrict__ bias, const float* __restrict__ res) {
    extern __shared__ float sm[];
    const uint32_t smem_u = (uint32_t)__cvta_generic_to_shared(sm);
    const int tid = threadIdx.x, wid = tid >> 5, lane = tid & 31;
    const int g = lane >> 2, tg = lane & 3;
    const int m0 = blockIdx.y * BM;
    const int n0 = blockIdx.x * BN;
    const int wm = (wid & 1) * 64;     // 2 warp-rows of 64
    const int wn = (wid >> 1) * 32;    // 8 warp-cols of 32

    float acc[4][4][4];
#pragma unroll
    for (int i = 0; i < 4; i++)
#pragma unroll
        for (int j = 0; j < 4; j++)
#pragma unroll
            for (int k = 0; k < 4; k++) acc[i][j][k] = 0.f;

    const int T = K / BK;
    gemm_load_stage<AMODE>(A, B, N, m0, n0, 0, K, smem_u);
    cp_commit();
    gemm_load_stage<AMODE>(A, B, N, m0, n0, BK, K, smem_u + STAGE_F * 4);
    cp_commit();

    int s = 0;
    for (int kt = 0; kt < T; kt++) {
        cp_wait1();
        __syncthreads();
        if (kt + 2 < T) {
            int s2 = (s + 2 >= STAGES) ? s + 2 - STAGES : s + 2;
            gemm_load_stage<AMODE>(A, B, N, m0, n0, (kt + 2) * BK, K,
                                   smem_u + (uint32_t)s2 * STAGE_F * 4);
        }
        cp_commit();
        gemm_compute_stage(smem_u + (uint32_t)s * STAGE_F * 4, sm + s * STAGE_F,
                           wm, wn, acc);
        s = (s + 1 == STAGES) ? 0 : s + 1;
    }

#pragma unroll
    for (int mt = 0; mt < 4; mt++) {
        const int r0 = m0 + wm + mt * 16 + g;
        const int r1 = r0 + 8;
#pragma unroll
        for (int nt = 0; nt < 4; nt++) {
            const int c = n0 + wn + nt * 8 + 2 * tg;
            float2 v0 = make_float2(acc[mt][nt][0], acc[mt][nt][1]);
            float2 v1 = make_float2(acc[mt][nt][2], acc[mt][nt][3]);
            if (bias) {
                float2 bb = *reinterpret_cast<const float2*>(bias + c);
                v0.x += bb.x; v0.y += bb.y; v1.x += bb.x; v1.y += bb.y;
            }
            if (res) {
                float2 q0r = *reinterpret_cast<const float2*>(res + (size_t)r0 * N + c);
                float2 q1r = *reinterpret_cast<const float2*>(res + (size_t)r1 * N + c);
                v0.x += q0r.x; v0.y += q0r.y; v1.x += q1r.x; v1.y += q1r.y;
            }
            *reinterpret_cast<float2*>(C + (size_t)r0 * N + c) = v0;
            *reinterpret_cast<float2*>(C + (size_t)r1 * N + c) = v1;
        }
    }
}

// ---- fused QKV: one GEMM over N=3072, scatter into q_bh/k_bh/v_bh ---------
// Also writes rounded K copy (token-major) and rounded V copy TRANSPOSED.
__global__ __launch_bounds__(GTH, 1)
void gemm_qkv_kernel(const float* __restrict__ A, const float* __restrict__ W,
                     float* __restrict__ Cq, float* __restrict__ Ck,
                     float* __restrict__ Cv, float* __restrict__ Ckr,
                     float* __restrict__ Cvt) {
    extern __shared__ float sm[];
    const uint32_t smem_u = (uint32_t)__cvta_generic_to_shared(sm);
    const int tid = threadIdx.x, wid = tid >> 5, lane = tid & 31;
    const int g = lane >> 2, tg = lane & 3;
    const int m0 = blockIdx.y * BM;
    const int arr = blockIdx.x >> 2;                 // 0..2 : which weight/output
    const int nb  = (blockIdx.x & 3) * BN;           // column base within the array
    const float* B = W + (size_t)arr * DMOD * DMOD;  // Wq/Wk/Wv pre-rounded, contiguous
    float* C  = (arr == 0) ? Cq : (arr == 1) ? Ck : Cv;
    const int wm = (wid & 1) * 64;
    const int wn = (wid >> 1) * 32;
    const int K = DMOD;

    float acc[4][4][4];
#pragma unroll
    for (int i = 0; i < 4; i++)
#pragma unroll
        for (int j = 0; j < 4; j++)
#pragma unroll
            for (int k = 0; k < 4; k++) acc[i][j][k] = 0.f;

    const int T = K / BK;
    gemm_load_stage<0>(A, B, DMOD, m0, nb, 0, K, smem_u);
    cp_commit();
    gemm_load_stage<0>(A, B, DMOD, m0, nb, BK, K, smem_u + STAGE_F * 4);
    cp_commit();

    int s = 0;
    for (int kt = 0; kt < T; kt++) {
        cp_wait1();
        __syncthreads();
        if (kt + 2 < T) {
            int s2 = (s + 2 >= STAGES) ? s + 2 - STAGES : s + 2;
            gemm_load_stage<0>(A, B, DMOD, m0, nb, (kt + 2) * BK, K,
                               smem_u + (uint32_t)s2 * STAGE_F * 4);
        }
        cp_commit();
        gemm_compute_stage(smem_u + (uint32_t)s * STAGE_F * 4, sm + s * STAGE_F,
                           wm, wn, acc);
        s = (s + 1 == STAGES) ? 0 : s + 1;
    }

    // scatter to (B*H, TOK, DHD) (+ rounded copies for flash)
#pragma unroll
    for (int mt = 0; mt < 4; mt++) {
        const int r0 = m0 + wm + mt * 16 + g;
        const int r1 = r0 + 8;
        const int b0_ = r0 >> 11, n0_ = r0 & (TOK - 1);
        const int b1_ = r1 >> 11, n1_ = r1 & (TOK - 1);
#pragma unroll
        for (int nt = 0; nt < 4; nt++) {
            const int cl = nb + wn + nt * 8 + 2 * tg;
            const int hh = cl >> 6, dd = cl & (DHD - 1);
            const size_t o0 = ((size_t)(b0_ * NH + hh) * TOK + n0_) * DHD + dd;
            const size_t o1 = ((size_t)(b1_ * NH + hh) * TOK + n1_) * DHD + dd;
            float2 v0 = make_float2(acc[mt][nt][0], acc[mt][nt][1]);
            float2 v1 = make_float2(acc[mt][nt][2], acc[mt][nt][3]);
            *reinterpret_cast<float2*>(C + o0) = v0;
            *reinterpret_cast<float2*>(C + o1) = v1;
            if (arr == 1) {
                float2 r0v = make_float2(f2tf32f(v0.x), f2tf32f(v0.y));
                float2 r1v = make_float2(f2tf32f(v1.x), f2tf32f(v1.y));
                *reinterpret_cast<float2*>(Ckr + o0) = r0v;
                *reinterpret_cast<float2*>(Ckr + o1) = r1v;
            } else if (arr == 2) {
                const size_t t0 = ((size_t)(b0_ * NH + hh) * DHD + dd) * TOK + n0_;
                const size_t t1 = ((size_t)(b1_ * NH + hh) * DHD + dd) * TOK + n1_;
                Cvt[t0]       = f2tf32f(v0.x);
                Cvt[t0 + TOK] = f2tf32f(v0.y);
                Cvt[t1]       = f2tf32f(v1.x);
                Cvt[t1 + TOK] = f2tf32f(v1.y);
            }
        }
    }
}

// ---------------- flash attention v3: LDSM everywhere -----------------------
// K from rounded token-major copy; V from rounded TRANSPOSED copy; P via smem.
constexpr int FA_LDK    = DHD + 4;                  // 68 floats/row (K tile)
constexpr int FA_LDVT   = 128 + 4;                  // 132 floats/row (Vt tile)
constexpr int FA_KTILE  = 128 * FA_LDK;             // 8704 floats
constexpr int FA_VTILE  = DHD * FA_LDVT;            // 8448 floats
constexpr int FA_STAGE_F = FA_KTILE + FA_VTILE;     // 17152 floats
constexpr int FA_P_OFF  = 2 * FA_STAGE_F;           // P strip after 2 KV stages
constexpr int FA_LDP    = 132;                      // P row stride (floats)
constexpr int SMEM_FA   = (FA_P_OFF + 128 * FA_LDP) * 4;  // 204800 bytes

__global__ __launch_bounds__(256)
void flash_attn_kernel(const float* __restrict__ Q, const float* __restrict__ Kr,
                       const float* __restrict__ Vt, float* __restrict__ O,
                       float* __restrict__ Or) {
    extern __shared__ float sm[];
    const uint32_t smem_u = (uint32_t)__cvta_generic_to_shared(sm);

    const int tid = threadIdx.x, wid = tid >> 5, lane = tid & 31;
    const int g = lane >> 2, tg = lane & 3;
    const int bh = blockIdx.y;
    const int q0 = blockIdx.x * 128;
    const float* Qp  = Q  + (size_t)bh * TOK * DHD;
    const float* Kp  = Kr + (size_t)bh * TOK * DHD;
    const float* Vtp = Vt + (size_t)bh * DHD * TOK;   // [dh][token]
    float* Op  = O  + (size_t)bh * TOK * DHD;
    float* Opr = Or + (size_t)bh * TOK * DHD;
    const int wm = wid * 16;
    const int r0 = q0 + wm + g, r1 = r0 + 8;

    // Q fragments (scaled by 1/8 exact, tf32-rounded)
    uint32_t qf[8][4];
#pragma unroll
    for (int ks = 0; ks < 8; ks++) {
        int c = ks * 8 + tg;
        qf[ks][0] = f2tf32(Qp[(size_t)r0 * DHD + c] * 0.125f);
        qf[ks][1] = f2tf32(Qp[(size_t)r1 * DHD + c] * 0.125f);
        qf[ks][2] = f2tf32(Qp[(size_t)r0 * DHD + c + 4] * 0.125f);
        qf[ks][3] = f2tf32(Qp[(size_t)r1 * DHD + c + 4] * 0.125f);
    }

    // ldmatrix per-lane offsets (bytes)
    const uint32_t ldsk_off =
        (uint32_t)((((lane & 7) + ((lane >> 4) & 1) * 8) * FA_LDK +
                    ((lane >> 3) & 1) * 4)) * 4u;
    const uint32_t ldsv_off =
        (uint32_t)((((lane & 7) + ((lane >> 4) & 1) * 8) * FA_LDVT +
                    ((lane >> 3) & 1) * 4)) * 4u;
    // P strip addresses
    const uint32_t p_u = smem_u + (uint32_t)FA_P_OFF * 4u;
    const uint32_t p_st0 = p_u + (uint32_t)((wm + g) * FA_LDP + 2 * tg) * 4u;
    const uint32_t p_st1 = p_u + (uint32_t)((wm + 8 + g) * FA_LDP + 2 * tg) * 4u;
    const uint32_t p_ld  = p_u +
        (uint32_t)((wm + (lane & 15)) * FA_LDP + ((lane >> 4) << 2)) * 4u;

    float m0 = -1e30f, m1 = -1e30f, l0 = 0.f, l1 = 0.f;
    float o[8][4];
#pragma unroll
    for (int i = 0; i < 8; i++)
#pragma unroll
        for (int j = 0; j < 4; j++) o[i][j] = 0.f;

    auto loadKV = [&](int j, int st) {
        const uint32_t kd = smem_u + (uint32_t)st * FA_STAGE_F * 4u;
        const uint32_t vd = kd + (uint32_t)FA_KTILE * 4u;
#pragma unroll
        for (int i = 0; i < 8; i++) {          // K: 128 tok x 64 dh
            int s = tid + i * 256;
            int r = s >> 4, c = (s & 15) << 2;
            cp_async16(kd + (uint32_t)(r * FA_LDK + c) * 4u,
                       Kp + (size_t)(j + r) * DHD + c);
        }
#pragma unroll
        for (int i = 0; i < 8; i++) {          // Vt: 64 dh x 128 tok
            int s = tid + i * 256;
            int r = s >> 5, c = (s & 31) << 2;
            cp_async16(vd + (uint32_t)(r * FA_LDVT + c) * 4u,
                       Vtp + (size_t)r * TOK + j + c);
        }
    };

    loadKV(0, 0);
    cp_commit();

    const int NT = TOK / 128;
    for (int jt = 0; jt < NT; jt++) {
        if (jt + 1 < NT) {
            loadKV((jt + 1) * 128, (jt + 1) & 1);
            cp_commit();
            cp_wait1();
        } else {
            cp_wait0();
        }
        __syncthreads();

        const int st = jt & 1;
        const uint32_t ks_u = smem_u + (uint32_t)st * FA_STAGE_F * 4u;
        const uint32_t vt_u = ks_u + (uint32_t)FA_KTILE * 4u;

        // S = (Q/8) K^T : B-frags via ldmatrix
        float sc[16][4];
#pragma unroll
        for (int nt = 0; nt < 16; nt++)
#pragma unroll
            for (int k4 = 0; k4 < 4; k4++) sc[nt][k4] = 0.f;
#pragma unroll
        for (int ks = 0; ks < 8; ks++) {
            const uint32_t kaddr = ks_u + (uint32_t)(ks * 8) * 4u + ldsk_off;
#pragma unroll
            for (int nt4 = 0; nt4 < 4; nt4++) {
                uint32_t bf[4][2];
                LDSM_X4(bf[0][0], bf[0][1], bf[1][0], bf[1][1],
                        kaddr + (uint32_t)(nt4 * 32 * FA_LDK) * 4u);
                LDSM_X4(bf[2][0], bf[2][1], bf[3][0], bf[3][1],
                        kaddr + (uint32_t)((nt4 * 32 + 16) * FA_LDK) * 4u);
#pragma unroll
                for (int c4 = 0; c4 < 4; c4++)
                    mma_tf32(sc[nt4 * 4 + c4], qf[ks], bf[c4][0], bf[c4][1]);
            }
        }

        // online softmax; rounded P goes straight to smem strip
        float tm0 = -1e30f, tm1 = -1e30f;
#pragma unroll
        for (int nt = 0; nt < 16; nt++) {
            tm0 = fmaxf(tm0, fmaxf(sc[nt][0], sc[nt][1]));
            tm1 = fmaxf(tm1, fmaxf(sc[nt][2], sc[nt][3]));
        }
        tm0 = fmaxf(tm0, __shfl_xor_sync(0xffffffffu, tm0, 1));
        tm0 = fmaxf(tm0, __shfl_xor_sync(0xffffffffu, tm0, 2));
        tm1 = fmaxf(tm1, __shfl_xor_sync(0xffffffffu, tm1, 1));
        tm1 = fmaxf(tm1, __shfl_xor_sync(0xffffffffu, tm1, 2));
        const float nm0 = fmaxf(m0, tm0), nm1 = fmaxf(m1, tm1);
        const float a0 = __expf(m0 - nm0), a1 = __expf(m1 - nm1);
        float ts0 = 0.f, ts1 = 0.f;
#pragma unroll
        for (int nt = 0; nt < 16; nt++) {
            float p0 = __expf(sc[nt][0] - nm0);
            float p1 = __expf(sc[nt][1] - nm0);
            float p2 = __expf(sc[nt][2] - nm1);
            float p3 = __expf(sc[nt][3] - nm1);
            ts0 += p0 + p1; ts1 += p2 + p3;
            STS64(p_st0 + (uint32_t)(nt * 8) * 4u, f2tf32f(p0), f2tf32f(p1));
            STS64(p_st1 + (uint32_t)(nt * 8) * 4u, f2tf32f(p2), f2tf32f(p3));
        }
        __syncwarp();
        ts0 += __shfl_xor_sync(0xffffffffu, ts0, 1);
        ts0 += __shfl_xor_sync(0xffffffffu, ts0, 2);
        ts1 += __shfl_xor_sync(0xffffffffu, ts1, 1);
        ts1 += __shfl_xor_sync(0xffffffffu, ts1, 2);
        l0 = l0 * a0 + ts0; l1 = l1 * a1 + ts1;
        m0 = nm0; m1 = nm1;
#pragma unroll
        for (int nt = 0; nt < 8; nt++) {
            o[nt][0] *= a0; o[nt][1] *= a0; o[nt][2] *= a1; o[nt][3] *= a1;
        }

        // O += P @ V : A-frags from P strip, B-frags from Vt, all ldmatrix
#pragma unroll
        for (int kt = 0; kt < 16; kt++) {
            uint32_t af[4];
            LDSM_X4(af[0], af[1], af[2], af[3], p_ld + (uint32_t)(kt * 8) * 4u);
            const uint32_t vaddr = vt_u + (uint32_t)(kt * 8) * 4u + ldsv_off;
#pragma unroll
            for (int ntp = 0; ntp < 4; ntp++) {
                uint32_t vb[4];
                LDSM_X4(vb[0], vb[1], vb[2], vb[3],
                        vaddr + (uint32_t)(ntp * 16 * FA_LDVT) * 4u);
                mma_tf32(o[2 * ntp],     af, vb[0], vb[1]);
                mma_tf32(o[2 * ntp + 1], af, vb[2], vb[3]);
            }
        }
        __syncthreads();
    }

    const float il0 = 1.f / l0, il1 = 1.f / l1;
#pragma unroll
    for (int nt = 0; nt < 8; nt++) {
        int c = nt * 8 + 2 * tg;
        float2 v0 = make_float2(o[nt][0] * il0, o[nt][1] * il0);
        float2 v1 = make_float2(o[nt][2] * il1, o[nt][3] * il1);
        *reinterpret_cast<float2*>(Op + (size_t)r0 * DHD + c) = v0;
        *reinterpret_cast<float2*>(Op + (size_t)r1 * DHD + c) = v1;
        float2 r0v = make_float2(f2tf32f(v0.x), f2tf32f(v0.y));
        float2 r1v = make_float2(f2tf32f(v1.x), f2tf32f(v1.y));
        *reinterpret_cast<float2*>(Opr + (size_t)r0 * DHD + c) = r0v;
        *reinterpret_cast<float2*>(Opr + (size_t)r1 * DHD + c) = r1v;
    }
}

// ---------------- GEGLU (output tf32-rounded; it only feeds FF2 GEMM) ------
__global__ __launch_bounds__(256)
void geglu_kernel(const float* __restrict__ h, float* __restrict__ act) {
    const int idx = blockIdx.x * 256 + threadIdx.x;
    const int m = idx >> 10;
    const int c = (idx & 1023) << 2;
    const float4 a  = *reinterpret_cast<const float4*>(h + (size_t)m * (2 * FF) + c);
    const float4 gt = *reinterpret_cast<const float4*>(h + (size_t)m * (2 * FF) + FF + c);
    float4 o;
    o.x = f2tf32f(a.x * gelu_exact(gt.x));
    o.y = f2tf32f(a.y * gelu_exact(gt.y));
    o.z = f2tf32f(a.z * gelu_exact(gt.z));
    o.w = f2tf32f(a.w * gelu_exact(gt.w));
    *reinterpret_cast<float4*>(act + (size_t)m * FF + c) = o;
}

// ---------------- launch ---------------------------------------------------
extern "C" void kernel_launch(void* const* d_in, const int* in_sizes, int n_in,
                              void* d_out, int out_size) {
    (void)in_sizes; (void)n_in; (void)out_size;
    const float* x     = (const float*)d_in[0];
    const float* Wq    = (const float*)d_in[1];
    const float* Wk    = (const float*)d_in[2];
    const float* Wv    = (const float*)d_in[3];
    const float* Wo    = (const float*)d_in[4];
    const float* bo    = (const float*)d_in[5];
    const float* ln1_g = (const float*)d_in[6];
    const float* ln1_b = (const float*)d_in[7];
    const float* ln3_g = (const float*)d_in[8];
    const float* ln3_b = (const float*)d_in[9];
    const float* Wff1  = (const float*)d_in[10];
    const float* bff1  = (const float*)d_in[11];
    const float* Wff2  = (const float*)d_in[12];
    const float* bff2  = (const float*)d_in[13];

    float* out = (float*)d_out;
    const size_t SZ = (size_t)MROWS * DMOD;
    float* out_x  = out;            // x
    float* out_q  = out + SZ;       // q_bh
    float* out_k  = out + 2 * SZ;   // k_bh
    float* out_v  = out + 3 * SZ;   // v_bh
    float* out_io = out + 4 * SZ;   // inter_out
    float* out_xf = out + 5 * SZ;   // x_features

    float *x2, *xf2, *xfr, *ior, *kr, *vtr, *hbuf, *actbuf, *wbuf;
    cudaGetSymbolAddress((void**)&x2,     g_x2);
    cudaGetSymbolAddress((void**)&xf2,    g_xf2);
    cudaGetSymbolAddress((void**)&xfr,    g_xfr);
    cudaGetSymbolAddress((void**)&ior,    g_ior);
    cudaGetSymbolAddress((void**)&kr,     g_kr);
    cudaGetSymbolAddress((void**)&vtr,    g_vtr);
    cudaGetSymbolAddress((void**)&hbuf,   g_h);
    cudaGetSymbolAddress((void**)&actbuf, g_act);
    cudaGetSymbolAddress((void**)&wbuf,   g_w);

    cudaFuncSetAttribute(gemm_qkv_kernel,
                         cudaFuncAttributeMaxDynamicSharedMemorySize, SMEM_GEMM);
    cudaFuncSetAttribute(gemm3_kernel<0>,
                         cudaFuncAttributeMaxDynamicSharedMemorySize, SMEM_GEMM);
    cudaFuncSetAttribute(gemm3_kernel<1>,
                         cudaFuncAttributeMaxDynamicSharedMemorySize, SMEM_GEMM);
    cudaFuncSetAttribute(flash_attn_kernel,
                         cudaFuncAttributeMaxDynamicSharedMemorySize, SMEM_FA);

    const dim3 blk(GTH);

    // 0) pre-round all weights to tf32, single launch (16M floats = 4M float4)
    cvt_weights_kernel<<<(16 * 1024 * 1024 / 4) / 256, 256>>>(
        (const float4*)Wq, (const float4*)Wk, (const float4*)Wv, (const float4*)Wo,
        (const float4*)Wff1, (const float4*)Wff2, (float4*)wbuf);

    // 1) LN1 -> x_features (exact) + rounded copy for GEMM A
    ln_kernel<<<MROWS, 256>>>(x, ln1_g, ln1_b, out_xf, xfr);

    // 2) fused QKV GEMM; exact q/k/v to d_out, rounded k (token-major) + v (transposed)
    gemm_qkv_kernel<<<dim3(3 * DMOD / BN, MROWS / BM), blk, SMEM_GEMM>>>(
        xfr, wbuf + WOFF_Q, out_q, out_k, out_v, kr, vtr);

    // 3) attention -> inter_out (exact) + rounded copy
    flash_attn_kernel<<<dim3(TOK / 128, NBAT * NH), 256, SMEM_FA>>>(
        out_q, kr, vtr, out_io, ior);

    // 4) Wo GEMM (gather-A from rounded inter_out) + bo + residual x -> x2 (exact)
    gemm3_kernel<1><<<dim3(DMOD / BN, MROWS / BM), blk, SMEM_GEMM>>>(
        ior, wbuf + WOFF_O, x2, MROWS, DMOD, DMOD, bo, x);

    // 5) LN3 -> xf2 (rounded only; internal)
    ln_kernel<<<MROWS, 256>>>(x2, ln3_g, ln3_b, nullptr, xf2);

    // 6) FF1 GEMM (+bff1) -> h (exact; geglu needs exact gate)
    gemm3_kernel<0><<<dim3(2 * FF / BN, MROWS / BM), blk, SMEM_GEMM>>>(
        xf2, wbuf + WOFF_FF1, hbuf, MROWS, 2 * FF, DMOD, bff1, nullptr);

    // 7) GEGLU -> act (rounded)
    geglu_kernel<<<(MROWS * (FF / 4)) / 256, 256>>>(hbuf, actbuf);

    // 8) FF2 GEMM (+bff2) + residual x2 -> final x
    gemm3_kernel<0><<<dim3(DMOD / BN, MROWS / BM), blk, SMEM_GEMM>>>(
        actbuf, wbuf + WOFF_FF2, out_x, MROWS, DMOD, FF, bff2, x2);
}

// round 13
// speedup vs baseline: 1.1298x; 1.0017x over previous
#include <cuda_runtime.h>
#include <cstdint>
#include <cstdio>

#define TOK   2048
#define NBAT  2
#define NH    16
#define DHD   64
#define DMOD  1024
#define MROWS 4096   /* B*N */
#define FF    4096

// ---------------- scratch (static device globals; no runtime allocation) ---
__device__ float g_x2 [MROWS * DMOD];            // 16 MB : x after attn residual (exact)
__device__ float g_xf2[MROWS * DMOD];            // 16 MB : LN3 output (tf32-rounded)
__device__ float g_xfr[MROWS * DMOD];            // 16 MB : LN1 output (tf32-rounded)
__device__ float g_ior[MROWS * DMOD];            // 16 MB : inter_out (tf32-rounded)
__device__ float g_kr [MROWS * DMOD];            // 16 MB : k_bh tf32-rounded
__device__ float g_vtr[MROWS * DMOD];            // 16 MB : v_bh tf32-rounded TRANSPOSED [bh][dh][tok]
__device__ float g_h  [(size_t)MROWS * 2 * FF];  // 128 MB: FF1 output (exact)
__device__ float g_act[(size_t)MROWS * FF];      // 64 MB : geglu output (tf32-rounded)
__device__ float g_w  [16 * 1024 * 1024];        // 64 MB : all weights, tf32-rounded + TRANSPOSED (n-major)
// offsets (floats) within g_w (each block is Wt = [N][K] row-major):
#define WOFF_Q    0
#define WOFF_K    (1024 * 1024)
#define WOFF_V    (2 * 1024 * 1024)
#define WOFF_O    (3 * 1024 * 1024)
#define WOFF_FF1  (4 * 1024 * 1024)
#define WOFF_FF2  (12 * 1024 * 1024)

// ---------------- helpers --------------------------------------------------
__device__ __forceinline__ uint32_t f2tf32(float x) {
    uint32_t t;
    asm("cvt.rna.tf32.f32 %0, %1;" : "=r"(t) : "f"(x));
    return t;
}
__device__ __forceinline__ float f2tf32f(float x) { return __uint_as_float(f2tf32(x)); }

__device__ __forceinline__ void mma_tf32(float c[4], const uint32_t a[4],
                                         uint32_t b0, uint32_t b1) {
    asm volatile(
        "mma.sync.aligned.m16n8k8.row.col.f32.tf32.tf32.f32 "
        "{%0,%1,%2,%3}, {%4,%5,%6,%7}, {%8,%9}, {%0,%1,%2,%3};\n"
        : "+f"(c[0]), "+f"(c[1]), "+f"(c[2]), "+f"(c[3])
        : "r"(a[0]), "r"(a[1]), "r"(a[2]), "r"(a[3]), "r"(b0), "r"(b1));
}

#define LDSM_X4(r0, r1, r2, r3, addr)                                         \
    asm volatile("ldmatrix.sync.aligned.m8n8.x4.shared.b16 {%0,%1,%2,%3}, [%4];" \
                 : "=r"(r0), "=r"(r1), "=r"(r2), "=r"(r3) : "r"(addr))

#define STS64(addr, v0, v1)                                                   \
    asm volatile("st.shared.v2.f32 [%0], {%1, %2};" :: "r"(addr), "f"(v0), "f"(v1))

__device__ __forceinline__ void cp_async16(uint32_t dst, const void* src) {
    asm volatile("cp.async.cg.shared.global [%0], [%1], 16;\n" :: "r"(dst), "l"(src));
}
__device__ __forceinline__ void cp_commit() {
    asm volatile("cp.async.commit_group;\n" ::: "memory");
}
__device__ __forceinline__ void cp_wait1() {
    asm volatile("cp.async.wait_group 1;\n" ::: "memory");
}
__device__ __forceinline__ void cp_wait0() {
    asm volatile("cp.async.wait_group 0;\n" ::: "memory");
}

__device__ __forceinline__ float gelu_exact(float x) {
    return 0.5f * x * (1.0f + erff(x * 0.70710678118654752f));
}

// ------------ weight transpose+round: src[K][N] -> dst[N][K], tf32 ----------
__global__ __launch_bounds__(256)
void cvt_t_kernel(const float* __restrict__ src, float* __restrict__ dst,
                  int K, int N) {
    __shared__ float t[32][33];
    const int k0 = blockIdx.y * 32, n0 = blockIdx.x * 32;
    const int tx = threadIdx.x & 31, ty = threadIdx.x >> 5;   // ty 0..7
#pragma unroll
    for (int i = 0; i < 32; i += 8)
        t[ty + i][tx] = f2tf32f(src[(size_t)(k0 + ty + i) * N + n0 + tx]);
    __syncthreads();
#pragma unroll
    for (int i = 0; i < 32; i += 8)
        dst[(size_t)(n0 + ty + i) * K + k0 + tx] = t[tx][ty + i];
}

// ---------------- LayerNorm (one block per row of 1024) --------------------
__global__ __launch_bounds__(256)
void ln_kernel(const float* __restrict__ x, const float* __restrict__ gw,
               const float* __restrict__ bw, float* __restrict__ y,
               float* __restrict__ yr) {
    __shared__ float red[16];
    const int row = blockIdx.x;
    const int tid = threadIdx.x;
    const float4 v = reinterpret_cast<const float4*>(x + (size_t)row * DMOD)[tid];
    float s  = v.x + v.y + v.z + v.w;
    float ss = v.x * v.x + v.y * v.y + v.z * v.z + v.w * v.w;
#pragma unroll
    for (int o = 16; o > 0; o >>= 1) {
        s  += __shfl_xor_sync(0xffffffffu, s,  o);
        ss += __shfl_xor_sync(0xffffffffu, ss, o);
    }
    if ((tid & 31) == 0) { red[tid >> 5] = s; red[8 + (tid >> 5)] = ss; }
    __syncthreads();
    float ts = 0.f, tss = 0.f;
#pragma unroll
    for (int w = 0; w < 8; w++) { ts += red[w]; tss += red[8 + w]; }
    const float mu  = ts * (1.0f / DMOD);
    const float var = tss * (1.0f / DMOD) - mu * mu;
    const float rs  = rsqrtf(var + 1e-5f);
    const float4 gv = reinterpret_cast<const float4*>(gw)[tid];
    const float4 bv = reinterpret_cast<const float4*>(bw)[tid];
    float4 o;
    o.x = (v.x - mu) * rs * gv.x + bv.x;
    o.y = (v.y - mu) * rs * gv.y + bv.y;
    o.z = (v.z - mu) * rs * gv.z + bv.z;
    o.w = (v.w - mu) * rs * gv.w + bv.w;
    if (y)  reinterpret_cast<float4*>(y  + (size_t)row * DMOD)[tid] = o;
    if (yr) {
        float4 r = make_float4(f2tf32f(o.x), f2tf32f(o.y), f2tf32f(o.z), f2tf32f(o.w));
        reinterpret_cast<float4*>(yr + (size_t)row * DMOD)[tid] = r;
    }
}

// -- TF32 GEMM v6: CTA 128x256, 512 thr, warp 64x32, cp.async 3-stage,
//    LDSM for BOTH A and B fragments (B stored n-major, weights pre-transposed)
constexpr int BM = 128, BN = 256, BK = 32, STAGES = 3;
constexpr int GTH = 512;                                       // GEMM threads
constexpr int LDA_S = 36, LDB_T = 36;
constexpr int STAGE_F = BM * LDA_S + BN * LDB_T;               // 13824 floats
constexpr int SMEM_GEMM = STAGES * STAGE_F * 4;                // 165888 bytes

// AMODE 0: A row-major [M][K].  AMODE 1: A gathered from inter_out (B,H,TOK,DHD).
template <int AMODE>
struct ALoader {
    static __device__ __forceinline__ const float* ptr(const float* A, int gm, int gk, int K) {
        if (AMODE == 0) return A + (size_t)gm * K + gk;
        int bb = gm >> 11, nn = gm & (TOK - 1);
        int hh = gk >> 6,  dd = gk & (DHD - 1);
        return A + (((size_t)(bb * NH + hh) * TOK + nn) * DHD + dd);
    }
};

// Bt: [N][K] row-major (ld = K). Tile: rows nb..nb+255, cols kb..kb+31.
template <int AMODE>
__device__ __forceinline__ void gemm_load_stage(
    const float* __restrict__ A, const float* __restrict__ Bt,
    int m0, int nb, int kb, int K, uint32_t smem_stage) {
#pragma unroll
    for (int i = 0; i < 2; i++) {                // A: 128x32 = 1024 chunks / 512 thr
        int c = i * GTH + threadIdx.x;
        int row = c >> 3, kc = (c & 7) << 2;
        const float* src = ALoader<AMODE>::ptr(A, m0 + row, kb + kc, K);
        cp_async16(smem_stage + (uint32_t)(row * LDA_S + kc) * 4u, src);
    }
    const uint32_t bs = smem_stage + (uint32_t)(BM * LDA_S) * 4u;
#pragma unroll
    for (int i = 0; i < 4; i++) {                // Bt: 256x32 = 2048 chunks / 512 thr
        int c = i * GTH + threadIdx.x;
        int row = c >> 3, kc = (c & 7) << 2;
        cp_async16(bs + (uint32_t)(row * LDB_T + kc) * 4u,
                   Bt + (size_t)(nb + row) * K + kb + kc);
    }
}

// A and B fragments both via ldmatrix.x4.
__device__ __forceinline__ void gemm_compute_stage(
    uint32_t st_u, int wm, int wn, float acc[4][4][4]) {
    const int lane = threadIdx.x & 31;
    const uint32_t a_base = st_u +
        (uint32_t)((wm + (lane & 15)) * LDA_S + ((lane >> 4) << 2)) * 4u;
    const uint32_t b_base = st_u + (uint32_t)(BM * LDA_S) * 4u +
        (uint32_t)((wn + (lane & 7) + ((lane >> 4) & 1) * 8) * LDB_T +
                   ((lane >> 3) & 1) * 4) * 4u;
#pragma unroll
    for (int kk = 0; kk < BK; kk += 8) {
        uint32_t af[4][4];
#pragma unroll
        for (int mt = 0; mt < 4; mt++) {
            LDSM_X4(af[mt][0], af[mt][1], af[mt][2], af[mt][3],
                    a_base + (uint32_t)(mt * 16 * LDA_S + kk) * 4u);
        }
        uint32_t bf0[4], bf1[4];
        LDSM_X4(bf0[0], bf0[1], bf0[2], bf0[3], b_base + (uint32_t)kk * 4u);
        LDSM_X4(bf1[0], bf1[1], bf1[2], bf1[3],
                b_base + (uint32_t)(16 * LDB_T + kk) * 4u);
#pragma unroll
        for (int mt = 0; mt < 4; mt++) {
            mma_tf32(acc[mt][0], af[mt], bf0[0], bf0[1]);
            mma_tf32(acc[mt][1], af[mt], bf0[2], bf0[3]);
            mma_tf32(acc[mt][2], af[mt], bf1[0], bf1[1]);
            mma_tf32(acc[mt][3], af[mt], bf1[2], bf1[3]);
        }
    }
}

// ---- standard output: C row-major (ldc = N), optional bias + residual -----
template <int AMODE>
__global__ __launch_bounds__(GTH, 1)
void gemm3_kernel(const float* __restrict__ A, const float* __restrict__ Bt,
                  float* __restrict__ C, int M, int N, int K,
                  const float* __restrict__ bias, const float* __restrict__ res) {
    extern __shared__ float sm[];
    const uint32_t smem_u = (uint32_t)__cvta_generic_to_shared(sm);
    const int tid = threadIdx.x, wid = tid >> 5, lane = tid & 31;
    const int g = lane >> 2, tg = lane & 3;
    const int m0 = blockIdx.y * BM;
    const int n0 = blockIdx.x * BN;
    const int wm = (wid & 1) * 64;     // 2 warp-rows of 64
    const int wn = (wid >> 1) * 32;    // 8 warp-cols of 32

    float acc[4][4][4];
#pragma unroll
    for (int i = 0; i < 4; i++)
#pragma unroll
        for (int j = 0; j < 4; j++)
#pragma unroll
            for (int k = 0; k < 4; k++) acc[i][j][k] = 0.f;

    const int T = K / BK;
    gemm_load_stage<AMODE>(A, Bt, m0, n0, 0, K, smem_u);
    cp_commit();
    gemm_load_stage<AMODE>(A, Bt, m0, n0, BK, K, smem_u + STAGE_F * 4);
    cp_commit();

    int s = 0;
    for (int kt = 0; kt < T; kt++) {
        cp_wait1();
        __syncthreads();
        if (kt + 2 < T) {
            int s2 = (s + 2 >= STAGES) ? s + 2 - STAGES : s + 2;
            gemm_load_stage<AMODE>(A, Bt, m0, n0, (kt + 2) * BK, K,
                                   smem_u + (uint32_t)s2 * STAGE_F * 4);
        }
        cp_commit();
        gemm_compute_stage(smem_u + (uint32_t)s * STAGE_F * 4, wm, wn, acc);
        s = (s + 1 == STAGES) ? 0 : s + 1;
    }

#pragma unroll
    for (int mt = 0; mt < 4; mt++) {
        const int r0 = m0 + wm + mt * 16 + g;
        const int r1 = r0 + 8;
#pragma unroll
        for (int nt = 0; nt < 4; nt++) {
            const int c = n0 + wn + nt * 8 + 2 * tg;
            float2 v0 = make_float2(acc[mt][nt][0], acc[mt][nt][1]);
            float2 v1 = make_float2(acc[mt][nt][2], acc[mt][nt][3]);
            if (bias) {
                float2 bb = *reinterpret_cast<const float2*>(bias + c);
                v0.x += bb.x; v0.y += bb.y; v1.x += bb.x; v1.y += bb.y;
            }
            if (res) {
                float2 q0r = *reinterpret_cast<const float2*>(res + (size_t)r0 * N + c);
                float2 q1r = *reinterpret_cast<const float2*>(res + (size_t)r1 * N + c);
                v0.x += q0r.x; v0.y += q0r.y; v1.x += q1r.x; v1.y += q1r.y;
            }
            *reinterpret_cast<float2*>(C + (size_t)r0 * N + c) = v0;
            *reinterpret_cast<float2*>(C + (size_t)r1 * N + c) = v1;
        }
    }
}

// ---- fused QKV: one GEMM over N=3072, scatter into q_bh/k_bh/v_bh ---------
// Also writes rounded K copy (token-major) and rounded V copy TRANSPOSED.
__global__ __launch_bounds__(GTH, 1)
void gemm_qkv_kernel(const float* __restrict__ A, const float* __restrict__ Wt,
                     float* __restrict__ Cq, float* __restrict__ Ck,
                     float* __restrict__ Cv, float* __restrict__ Ckr,
                     float* __restrict__ Cvt) {
    extern __shared__ float sm[];
    const uint32_t smem_u = (uint32_t)__cvta_generic_to_shared(sm);
    const int tid = threadIdx.x, wid = tid >> 5, lane = tid & 31;
    const int g = lane >> 2, tg = lane & 3;
    const int m0 = blockIdx.y * BM;
    const int arr = blockIdx.x >> 2;                 // 0..2 : which weight/output
    const int nb  = (blockIdx.x & 3) * BN;           // column base within the array
    const float* Bt = Wt + (size_t)arr * DMOD * DMOD; // Wq^T/Wk^T/Wv^T contiguous
    float* C  = (arr == 0) ? Cq : (arr == 1) ? Ck : Cv;
    const int wm = (wid & 1) * 64;
    const int wn = (wid >> 1) * 32;
    const int K = DMOD;

    float acc[4][4][4];
#pragma unroll
    for (int i = 0; i < 4; i++)
#pragma unroll
        for (int j = 0; j < 4; j++)
#pragma unroll
            for (int k = 0; k < 4; k++) acc[i][j][k] = 0.f;

    const int T = K / BK;
    gemm_load_stage<0>(A, Bt, m0, nb, 0, K, smem_u);
    cp_commit();
    gemm_load_stage<0>(A, Bt, m0, nb, BK, K, smem_u + STAGE_F * 4);
    cp_commit();

    int s = 0;
    for (int kt = 0; kt < T; kt++) {
        cp_wait1();
        __syncthreads();
        if (kt + 2 < T) {
            int s2 = (s + 2 >= STAGES) ? s + 2 - STAGES : s + 2;
            gemm_load_stage<0>(A, Bt, m0, nb, (kt + 2) * BK, K,
                               smem_u + (uint32_t)s2 * STAGE_F * 4);
        }
        cp_commit();
        gemm_compute_stage(smem_u + (uint32_t)s * STAGE_F * 4, wm, wn, acc);
        s = (s + 1 == STAGES) ? 0 : s + 1;
    }

    // scatter to (B*H, TOK, DHD) (+ rounded copies for flash)
#pragma unroll
    for (int mt = 0; mt < 4; mt++) {
        const int r0 = m0 + wm + mt * 16 + g;
        const int r1 = r0 + 8;
        const int b0_ = r0 >> 11, n0_ = r0 & (TOK - 1);
        const int b1_ = r1 >> 11, n1_ = r1 & (TOK - 1);
#pragma unroll
        for (int nt = 0; nt < 4; nt++) {
            const int cl = nb + wn + nt * 8 + 2 * tg;
            const int hh = cl >> 6, dd = cl & (DHD - 1);
            const size_t o0 = ((size_t)(b0_ * NH + hh) * TOK + n0_) * DHD + dd;
            const size_t o1 = ((size_t)(b1_ * NH + hh) * TOK + n1_) * DHD + dd;
            float2 v0 = make_float2(acc[mt][nt][0], acc[mt][nt][1]);
            float2 v1 = make_float2(acc[mt][nt][2], acc[mt][nt][3]);
            *reinterpret_cast<float2*>(C + o0) = v0;
            *reinterpret_cast<float2*>(C + o1) = v1;
            if (arr == 1) {
                float2 r0v = make_float2(f2tf32f(v0.x), f2tf32f(v0.y));
                float2 r1v = make_float2(f2tf32f(v1.x), f2tf32f(v1.y));
                *reinterpret_cast<float2*>(Ckr + o0) = r0v;
                *reinterpret_cast<float2*>(Ckr + o1) = r1v;
            } else if (arr == 2) {
                const size_t t0 = ((size_t)(b0_ * NH + hh) * DHD + dd) * TOK + n0_;
                const size_t t1 = ((size_t)(b1_ * NH + hh) * DHD + dd) * TOK + n1_;
                Cvt[t0]       = f2tf32f(v0.x);
                Cvt[t0 + TOK] = f2tf32f(v0.y);
                Cvt[t1]       = f2tf32f(v1.x);
                Cvt[t1 + TOK] = f2tf32f(v1.y);
            }
        }
    }
}

// ---------------- flash attention v3: LDSM everywhere -----------------------
// K from rounded token-major copy; V from rounded TRANSPOSED copy; P via smem.
constexpr int FA_LDK    = DHD + 4;                  // 68 floats/row (K tile)
constexpr int FA_LDVT   = 128 + 4;                  // 132 floats/row (Vt tile)
constexpr int FA_KTILE  = 128 * FA_LDK;             // 8704 floats
constexpr int FA_VTILE  = DHD * FA_LDVT;            // 8448 floats
constexpr int FA_STAGE_F = FA_KTILE + FA_VTILE;     // 17152 floats
constexpr int FA_P_OFF  = 2 * FA_STAGE_F;           // P strip after 2 KV stages
constexpr int FA_LDP    = 132;                      // P row stride (floats)
constexpr int SMEM_FA   = (FA_P_OFF + 128 * FA_LDP) * 4;  // 204800 bytes

__global__ __launch_bounds__(256)
void flash_attn_kernel(const float* __restrict__ Q, const float* __restrict__ Kr,
                       const float* __restrict__ Vt, float* __restrict__ O,
                       float* __restrict__ Or) {
    extern __shared__ float sm[];
    const uint32_t smem_u = (uint32_t)__cvta_generic_to_shared(sm);

    const int tid = threadIdx.x, wid = tid >> 5, lane = tid & 31;
    const int g = lane >> 2, tg = lane & 3;
    const int bh = blockIdx.y;
    const int q0 = blockIdx.x * 128;
    const float* Qp  = Q  + (size_t)bh * TOK * DHD;
    const float* Kp  = Kr + (size_t)bh * TOK * DHD;
    const float* Vtp = Vt + (size_t)bh * DHD * TOK;   // [dh][token]
    float* Op  = O  + (size_t)bh * TOK * DHD;
    float* Opr = Or + (size_t)bh * TOK * DHD;
    const int wm = wid * 16;
    const int r0 = q0 + wm + g, r1 = r0 + 8;

    // Q fragments (scaled by 1/8 exact, tf32-rounded)
    uint32_t qf[8][4];
#pragma unroll
    for (int ks = 0; ks < 8; ks++) {
        int c = ks * 8 + tg;
        qf[ks][0] = f2tf32(Qp[(size_t)r0 * DHD + c] * 0.125f);
        qf[ks][1] = f2tf32(Qp[(size_t)r1 * DHD + c] * 0.125f);
        qf[ks][2] = f2tf32(Qp[(size_t)r0 * DHD + c + 4] * 0.125f);
        qf[ks][3] = f2tf32(Qp[(size_t)r1 * DHD + c + 4] * 0.125f);
    }

    // ldmatrix per-lane offsets (bytes)
    const uint32_t ldsk_off =
        (uint32_t)((((lane & 7) + ((lane >> 4) & 1) * 8) * FA_LDK +
                    ((lane >> 3) & 1) * 4)) * 4u;
    const uint32_t ldsv_off =
        (uint32_t)((((lane & 7) + ((lane >> 4) & 1) * 8) * FA_LDVT +
                    ((lane >> 3) & 1) * 4)) * 4u;
    // P strip addresses
    const uint32_t p_u = smem_u + (uint32_t)FA_P_OFF * 4u;
    const uint32_t p_st0 = p_u + (uint32_t)((wm + g) * FA_LDP + 2 * tg) * 4u;
    const uint32_t p_st1 = p_u + (uint32_t)((wm + 8 + g) * FA_LDP + 2 * tg) * 4u;
    const uint32_t p_ld  = p_u +
        (uint32_t)((wm + (lane & 15)) * FA_LDP + ((lane >> 4) << 2)) * 4u;

    float m0 = -1e30f, m1 = -1e30f, l0 = 0.f, l1 = 0.f;
    float o[8][4];
#pragma unroll
    for (int i = 0; i < 8; i++)
#pragma unroll
        for (int j = 0; j < 4; j++) o[i][j] = 0.f;

    auto loadKV = [&](int j, int st) {
        const uint32_t kd = smem_u + (uint32_t)st * FA_STAGE_F * 4u;
        const uint32_t vd = kd + (uint32_t)FA_KTILE * 4u;
#pragma unroll
        for (int i = 0; i < 8; i++) {          // K: 128 tok x 64 dh
            int s = tid + i * 256;
            int r = s >> 4, c = (s & 15) << 2;
            cp_async16(kd + (uint32_t)(r * FA_LDK + c) * 4u,
                       Kp + (size_t)(j + r) * DHD + c);
        }
#pragma unroll
        for (int i = 0; i < 8; i++) {          // Vt: 64 dh x 128 tok
            int s = tid + i * 256;
            int r = s >> 5, c = (s & 31) << 2;
            cp_async16(vd + (uint32_t)(r * FA_LDVT + c) * 4u,
                       Vtp + (size_t)r * TOK + j + c);
        }
    };

    loadKV(0, 0);
    cp_commit();

    const int NT = TOK / 128;
    for (int jt = 0; jt < NT; jt++) {
        if (jt + 1 < NT) {
            loadKV((jt + 1) * 128, (jt + 1) & 1);
            cp_commit();
            cp_wait1();
        } else {
            cp_wait0();
        }
        __syncthreads();

        const int st = jt & 1;
        const uint32_t ks_u = smem_u + (uint32_t)st * FA_STAGE_F * 4u;
        const uint32_t vt_u = ks_u + (uint32_t)FA_KTILE * 4u;

        // S = (Q/8) K^T : B-frags via ldmatrix
        float sc[16][4];
#pragma unroll
        for (int nt = 0; nt < 16; nt++)
#pragma unroll
            for (int k4 = 0; k4 < 4; k4++) sc[nt][k4] = 0.f;
#pragma unroll
        for (int ks = 0; ks < 8; ks++) {
            const uint32_t kaddr = ks_u + (uint32_t)(ks * 8) * 4u + ldsk_off;
#pragma unroll
            for (int nt4 = 0; nt4 < 4; nt4++) {
                uint32_t bf[4][2];
                LDSM_X4(bf[0][0], bf[0][1], bf[1][0], bf[1][1],
                        kaddr + (uint32_t)(nt4 * 32 * FA_LDK) * 4u);
                LDSM_X4(bf[2][0], bf[2][1], bf[3][0], bf[3][1],
                        kaddr + (uint32_t)((nt4 * 32 + 16) * FA_LDK) * 4u);
#pragma unroll
                for (int c4 = 0; c4 < 4; c4++)
                    mma_tf32(sc[nt4 * 4 + c4], qf[ks], bf[c4][0], bf[c4][1]);
            }
        }

        // online softmax; rounded P goes straight to smem strip
        float tm0 = -1e30f, tm1 = -1e30f;
#pragma unroll
        for (int nt = 0; nt < 16; nt++) {
            tm0 = fmaxf(tm0, fmaxf(sc[nt][0], sc[nt][1]));
            tm1 = fmaxf(tm1, fmaxf(sc[nt][2], sc[nt][3]));
        }
        tm0 = fmaxf(tm0, __shfl_xor_sync(0xffffffffu, tm0, 1));
        tm0 = fmaxf(tm0, __shfl_xor_sync(0xffffffffu, tm0, 2));
        tm1 = fmaxf(tm1, __shfl_xor_sync(0xffffffffu, tm1, 1));
        tm1 = fmaxf(tm1, __shfl_xor_sync(0xffffffffu, tm1, 2));
        const float nm0 = fmaxf(m0, tm0), nm1 = fmaxf(m1, tm1);
        const float a0 = __expf(m0 - nm0), a1 = __expf(m1 - nm1);
        float ts0 = 0.f, ts1 = 0.f;
#pragma unroll
        for (int nt = 0; nt < 16; nt++) {
            float p0 = __expf(sc[nt][0] - nm0);
            float p1 = __expf(sc[nt][1] - nm0);
            float p2 = __expf(sc[nt][2] - nm1);
            float p3 = __expf(sc[nt][3] - nm1);
            ts0 += p0 + p1; ts1 += p2 + p3;
            STS64(p_st0 + (uint32_t)(nt * 8) * 4u, f2tf32f(p0), f2tf32f(p1));
            STS64(p_st1 + (uint32_t)(nt * 8) * 4u, f2tf32f(p2), f2tf32f(p3));
        }
        __syncwarp();
        ts0 += __shfl_xor_sync(0xffffffffu, ts0, 1);
        ts0 += __shfl_xor_sync(0xffffffffu, ts0, 2);
        ts1 += __shfl_xor_sync(0xffffffffu, ts1, 1);
        ts1 += __shfl_xor_sync(0xffffffffu, ts1, 2);
        l0 = l0 * a0 + ts0; l1 = l1 * a1 + ts1;
        m0 = nm0; m1 = nm1;
#pragma unroll
        for (int nt = 0; nt < 8; nt++) {
            o[nt][0] *= a0; o[nt][1] *= a0; o[nt][2] *= a1; o[nt][3] *= a1;
        }

        // O += P @ V : A-frags from P strip, B-frags from Vt, all ldmatrix
#pragma unroll
        for (int kt = 0; kt < 16; kt++) {
            uint32_t af[4];
            LDSM_X4(af[0], af[1], af[2], af[3], p_ld + (uint32_t)(kt * 8) * 4u);
            const uint32_t vaddr = vt_u + (uint32_t)(kt * 8) * 4u + ldsv_off;
#pragma unroll
            for (int ntp = 0; ntp < 4; ntp++) {
                uint32_t vb[4];
                LDSM_X4(vb[0], vb[1], vb[2], vb[3],
                        vaddr + (uint32_t)(ntp * 16 * FA_LDVT) * 4u);
                mma_tf32(o[2 * ntp],     af, vb[0], vb[1]);
                mma_tf32(o[2 * ntp + 1], af, vb[2], vb[3]);
            }
        }
        __syncthreads();
    }

    const float il0 = 1.f / l0, il1 = 1.f / l1;
#pragma unroll
    for (int nt = 0; nt < 8; nt++) {
        int c = nt * 8 + 2 * tg;
        float2 v0 = make_float2(o[nt][0] * il0, o[nt][1] * il0);
        float2 v1 = make_float2(o[nt][2] * il1, o[nt][3] * il1);
        *reinterpret_cast<float2*>(Op + (size_t)r0 * DHD + c) = v0;
        *reinterpret_cast<float2*>(Op + (size_t)r1 * DHD + c) = v1;
        float2 r0v = make_float2(f2tf32f(v0.x), f2tf32f(v0.y));
        float2 r1v = make_float2(f2tf32f(v1.x), f2tf32f(v1.y));
        *reinterpret_cast<float2*>(Opr + (size_t)r0 * DHD + c) = r0v;
        *reinterpret_cast<float2*>(Opr + (size_t)r1 * DHD + c) = r1v;
    }
}

// ---------------- GEGLU (output tf32-rounded; it only feeds FF2 GEMM) ------
__global__ __launch_bounds__(256)
void geglu_kernel(const float* __restrict__ h, float* __restrict__ act) {
    const int idx = blockIdx.x * 256 + threadIdx.x;
    const int m = idx >> 10;
    const int c = (idx & 1023) << 2;
    const float4 a  = *reinterpret_cast<const float4*>(h + (size_t)m * (2 * FF) + c);
    const float4 gt = *reinterpret_cast<const float4*>(h + (size_t)m * (2 * FF) + FF + c);
    float4 o;
    o.x = f2tf32f(a.x * gelu_exact(gt.x));
    o.y = f2tf32f(a.y * gelu_exact(gt.y));
    o.z = f2tf32f(a.z * gelu_exact(gt.z));
    o.w = f2tf32f(a.w * gelu_exact(gt.w));
    *reinterpret_cast<float4*>(act + (size_t)m * FF + c) = o;
}

// ---------------- launch ---------------------------------------------------
extern "C" void kernel_launch(void* const* d_in, const int* in_sizes, int n_in,
                              void* d_out, int out_size) {
    (void)in_sizes; (void)n_in; (void)out_size;
    const float* x     = (const float*)d_in[0];
    const float* Wq    = (const float*)d_in[1];
    const float* Wk    = (const float*)d_in[2];
    const float* Wv    = (const float*)d_in[3];
    const float* Wo    = (const float*)d_in[4];
    const float* bo    = (const float*)d_in[5];
    const float* ln1_g = (const float*)d_in[6];
    const float* ln1_b = (const float*)d_in[7];
    const float* ln3_g = (const float*)d_in[8];
    const float* ln3_b = (const float*)d_in[9];
    const float* Wff1  = (const float*)d_in[10];
    const float* bff1  = (const float*)d_in[11];
    const float* Wff2  = (const float*)d_in[12];
    const float* bff2  = (const float*)d_in[13];

    float* out = (float*)d_out;
    const size_t SZ = (size_t)MROWS * DMOD;
    float* out_x  = out;            // x
    float* out_q  = out + SZ;       // q_bh
    float* out_k  = out + 2 * SZ;   // k_bh
    float* out_v  = out + 3 * SZ;   // v_bh
    float* out_io = out + 4 * SZ;   // inter_out
    float* out_xf = out + 5 * SZ;   // x_features

    float *x2, *xf2, *xfr, *ior, *kr, *vtr, *hbuf, *actbuf, *wbuf;
    cudaGetSymbolAddress((void**)&x2,     g_x2);
    cudaGetSymbolAddress((void**)&xf2,    g_xf2);
    cudaGetSymbolAddress((void**)&xfr,    g_xfr);
    cudaGetSymbolAddress((void**)&ior,    g_ior);
    cudaGetSymbolAddress((void**)&kr,     g_kr);
    cudaGetSymbolAddress((void**)&vtr,    g_vtr);
    cudaGetSymbolAddress((void**)&hbuf,   g_h);
    cudaGetSymbolAddress((void**)&actbuf, g_act);
    cudaGetSymbolAddress((void**)&wbuf,   g_w);

    cudaFuncSetAttribute(gemm_qkv_kernel,
                         cudaFuncAttributeMaxDynamicSharedMemorySize, SMEM_GEMM);
    cudaFuncSetAttribute(gemm3_kernel<0>,
                         cudaFuncAttributeMaxDynamicSharedMemorySize, SMEM_GEMM);
    cudaFuncSetAttribute(gemm3_kernel<1>,
                         cudaFuncAttributeMaxDynamicSharedMemorySize, SMEM_GEMM);
    cudaFuncSetAttribute(flash_attn_kernel,
                         cudaFuncAttributeMaxDynamicSharedMemorySize, SMEM_FA);

    const dim3 blk(GTH);

    // 0) transpose + round all weights to tf32 (Wt = [N][K], n-major)
    cvt_t_kernel<<<dim3(32, 32),  256>>>(Wq,   wbuf + WOFF_Q,   DMOD, DMOD);
    cvt_t_kernel<<<dim3(32, 32),  256>>>(Wk,   wbuf + WOFF_K,   DMOD, DMOD);
    cvt_t_kernel<<<dim3(32, 32),  256>>>(Wv,   wbuf + WOFF_V,   DMOD, DMOD);
    cvt_t_kernel<<<dim3(32, 32),  256>>>(Wo,   wbuf + WOFF_O,   DMOD, DMOD);
    cvt_t_kernel<<<dim3(256, 32), 256>>>(Wff1, wbuf + WOFF_FF1, DMOD, 2 * FF);
    cvt_t_kernel<<<dim3(32, 128), 256>>>(Wff2, wbuf + WOFF_FF2, FF,   DMOD);

    // 1) LN1 -> x_features (exact) + rounded copy for GEMM A
    ln_kernel<<<MROWS, 256>>>(x, ln1_g, ln1_b, out_xf, xfr);

    // 2) fused QKV GEMM; exact q/k/v to d_out, rounded k (token-major) + v (transposed)
    gemm_qkv_kernel<<<dim3(3 * DMOD / BN, MROWS / BM), blk, SMEM_GEMM>>>(
        xfr, wbuf + WOFF_Q, out_q, out_k, out_v, kr, vtr);

    // 3) attention -> inter_out (exact) + rounded copy
    flash_attn_kernel<<<dim3(TOK / 128, NBAT * NH), 256, SMEM_FA>>>(
        out_q, kr, vtr, out_io, ior);

    // 4) Wo GEMM (gather-A from rounded inter_out) + bo + residual x -> x2 (exact)
    gemm3_kernel<1><<<dim3(DMOD / BN, MROWS / BM), blk, SMEM_GEMM>>>(
        ior, wbuf + WOFF_O, x2, MROWS, DMOD, DMOD, bo, x);

    // 5) LN3 -> xf2 (rounded only; internal)
    ln_kernel<<<MROWS, 256>>>(x2, ln3_g, ln3_b, nullptr, xf2);

    // 6) FF1 GEMM (+bff1) -> h (exact; geglu needs exact gate)
    gemm3_kernel<0><<<dim3(2 * FF / BN, MROWS / BM), blk, SMEM_GEMM>>>(
        xf2, wbuf + WOFF_FF1, hbuf, MROWS, 2 * FF, DMOD, bff1, nullptr);

    // 7) GEGLU -> act (rounded)
    geglu_kernel<<<(MROWS * (FF / 4)) / 256, 256>>>(hbuf, actbuf);

    // 8) FF2 GEMM (+bff2) + residual x2 -> final x
    gemm3_kernel<0><<<dim3(DMOD / BN, MROWS / BM), blk, SMEM_GEMM>>>(
        actbuf, wbuf + WOFF_FF2, out_x, MROWS, DMOD, FF, bff2, x2);
}

// round 14
// speedup vs baseline: 1.1673x; 1.0332x over previous
#include <cuda_runtime.h>
#include <cstdint>
#include <cstdio>

#define TOK   2048
#define NBAT  2
#define NH    16
#define DHD   64
#define DMOD  1024
#define MROWS 4096   /* B*N */
#define FF    4096

// ---------------- scratch (static device globals; no runtime allocation) ---
__device__ float g_x2 [MROWS * DMOD];            // 16 MB : x after attn residual (exact)
__device__ float g_xf2[MROWS * DMOD];            // 16 MB : LN3 output (tf32-rounded)
__device__ float g_xfr[MROWS * DMOD];            // 16 MB : LN1 output (tf32-rounded)
__device__ float g_ior[MROWS * DMOD];            // 16 MB : inter_out (tf32-rounded)
__device__ float g_kr [MROWS * DMOD];            // 16 MB : k_bh tf32-rounded
__device__ float g_vtr[MROWS * DMOD];            // 16 MB : v_bh tf32-rounded TRANSPOSED [bh][dh][tok]
__device__ float g_h  [(size_t)MROWS * 2 * FF];  // 128 MB: FF1 output (exact)
__device__ float g_act[(size_t)MROWS * FF];      // 64 MB : geglu output (tf32-rounded)
__device__ float g_w  [16 * 1024 * 1024];        // 64 MB : all weights, tf32-rounded + TRANSPOSED (n-major)
// offsets (floats) within g_w (each block is Wt = [N][K] row-major):
#define WOFF_Q    0
#define WOFF_K    (1024 * 1024)
#define WOFF_V    (2 * 1024 * 1024)
#define WOFF_O    (3 * 1024 * 1024)
#define WOFF_FF1  (4 * 1024 * 1024)
#define WOFF_FF2  (12 * 1024 * 1024)

// ---------------- helpers --------------------------------------------------
__device__ __forceinline__ uint32_t f2tf32(float x) {
    uint32_t t;
    asm("cvt.rna.tf32.f32 %0, %1;" : "=r"(t) : "f"(x));
    return t;
}
__device__ __forceinline__ float f2tf32f(float x) { return __uint_as_float(f2tf32(x)); }

__device__ __forceinline__ void mma_tf32(float c[4], const uint32_t a[4],
                                         uint32_t b0, uint32_t b1) {
    asm volatile(
        "mma.sync.aligned.m16n8k8.row.col.f32.tf32.tf32.f32 "
        "{%0,%1,%2,%3}, {%4,%5,%6,%7}, {%8,%9}, {%0,%1,%2,%3};\n"
        : "+f"(c[0]), "+f"(c[1]), "+f"(c[2]), "+f"(c[3])
        : "r"(a[0]), "r"(a[1]), "r"(a[2]), "r"(a[3]), "r"(b0), "r"(b1));
}

#define LDSM_X4(r0, r1, r2, r3, addr)                                         \
    asm volatile("ldmatrix.sync.aligned.m8n8.x4.shared.b16 {%0,%1,%2,%3}, [%4];" \
                 : "=r"(r0), "=r"(r1), "=r"(r2), "=r"(r3) : "r"(addr))

#define STS64(addr, v0, v1)                                                   \
    asm volatile("st.shared.v2.f32 [%0], {%1, %2};" :: "r"(addr), "f"(v0), "f"(v1))

__device__ __forceinline__ void cp_async16(uint32_t dst, const void* src) {
    asm volatile("cp.async.cg.shared.global [%0], [%1], 16;\n" :: "r"(dst), "l"(src));
}
__device__ __forceinline__ void cp_commit() {
    asm volatile("cp.async.commit_group;\n" ::: "memory");
}
__device__ __forceinline__ void cp_wait1() {
    asm volatile("cp.async.wait_group 1;\n" ::: "memory");
}
__device__ __forceinline__ void cp_wait0() {
    asm volatile("cp.async.wait_group 0;\n" ::: "memory");
}

__device__ __forceinline__ float gelu_exact(float x) {
    return 0.5f * x * (1.0f + erff(x * 0.70710678118654752f));
}

// ------------ weight transpose+round: src[K][N] -> dst[N][K], tf32 ----------
__global__ __launch_bounds__(256)
void cvt_t_kernel(const float* __restrict__ src, float* __restrict__ dst,
                  int K, int N) {
    __shared__ float t[32][33];
    const int k0 = blockIdx.y * 32, n0 = blockIdx.x * 32;
    const int tx = threadIdx.x & 31, ty = threadIdx.x >> 5;   // ty 0..7
#pragma unroll
    for (int i = 0; i < 32; i += 8)
        t[ty + i][tx] = f2tf32f(src[(size_t)(k0 + ty + i) * N + n0 + tx]);
    __syncthreads();
#pragma unroll
    for (int i = 0; i < 32; i += 8)
        dst[(size_t)(n0 + ty + i) * K + k0 + tx] = t[tx][ty + i];
}

// ---------------- LayerNorm (one block per row of 1024) --------------------
__global__ __launch_bounds__(256)
void ln_kernel(const float* __restrict__ x, const float* __restrict__ gw,
               const float* __restrict__ bw, float* __restrict__ y,
               float* __restrict__ yr) {
    __shared__ float red[16];
    const int row = blockIdx.x;
    const int tid = threadIdx.x;
    const float4 v = reinterpret_cast<const float4*>(x + (size_t)row * DMOD)[tid];
    float s  = v.x + v.y + v.z + v.w;
    float ss = v.x * v.x + v.y * v.y + v.z * v.z + v.w * v.w;
#pragma unroll
    for (int o = 16; o > 0; o >>= 1) {
        s  += __shfl_xor_sync(0xffffffffu, s,  o);
        ss += __shfl_xor_sync(0xffffffffu, ss, o);
    }
    if ((tid & 31) == 0) { red[tid >> 5] = s; red[8 + (tid >> 5)] = ss; }
    __syncthreads();
    float ts = 0.f, tss = 0.f;
#pragma unroll
    for (int w = 0; w < 8; w++) { ts += red[w]; tss += red[8 + w]; }
    const float mu  = ts * (1.0f / DMOD);
    const float var = tss * (1.0f / DMOD) - mu * mu;
    const float rs  = rsqrtf(var + 1e-5f);
    const float4 gv = reinterpret_cast<const float4*>(gw)[tid];
    const float4 bv = reinterpret_cast<const float4*>(bw)[tid];
    float4 o;
    o.x = (v.x - mu) * rs * gv.x + bv.x;
    o.y = (v.y - mu) * rs * gv.y + bv.y;
    o.z = (v.z - mu) * rs * gv.z + bv.z;
    o.w = (v.w - mu) * rs * gv.w + bv.w;
    if (y)  reinterpret_cast<float4*>(y  + (size_t)row * DMOD)[tid] = o;
    if (yr) {
        float4 r = make_float4(f2tf32f(o.x), f2tf32f(o.y), f2tf32f(o.z), f2tf32f(o.w));
        reinterpret_cast<float4*>(yr + (size_t)row * DMOD)[tid] = r;
    }
}

// -- TF32 GEMM v6: CTA 128x256, 512 thr, warp 64x32, cp.async 3-stage,
//    LDSM for BOTH A and B fragments (B stored n-major, weights pre-transposed)
constexpr int BM = 128, BN = 256, BK = 32, STAGES = 3;
constexpr int GTH = 512;                                       // GEMM threads
constexpr int LDA_S = 36, LDB_T = 36;
constexpr int STAGE_F = BM * LDA_S + BN * LDB_T;               // 13824 floats
constexpr int SMEM_GEMM = STAGES * STAGE_F * 4;                // 165888 bytes

// AMODE 0: A row-major [M][K].  AMODE 1: A gathered from inter_out (B,H,TOK,DHD).
template <int AMODE>
struct ALoader {
    static __device__ __forceinline__ const float* ptr(const float* A, int gm, int gk, int K) {
        if (AMODE == 0) return A + (size_t)gm * K + gk;
        int bb = gm >> 11, nn = gm & (TOK - 1);
        int hh = gk >> 6,  dd = gk & (DHD - 1);
        return A + (((size_t)(bb * NH + hh) * TOK + nn) * DHD + dd);
    }
};

// Bt: [N][K] row-major (ld = K). Tile: rows nb..nb+255, cols kb..kb+31.
template <int AMODE>
__device__ __forceinline__ void gemm_load_stage(
    const float* __restrict__ A, const float* __restrict__ Bt,
    int m0, int nb, int kb, int K, uint32_t smem_stage) {
#pragma unroll
    for (int i = 0; i < 2; i++) {                // A: 128x32 = 1024 chunks / 512 thr
        int c = i * GTH + threadIdx.x;
        int row = c >> 3, kc = (c & 7) << 2;
        const float* src = ALoader<AMODE>::ptr(A, m0 + row, kb + kc, K);
        cp_async16(smem_stage + (uint32_t)(row * LDA_S + kc) * 4u, src);
    }
    const uint32_t bs = smem_stage + (uint32_t)(BM * LDA_S) * 4u;
#pragma unroll
    for (int i = 0; i < 4; i++) {                // Bt: 256x32 = 2048 chunks / 512 thr
        int c = i * GTH + threadIdx.x;
        int row = c >> 3, kc = (c & 7) << 2;
        cp_async16(bs + (uint32_t)(row * LDB_T + kc) * 4u,
                   Bt + (size_t)(nb + row) * K + kb + kc);
    }
}

// A and B fragments both via ldmatrix.x4.
__device__ __forceinline__ void gemm_compute_stage(
    uint32_t st_u, int wm, int wn, float acc[4][4][4]) {
    const int lane = threadIdx.x & 31;
    const uint32_t a_base = st_u +
        (uint32_t)((wm + (lane & 15)) * LDA_S + ((lane >> 4) << 2)) * 4u;
    const uint32_t b_base = st_u + (uint32_t)(BM * LDA_S) * 4u +
        (uint32_t)((wn + (lane & 7) + ((lane >> 4) & 1) * 8) * LDB_T +
                   ((lane >> 3) & 1) * 4) * 4u;
#pragma unroll
    for (int kk = 0; kk < BK; kk += 8) {
        uint32_t af[4][4];
#pragma unroll
        for (int mt = 0; mt < 4; mt++) {
            LDSM_X4(af[mt][0], af[mt][1], af[mt][2], af[mt][3],
                    a_base + (uint32_t)(mt * 16 * LDA_S + kk) * 4u);
        }
        uint32_t bf0[4], bf1[4];
        LDSM_X4(bf0[0], bf0[1], bf0[2], bf0[3], b_base + (uint32_t)kk * 4u);
        LDSM_X4(bf1[0], bf1[1], bf1[2], bf1[3],
                b_base + (uint32_t)(16 * LDB_T + kk) * 4u);
#pragma unroll
        for (int mt = 0; mt < 4; mt++) {
            mma_tf32(acc[mt][0], af[mt], bf0[0], bf0[1]);
            mma_tf32(acc[mt][1], af[mt], bf0[2], bf0[3]);
            mma_tf32(acc[mt][2], af[mt], bf1[0], bf1[1]);
            mma_tf32(acc[mt][3], af[mt], bf1[2], bf1[3]);
        }
    }
}

// ---- standard output: C row-major (ldc = N), optional bias + residual -----
template <int AMODE>
__global__ __launch_bounds__(GTH, 1)
void gemm3_kernel(const float* __restrict__ A, const float* __restrict__ Bt,
                  float* __restrict__ C, int M, int N, int K,
                  const float* __restrict__ bias, const float* __restrict__ res) {
    extern __shared__ float sm[];
    const uint32_t smem_u = (uint32_t)__cvta_generic_to_shared(sm);
    const int tid = threadIdx.x, wid = tid >> 5, lane = tid & 31;
    const int g = lane >> 2, tg = lane & 3;
    const int m0 = blockIdx.y * BM;
    const int n0 = blockIdx.x * BN;
    const int wm = (wid & 1) * 64;     // 2 warp-rows of 64
    const int wn = (wid >> 1) * 32;    // 8 warp-cols of 32

    float acc[4][4][4];
#pragma unroll
    for (int i = 0; i < 4; i++)
#pragma unroll
        for (int j = 0; j < 4; j++)
#pragma unroll
            for (int k = 0; k < 4; k++) acc[i][j][k] = 0.f;

    const int T = K / BK;
    gemm_load_stage<AMODE>(A, Bt, m0, n0, 0, K, smem_u);
    cp_commit();
    gemm_load_stage<AMODE>(A, Bt, m0, n0, BK, K, smem_u + STAGE_F * 4);
    cp_commit();

    int s = 0;
    for (int kt = 0; kt < T; kt++) {
        cp_wait1();
        __syncthreads();
        if (kt + 2 < T) {
            int s2 = (s + 2 >= STAGES) ? s + 2 - STAGES : s + 2;
            gemm_load_stage<AMODE>(A, Bt, m0, n0, (kt + 2) * BK, K,
                                   smem_u + (uint32_t)s2 * STAGE_F * 4);
        }
        cp_commit();
        gemm_compute_stage(smem_u + (uint32_t)s * STAGE_F * 4, wm, wn, acc);
        s = (s + 1 == STAGES) ? 0 : s + 1;
    }

#pragma unroll
    for (int mt = 0; mt < 4; mt++) {
        const int r0 = m0 + wm + mt * 16 + g;
        const int r1 = r0 + 8;
#pragma unroll
        for (int nt = 0; nt < 4; nt++) {
            const int c = n0 + wn + nt * 8 + 2 * tg;
            float2 v0 = make_float2(acc[mt][nt][0], acc[mt][nt][1]);
            float2 v1 = make_float2(acc[mt][nt][2], acc[mt][nt][3]);
            if (bias) {
                float2 bb = *reinterpret_cast<const float2*>(bias + c);
                v0.x += bb.x; v0.y += bb.y; v1.x += bb.x; v1.y += bb.y;
            }
            if (res) {
                float2 q0r = *reinterpret_cast<const float2*>(res + (size_t)r0 * N + c);
                float2 q1r = *reinterpret_cast<const float2*>(res + (size_t)r1 * N + c);
                v0.x += q0r.x; v0.y += q0r.y; v1.x += q1r.x; v1.y += q1r.y;
            }
            *reinterpret_cast<float2*>(C + (size_t)r0 * N + c) = v0;
            *reinterpret_cast<float2*>(C + (size_t)r1 * N + c) = v1;
        }
    }
}

// ---- fused QKV: one GEMM over N=3072, scatter into q_bh/k_bh/v_bh ---------
// Also writes rounded K copy (token-major) and rounded V copy TRANSPOSED.
__global__ __launch_bounds__(GTH, 1)
void gemm_qkv_kernel(const float* __restrict__ A, const float* __restrict__ Wt,
                     float* __restrict__ Cq, float* __restrict__ Ck,
                     float* __restrict__ Cv, float* __restrict__ Ckr,
                     float* __restrict__ Cvt) {
    extern __shared__ float sm[];
    const uint32_t smem_u = (uint32_t)__cvta_generic_to_shared(sm);
    const int tid = threadIdx.x, wid = tid >> 5, lane = tid & 31;
    const int g = lane >> 2, tg = lane & 3;
    const int m0 = blockIdx.y * BM;
    const int arr = blockIdx.x >> 2;                 // 0..2 : which weight/output
    const int nb  = (blockIdx.x & 3) * BN;           // column base within the array
    const float* Bt = Wt + (size_t)arr * DMOD * DMOD; // Wq^T/Wk^T/Wv^T contiguous
    float* C  = (arr == 0) ? Cq : (arr == 1) ? Ck : Cv;
    const int wm = (wid & 1) * 64;
    const int wn = (wid >> 1) * 32;
    const int K = DMOD;

    float acc[4][4][4];
#pragma unroll
    for (int i = 0; i < 4; i++)
#pragma unroll
        for (int j = 0; j < 4; j++)
#pragma unroll
            for (int k = 0; k < 4; k++) acc[i][j][k] = 0.f;

    const int T = K / BK;
    gemm_load_stage<0>(A, Bt, m0, nb, 0, K, smem_u);
    cp_commit();
    gemm_load_stage<0>(A, Bt, m0, nb, BK, K, smem_u + STAGE_F * 4);
    cp_commit();

    int s = 0;
    for (int kt = 0; kt < T; kt++) {
        cp_wait1();
        __syncthreads();
        if (kt + 2 < T) {
            int s2 = (s + 2 >= STAGES) ? s + 2 - STAGES : s + 2;
            gemm_load_stage<0>(A, Bt, m0, nb, (kt + 2) * BK, K,
                               smem_u + (uint32_t)s2 * STAGE_F * 4);
        }
        cp_commit();
        gemm_compute_stage(smem_u + (uint32_t)s * STAGE_F * 4, wm, wn, acc);
        s = (s + 1 == STAGES) ? 0 : s + 1;
    }

    // scatter to (B*H, TOK, DHD) (+ rounded copies for flash)
#pragma unroll
    for (int mt = 0; mt < 4; mt++) {
        const int r0 = m0 + wm + mt * 16 + g;
        const int r1 = r0 + 8;
        const int b0_ = r0 >> 11, n0_ = r0 & (TOK - 1);
        const int b1_ = r1 >> 11, n1_ = r1 & (TOK - 1);
#pragma unroll
        for (int nt = 0; nt < 4; nt++) {
            const int cl = nb + wn + nt * 8 + 2 * tg;
            const int hh = cl >> 6, dd = cl & (DHD - 1);
            const size_t o0 = ((size_t)(b0_ * NH + hh) * TOK + n0_) * DHD + dd;
            const size_t o1 = ((size_t)(b1_ * NH + hh) * TOK + n1_) * DHD + dd;
            float2 v0 = make_float2(acc[mt][nt][0], acc[mt][nt][1]);
            float2 v1 = make_float2(acc[mt][nt][2], acc[mt][nt][3]);
            *reinterpret_cast<float2*>(C + o0) = v0;
            *reinterpret_cast<float2*>(C + o1) = v1;
            if (arr == 1) {
                float2 r0v = make_float2(f2tf32f(v0.x), f2tf32f(v0.y));
                float2 r1v = make_float2(f2tf32f(v1.x), f2tf32f(v1.y));
                *reinterpret_cast<float2*>(Ckr + o0) = r0v;
                *reinterpret_cast<float2*>(Ckr + o1) = r1v;
            } else if (arr == 2) {
                const size_t t0 = ((size_t)(b0_ * NH + hh) * DHD + dd) * TOK + n0_;
                const size_t t1 = ((size_t)(b1_ * NH + hh) * DHD + dd) * TOK + n1_;
                Cvt[t0]       = f2tf32f(v0.x);
                Cvt[t0 + TOK] = f2tf32f(v0.y);
                Cvt[t1]       = f2tf32f(v1.x);
                Cvt[t1 + TOK] = f2tf32f(v1.y);
            }
        }
    }
}

// ---------------- flash attention v4: 64-token KV tiles, 2 CTAs/SM ----------
// K from rounded token-major copy; V from rounded TRANSPOSED copy; P via smem.
constexpr int FA_TOKT   = 64;                       // tokens per KV tile
constexpr int FA_LDK    = DHD + 4;                  // 68 floats/row (K tile: rows=tok)
constexpr int FA_LDVT   = FA_TOKT + 4;              // 68 floats/row (Vt tile: rows=dh)
constexpr int FA_KTILE  = FA_TOKT * FA_LDK;         // 4352 floats
constexpr int FA_VTILE  = DHD * FA_LDVT;            // 4352 floats
constexpr int FA_STAGE_F = FA_KTILE + FA_VTILE;     // 8704 floats
constexpr int FA_P_OFF  = 2 * FA_STAGE_F;           // P strip after 2 KV stages
constexpr int FA_LDP    = FA_TOKT + 4;              // 68 floats/row
constexpr int SMEM_FA   = (FA_P_OFF + 128 * FA_LDP) * 4;  // 104448 bytes

__global__ __launch_bounds__(256, 2)
void flash_attn_kernel(const float* __restrict__ Q, const float* __restrict__ Kr,
                       const float* __restrict__ Vt, float* __restrict__ O,
                       float* __restrict__ Or) {
    extern __shared__ float sm[];
    const uint32_t smem_u = (uint32_t)__cvta_generic_to_shared(sm);

    const int tid = threadIdx.x, wid = tid >> 5, lane = tid & 31;
    const int g = lane >> 2, tg = lane & 3;
    const int bh = blockIdx.y;
    const int q0 = blockIdx.x * 128;
    const float* Qp  = Q  + (size_t)bh * TOK * DHD;
    const float* Kp  = Kr + (size_t)bh * TOK * DHD;
    const float* Vtp = Vt + (size_t)bh * DHD * TOK;   // [dh][token]
    float* Op  = O  + (size_t)bh * TOK * DHD;
    float* Opr = Or + (size_t)bh * TOK * DHD;
    const int wm = wid * 16;
    const int r0 = q0 + wm + g, r1 = r0 + 8;

    // Q fragments (scaled by 1/8 exact, tf32-rounded)
    uint32_t qf[8][4];
#pragma unroll
    for (int ks = 0; ks < 8; ks++) {
        int c = ks * 8 + tg;
        qf[ks][0] = f2tf32(Qp[(size_t)r0 * DHD + c] * 0.125f);
        qf[ks][1] = f2tf32(Qp[(size_t)r1 * DHD + c] * 0.125f);
        qf[ks][2] = f2tf32(Qp[(size_t)r0 * DHD + c + 4] * 0.125f);
        qf[ks][3] = f2tf32(Qp[(size_t)r1 * DHD + c + 4] * 0.125f);
    }

    // ldmatrix per-lane offsets (bytes)
    const uint32_t ldsk_off =
        (uint32_t)((((lane & 7) + ((lane >> 4) & 1) * 8) * FA_LDK +
                    ((lane >> 3) & 1) * 4)) * 4u;
    const uint32_t ldsv_off =
        (uint32_t)((((lane & 7) + ((lane >> 4) & 1) * 8) * FA_LDVT +
                    ((lane >> 3) & 1) * 4)) * 4u;
    // P strip addresses
    const uint32_t p_u = smem_u + (uint32_t)FA_P_OFF * 4u;
    const uint32_t p_st0 = p_u + (uint32_t)((wm + g) * FA_LDP + 2 * tg) * 4u;
    const uint32_t p_st1 = p_u + (uint32_t)((wm + 8 + g) * FA_LDP + 2 * tg) * 4u;
    const uint32_t p_ld  = p_u +
        (uint32_t)((wm + (lane & 15)) * FA_LDP + ((lane >> 4) << 2)) * 4u;

    float m0 = -1e30f, m1 = -1e30f, l0 = 0.f, l1 = 0.f;
    float o[8][4];
#pragma unroll
    for (int i = 0; i < 8; i++)
#pragma unroll
        for (int j = 0; j < 4; j++) o[i][j] = 0.f;

    auto loadKV = [&](int j, int st) {
        const uint32_t kd = smem_u + (uint32_t)st * FA_STAGE_F * 4u;
        const uint32_t vd = kd + (uint32_t)FA_KTILE * 4u;
#pragma unroll
        for (int i = 0; i < 4; i++) {          // K: 64 tok x 64 dh
            int s = tid + i * 256;
            int r = s >> 4, c = (s & 15) << 2;
            cp_async16(kd + (uint32_t)(r * FA_LDK + c) * 4u,
                       Kp + (size_t)(j + r) * DHD + c);
        }
#pragma unroll
        for (int i = 0; i < 4; i++) {          // Vt: 64 dh x 64 tok
            int s = tid + i * 256;
            int r = s >> 4, c = (s & 15) << 2;
            cp_async16(vd + (uint32_t)(r * FA_LDVT + c) * 4u,
                       Vtp + (size_t)r * TOK + j + c);
        }
    };

    loadKV(0, 0);
    cp_commit();

    const int NT = TOK / FA_TOKT;
    for (int jt = 0; jt < NT; jt++) {
        if (jt + 1 < NT) {
            loadKV((jt + 1) * FA_TOKT, (jt + 1) & 1);
            cp_commit();
            cp_wait1();
        } else {
            cp_wait0();
        }
        __syncthreads();

        const int st = jt & 1;
        const uint32_t ks_u = smem_u + (uint32_t)st * FA_STAGE_F * 4u;
        const uint32_t vt_u = ks_u + (uint32_t)FA_KTILE * 4u;

        // S = (Q/8) K^T : B-frags via ldmatrix (8 n-tiles of 8 tokens)
        float sc[8][4];
#pragma unroll
        for (int nt = 0; nt < 8; nt++)
#pragma unroll
            for (int k4 = 0; k4 < 4; k4++) sc[nt][k4] = 0.f;
#pragma unroll
        for (int ks = 0; ks < 8; ks++) {
            const uint32_t kaddr = ks_u + (uint32_t)(ks * 8) * 4u + ldsk_off;
#pragma unroll
            for (int nt4 = 0; nt4 < 2; nt4++) {
                uint32_t bf[4][2];
                LDSM_X4(bf[0][0], bf[0][1], bf[1][0], bf[1][1],
                        kaddr + (uint32_t)(nt4 * 32 * FA_LDK) * 4u);
                LDSM_X4(bf[2][0], bf[2][1], bf[3][0], bf[3][1],
                        kaddr + (uint32_t)((nt4 * 32 + 16) * FA_LDK) * 4u);
#pragma unroll
                for (int c4 = 0; c4 < 4; c4++)
                    mma_tf32(sc[nt4 * 4 + c4], qf[ks], bf[c4][0], bf[c4][1]);
            }
        }

        // online softmax; rounded P goes straight to smem strip
        float tm0 = -1e30f, tm1 = -1e30f;
#pragma unroll
        for (int nt = 0; nt < 8; nt++) {
            tm0 = fmaxf(tm0, fmaxf(sc[nt][0], sc[nt][1]));
            tm1 = fmaxf(tm1, fmaxf(sc[nt][2], sc[nt][3]));
        }
        tm0 = fmaxf(tm0, __shfl_xor_sync(0xffffffffu, tm0, 1));
        tm0 = fmaxf(tm0, __shfl_xor_sync(0xffffffffu, tm0, 2));
        tm1 = fmaxf(tm1, __shfl_xor_sync(0xffffffffu, tm1, 1));
        tm1 = fmaxf(tm1, __shfl_xor_sync(0xffffffffu, tm1, 2));
        const float nm0 = fmaxf(m0, tm0), nm1 = fmaxf(m1, tm1);
        const float a0 = __expf(m0 - nm0), a1 = __expf(m1 - nm1);
        float ts0 = 0.f, ts1 = 0.f;
#pragma unroll
        for (int nt = 0; nt < 8; nt++) {
            float p0 = __expf(sc[nt][0] - nm0);
            float p1 = __expf(sc[nt][1] - nm0);
            float p2 = __expf(sc[nt][2] - nm1);
            float p3 = __expf(sc[nt][3] - nm1);
            ts0 += p0 + p1; ts1 += p2 + p3;
            STS64(p_st0 + (uint32_t)(nt * 8) * 4u, f2tf32f(p0), f2tf32f(p1));
            STS64(p_st1 + (uint32_t)(nt * 8) * 4u, f2tf32f(p2), f2tf32f(p3));
        }
        __syncwarp();
        ts0 += __shfl_xor_sync(0xffffffffu, ts0, 1);
        ts0 += __shfl_xor_sync(0xffffffffu, ts0, 2);
        ts1 += __shfl_xor_sync(0xffffffffu, ts1, 1);
        ts1 += __shfl_xor_sync(0xffffffffu, ts1, 2);
        l0 = l0 * a0 + ts0; l1 = l1 * a1 + ts1;
        m0 = nm0; m1 = nm1;
#pragma unroll
        for (int nt = 0; nt < 8; nt++) {
            o[nt][0] *= a0; o[nt][1] *= a0; o[nt][2] *= a1; o[nt][3] *= a1;
        }

        // O += P @ V : A-frags from P strip, B-frags from Vt, all ldmatrix
#pragma unroll
        for (int kt = 0; kt < 8; kt++) {
            uint32_t af[4];
            LDSM_X4(af[0], af[1], af[2], af[3], p_ld + (uint32_t)(kt * 8) * 4u);
            const uint32_t vaddr = vt_u + (uint32_t)(kt * 8) * 4u + ldsv_off;
#pragma unroll
            for (int ntp = 0; ntp < 4; ntp++) {
                uint32_t vb[4];
                LDSM_X4(vb[0], vb[1], vb[2], vb[3],
                        vaddr + (uint32_t)(ntp * 16 * FA_LDVT) * 4u);
                mma_tf32(o[2 * ntp],     af, vb[0], vb[1]);
                mma_tf32(o[2 * ntp + 1], af, vb[2], vb[3]);
            }
        }
        __syncthreads();
    }

    const float il0 = 1.f / l0, il1 = 1.f / l1;
#pragma unroll
    for (int nt = 0; nt < 8; nt++) {
        int c = nt * 8 + 2 * tg;
        float2 v0 = make_float2(o[nt][0] * il0, o[nt][1] * il0);
        float2 v1 = make_float2(o[nt][2] * il1, o[nt][3] * il1);
        *reinterpret_cast<float2*>(Op + (size_t)r0 * DHD + c) = v0;
        *reinterpret_cast<float2*>(Op + (size_t)r1 * DHD + c) = v1;
        float2 r0v = make_float2(f2tf32f(v0.x), f2tf32f(v0.y));
        float2 r1v = make_float2(f2tf32f(v1.x), f2tf32f(v1.y));
        *reinterpret_cast<float2*>(Opr + (size_t)r0 * DHD + c) = r0v;
        *reinterpret_cast<float2*>(Opr + (size_t)r1 * DHD + c) = r1v;
    }
}

// ---------------- GEGLU (output tf32-rounded; it only feeds FF2 GEMM) ------
__global__ __launch_bounds__(256)
void geglu_kernel(const float* __restrict__ h, float* __restrict__ act) {
    const int idx = blockIdx.x * 256 + threadIdx.x;
    const int m = idx >> 10;
    const int c = (idx & 1023) << 2;
    const float4 a  = *reinterpret_cast<const float4*>(h + (size_t)m * (2 * FF) + c);
    const float4 gt = *reinterpret_cast<const float4*>(h + (size_t)m * (2 * FF) + FF + c);
    float4 o;
    o.x = f2tf32f(a.x * gelu_exact(gt.x));
    o.y = f2tf32f(a.y * gelu_exact(gt.y));
    o.z = f2tf32f(a.z * gelu_exact(gt.z));
    o.w = f2tf32f(a.w * gelu_exact(gt.w));
    *reinterpret_cast<float4*>(act + (size_t)m * FF + c) = o;
}

// ---------------- launch ---------------------------------------------------
extern "C" void kernel_launch(void* const* d_in, const int* in_sizes, int n_in,
                              void* d_out, int out_size) {
    (void)in_sizes; (void)n_in; (void)out_size;
    const float* x     = (const float*)d_in[0];
    const float* Wq    = (const float*)d_in[1];
    const float* Wk    = (const float*)d_in[2];
    const float* Wv    = (const float*)d_in[3];
    const float* Wo    = (const float*)d_in[4];
    const float* bo    = (const float*)d_in[5];
    const float* ln1_g = (const float*)d_in[6];
    const float* ln1_b = (const float*)d_in[7];
    const float* ln3_g = (const float*)d_in[8];
    const float* ln3_b = (const float*)d_in[9];
    const float* Wff1  = (const float*)d_in[10];
    const float* bff1  = (const float*)d_in[11];
    const float* Wff2  = (const float*)d_in[12];
    const float* bff2  = (const float*)d_in[13];

    float* out = (float*)d_out;
    const size_t SZ = (size_t)MROWS * DMOD;
    float* out_x  = out;            // x
    float* out_q  = out + SZ;       // q_bh
    float* out_k  = out + 2 * SZ;   // k_bh
    float* out_v  = out + 3 * SZ;   // v_bh
    float* out_io = out + 4 * SZ;   // inter_out
    float* out_xf = out + 5 * SZ;   // x_features

    float *x2, *xf2, *xfr, *ior, *kr, *vtr, *hbuf, *actbuf, *wbuf;
    cudaGetSymbolAddress((void**)&x2,     g_x2);
    cudaGetSymbolAddress((void**)&xf2,    g_xf2);
    cudaGetSymbolAddress((void**)&xfr,    g_xfr);
    cudaGetSymbolAddress((void**)&ior,    g_ior);
    cudaGetSymbolAddress((void**)&kr,     g_kr);
    cudaGetSymbolAddress((void**)&vtr,    g_vtr);
    cudaGetSymbolAddress((void**)&hbuf,   g_h);
    cudaGetSymbolAddress((void**)&actbuf, g_act);
    cudaGetSymbolAddress((void**)&wbuf,   g_w);

    cudaFuncSetAttribute(gemm_qkv_kernel,
                         cudaFuncAttributeMaxDynamicSharedMemorySize, SMEM_GEMM);
    cudaFuncSetAttribute(gemm3_kernel<0>,
                         cudaFuncAttributeMaxDynamicSharedMemorySize, SMEM_GEMM);
    cudaFuncSetAttribute(gemm3_kernel<1>,
                         cudaFuncAttributeMaxDynamicSharedMemorySize, SMEM_GEMM);
    cudaFuncSetAttribute(flash_attn_kernel,
                         cudaFuncAttributeMaxDynamicSharedMemorySize, SMEM_FA);

    const dim3 blk(GTH);

    // 0) transpose + round all weights to tf32 (Wt = [N][K], n-major)
    cvt_t_kernel<<<dim3(32, 32),  256>>>(Wq,   wbuf + WOFF_Q,   DMOD, DMOD);
    cvt_t_kernel<<<dim3(32, 32),  256>>>(Wk,   wbuf + WOFF_K,   DMOD, DMOD);
    cvt_t_kernel<<<dim3(32, 32),  256>>>(Wv,   wbuf + WOFF_V,   DMOD, DMOD);
    cvt_t_kernel<<<dim3(32, 32),  256>>>(Wo,   wbuf + WOFF_O,   DMOD, DMOD);
    cvt_t_kernel<<<dim3(256, 32), 256>>>(Wff1, wbuf + WOFF_FF1, DMOD, 2 * FF);
    cvt_t_kernel<<<dim3(32, 128), 256>>>(Wff2, wbuf + WOFF_FF2, FF,   DMOD);

    // 1) LN1 -> x_features (exact) + rounded copy for GEMM A
    ln_kernel<<<MROWS, 256>>>(x, ln1_g, ln1_b, out_xf, xfr);

    // 2) fused QKV GEMM; exact q/k/v to d_out, rounded k (token-major) + v (transposed)
    gemm_qkv_kernel<<<dim3(3 * DMOD / BN, MROWS / BM), blk, SMEM_GEMM>>>(
        xfr, wbuf + WOFF_Q, out_q, out_k, out_v, kr, vtr);

    // 3) attention -> inter_out (exact) + rounded copy
    flash_attn_kernel<<<dim3(TOK / 128, NBAT * NH), 256, SMEM_FA>>>(
        out_q, kr, vtr, out_io, ior);

    // 4) Wo GEMM (gather-A from rounded inter_out) + bo + residual x -> x2 (exact)
    gemm3_kernel<1><<<dim3(DMOD / BN, MROWS / BM), blk, SMEM_GEMM>>>(
        ior, wbuf + WOFF_O, x2, MROWS, DMOD, DMOD, bo, x);

    // 5) LN3 -> xf2 (rounded only; internal)
    ln_kernel<<<MROWS, 256>>>(x2, ln3_g, ln3_b, nullptr, xf2);

    // 6) FF1 GEMM (+bff1) -> h (exact; geglu needs exact gate)
    gemm3_kernel<0><<<dim3(2 * FF / BN, MROWS / BM), blk, SMEM_GEMM>>>(
        xf2, wbuf + WOFF_FF1, hbuf, MROWS, 2 * FF, DMOD, bff1, nullptr);

    // 7) GEGLU -> act (rounded)
    geglu_kernel<<<(MROWS * (FF / 4)) / 256, 256>>>(hbuf, actbuf);

    // 8) FF2 GEMM (+bff2) + residual x2 -> final x
    gemm3_kernel<0><<<dim3(DMOD / BN, MROWS / BM), blk, SMEM_GEMM>>>(
        actbuf, wbuf + WOFF_FF2, out_x, MROWS, DMOD, FF, bff2, x2);
}

// round 15
// speedup vs baseline: 1.1916x; 1.0208x over previous
#include <cuda_runtime.h>
#include <cstdint>
#include <cstdio>

#define TOK   2048
#define NBAT  2
#define NH    16
#define DHD   64
#define DMOD  1024
#define MROWS 4096   /* B*N */
#define FF    4096

// ---------------- scratch (static device globals; no runtime allocation) ---
__device__ float g_x2 [MROWS * DMOD];            // 16 MB : x after attn residual (exact)
__device__ float g_xf2[MROWS * DMOD];            // 16 MB : LN3 output (tf32-rounded)
__device__ float g_xfr[MROWS * DMOD];            // 16 MB : LN1 output (tf32-rounded)
__device__ float g_ior[MROWS * DMOD];            // 16 MB : inter_out (tf32-rounded)
__device__ float g_kr [MROWS * DMOD];            // 16 MB : k_bh tf32-rounded
__device__ float g_vtr[MROWS * DMOD];            // 16 MB : v_bh tf32-rounded TRANSPOSED [bh][dh][tok]
__device__ float g_h  [(size_t)MROWS * 2 * FF];  // 128 MB: FF1 output (exact)
__device__ float g_act[(size_t)MROWS * FF];      // 64 MB : geglu output (tf32-rounded)
__device__ float g_w  [16 * 1024 * 1024];        // 64 MB : all weights, tf32-rounded + TRANSPOSED (n-major)
// offsets (floats) within g_w (each block is Wt = [N][K] row-major):
#define WOFF_Q    0
#define WOFF_K    (1024 * 1024)
#define WOFF_V    (2 * 1024 * 1024)
#define WOFF_O    (3 * 1024 * 1024)
#define WOFF_FF1  (4 * 1024 * 1024)
#define WOFF_FF2  (12 * 1024 * 1024)

// ---------------- helpers --------------------------------------------------
__device__ __forceinline__ uint32_t f2tf32(float x) {
    uint32_t t;
    asm("cvt.rna.tf32.f32 %0, %1;" : "=r"(t) : "f"(x));
    return t;
}
__device__ __forceinline__ float f2tf32f(float x) { return __uint_as_float(f2tf32(x)); }

__device__ __forceinline__ void mma_tf32(float c[4], const uint32_t a[4],
                                         uint32_t b0, uint32_t b1) {
    asm volatile(
        "mma.sync.aligned.m16n8k8.row.col.f32.tf32.tf32.f32 "
        "{%0,%1,%2,%3}, {%4,%5,%6,%7}, {%8,%9}, {%0,%1,%2,%3};\n"
        : "+f"(c[0]), "+f"(c[1]), "+f"(c[2]), "+f"(c[3])
        : "r"(a[0]), "r"(a[1]), "r"(a[2]), "r"(a[3]), "r"(b0), "r"(b1));
}

#define LDSM_X4(r0, r1, r2, r3, addr)                                         \
    asm volatile("ldmatrix.sync.aligned.m8n8.x4.shared.b16 {%0,%1,%2,%3}, [%4];" \
                 : "=r"(r0), "=r"(r1), "=r"(r2), "=r"(r3) : "r"(addr))

#define STS64(addr, v0, v1)                                                   \
    asm volatile("st.shared.v2.f32 [%0], {%1, %2};" :: "r"(addr), "f"(v0), "f"(v1))

__device__ __forceinline__ void cp_async16(uint32_t dst, const void* src) {
    asm volatile("cp.async.cg.shared.global [%0], [%1], 16;\n" :: "r"(dst), "l"(src));
}
__device__ __forceinline__ void cp_commit() {
    asm volatile("cp.async.commit_group;\n" ::: "memory");
}
__device__ __forceinline__ void cp_wait1() {
    asm volatile("cp.async.wait_group 1;\n" ::: "memory");
}
__device__ __forceinline__ void cp_wait0() {
    asm volatile("cp.async.wait_group 0;\n" ::: "memory");
}

__device__ __forceinline__ float gelu_exact(float x) {
    return 0.5f * x * (1.0f + erff(x * 0.70710678118654752f));
}

// ------------ weight transpose+round: src[K][N] -> dst[N][K], tf32 ----------
__global__ __launch_bounds__(256)
void cvt_t_kernel(const float* __restrict__ src, float* __restrict__ dst,
                  int K, int N) {
    __shared__ float t[32][33];
    const int k0 = blockIdx.y * 32, n0 = blockIdx.x * 32;
    const int tx = threadIdx.x & 31, ty = threadIdx.x >> 5;   // ty 0..7
#pragma unroll
    for (int i = 0; i < 32; i += 8)
        t[ty + i][tx] = f2tf32f(src[(size_t)(k0 + ty + i) * N + n0 + tx]);
    __syncthreads();
#pragma unroll
    for (int i = 0; i < 32; i += 8)
        dst[(size_t)(n0 + ty + i) * K + k0 + tx] = t[tx][ty + i];
}

// ---------------- LayerNorm (one block per row of 1024) --------------------
__global__ __launch_bounds__(256)
void ln_kernel(const float* __restrict__ x, const float* __restrict__ gw,
               const float* __restrict__ bw, float* __restrict__ y,
               float* __restrict__ yr) {
    __shared__ float red[16];
    const int row = blockIdx.x;
    const int tid = threadIdx.x;
    const float4 v = reinterpret_cast<const float4*>(x + (size_t)row * DMOD)[tid];
    float s  = v.x + v.y + v.z + v.w;
    float ss = v.x * v.x + v.y * v.y + v.z * v.z + v.w * v.w;
#pragma unroll
    for (int o = 16; o > 0; o >>= 1) {
        s  += __shfl_xor_sync(0xffffffffu, s,  o);
        ss += __shfl_xor_sync(0xffffffffu, ss, o);
    }
    if ((tid & 31) == 0) { red[tid >> 5] = s; red[8 + (tid >> 5)] = ss; }
    __syncthreads();
    float ts = 0.f, tss = 0.f;
#pragma unroll
    for (int w = 0; w < 8; w++) { ts += red[w]; tss += red[8 + w]; }
    const float mu  = ts * (1.0f / DMOD);
    const float var = tss * (1.0f / DMOD) - mu * mu;
    const float rs  = rsqrtf(var + 1e-5f);
    const float4 gv = reinterpret_cast<const float4*>(gw)[tid];
    const float4 bv = reinterpret_cast<const float4*>(bw)[tid];
    float4 o;
    o.x = (v.x - mu) * rs * gv.x + bv.x;
    o.y = (v.y - mu) * rs * gv.y + bv.y;
    o.z = (v.z - mu) * rs * gv.z + bv.z;
    o.w = (v.w - mu) * rs * gv.w + bv.w;
    if (y)  reinterpret_cast<float4*>(y  + (size_t)row * DMOD)[tid] = o;
    if (yr) {
        float4 r = make_float4(f2tf32f(o.x), f2tf32f(o.y), f2tf32f(o.z), f2tf32f(o.w));
        reinterpret_cast<float4*>(yr + (size_t)row * DMOD)[tid] = r;
    }
}

// -- TF32 GEMM v7: CTA 128x128, 256 thr, warp 64x32, cp.async 3-stage,
//    LDSM for A and B fragments; 2 CTAs/SM (110.6 KB smem, <=128 regs)
constexpr int BM = 128, BN = 128, BK = 32, STAGES = 3;
constexpr int GTH = 256;                                       // GEMM threads
constexpr int LDA_S = 36, LDB_T = 36;
constexpr int STAGE_F = BM * LDA_S + BN * LDB_T;               // 9216 floats
constexpr int SMEM_GEMM = STAGES * STAGE_F * 4;                // 110592 bytes

// AMODE 0: A row-major [M][K].  AMODE 1: A gathered from inter_out (B,H,TOK,DHD).
template <int AMODE>
struct ALoader {
    static __device__ __forceinline__ const float* ptr(const float* A, int gm, int gk, int K) {
        if (AMODE == 0) return A + (size_t)gm * K + gk;
        int bb = gm >> 11, nn = gm & (TOK - 1);
        int hh = gk >> 6,  dd = gk & (DHD - 1);
        return A + (((size_t)(bb * NH + hh) * TOK + nn) * DHD + dd);
    }
};

// Bt: [N][K] row-major (ld = K). Tile: rows nb..nb+127, cols kb..kb+31.
template <int AMODE>
__device__ __forceinline__ void gemm_load_stage(
    const float* __restrict__ A, const float* __restrict__ Bt,
    int m0, int nb, int kb, int K, uint32_t smem_stage) {
#pragma unroll
    for (int i = 0; i < 4; i++) {                // A: 128x32 = 1024 chunks / 256 thr
        int c = i * GTH + threadIdx.x;
        int row = c >> 3, kc = (c & 7) << 2;
        const float* src = ALoader<AMODE>::ptr(A, m0 + row, kb + kc, K);
        cp_async16(smem_stage + (uint32_t)(row * LDA_S + kc) * 4u, src);
    }
    const uint32_t bs = smem_stage + (uint32_t)(BM * LDA_S) * 4u;
#pragma unroll
    for (int i = 0; i < 4; i++) {                // Bt: 128x32 = 1024 chunks / 256 thr
        int c = i * GTH + threadIdx.x;
        int row = c >> 3, kc = (c & 7) << 2;
        cp_async16(bs + (uint32_t)(row * LDB_T + kc) * 4u,
                   Bt + (size_t)(nb + row) * K + kb + kc);
    }
}

// A and B fragments both via ldmatrix.x4.
__device__ __forceinline__ void gemm_compute_stage(
    uint32_t st_u, int wm, int wn, float acc[4][4][4]) {
    const int lane = threadIdx.x & 31;
    const uint32_t a_base = st_u +
        (uint32_t)((wm + (lane & 15)) * LDA_S + ((lane >> 4) << 2)) * 4u;
    const uint32_t b_base = st_u + (uint32_t)(BM * LDA_S) * 4u +
        (uint32_t)((wn + (lane & 7) + ((lane >> 4) & 1) * 8) * LDB_T +
                   ((lane >> 3) & 1) * 4) * 4u;
#pragma unroll
    for (int kk = 0; kk < BK; kk += 8) {
        uint32_t af[4][4];
#pragma unroll
        for (int mt = 0; mt < 4; mt++) {
            LDSM_X4(af[mt][0], af[mt][1], af[mt][2], af[mt][3],
                    a_base + (uint32_t)(mt * 16 * LDA_S + kk) * 4u);
        }
        uint32_t bf0[4], bf1[4];
        LDSM_X4(bf0[0], bf0[1], bf0[2], bf0[3], b_base + (uint32_t)kk * 4u);
        LDSM_X4(bf1[0], bf1[1], bf1[2], bf1[3],
                b_base + (uint32_t)(16 * LDB_T + kk) * 4u);
#pragma unroll
        for (int mt = 0; mt < 4; mt++) {
            mma_tf32(acc[mt][0], af[mt], bf0[0], bf0[1]);
            mma_tf32(acc[mt][1], af[mt], bf0[2], bf0[3]);
            mma_tf32(acc[mt][2], af[mt], bf1[0], bf1[1]);
            mma_tf32(acc[mt][3], af[mt], bf1[2], bf1[3]);
        }
    }
}

// ---- standard output: C row-major (ldc = N), optional bias + residual -----
template <int AMODE>
__global__ __launch_bounds__(GTH, 2)
void gemm3_kernel(const float* __restrict__ A, const float* __restrict__ Bt,
                  float* __restrict__ C, int M, int N, int K,
                  const float* __restrict__ bias, const float* __restrict__ res) {
    extern __shared__ float sm[];
    const uint32_t smem_u = (uint32_t)__cvta_generic_to_shared(sm);
    const int tid = threadIdx.x, wid = tid >> 5, lane = tid & 31;
    const int g = lane >> 2, tg = lane & 3;
    const int m0 = blockIdx.y * BM;
    const int n0 = blockIdx.x * BN;
    const int wm = (wid & 1) * 64;     // 2 warp-rows of 64
    const int wn = (wid >> 1) * 32;    // 4 warp-cols of 32

    float acc[4][4][4];
#pragma unroll
    for (int i = 0; i < 4; i++)
#pragma unroll
        for (int j = 0; j < 4; j++)
#pragma unroll
            for (int k = 0; k < 4; k++) acc[i][j][k] = 0.f;

    const int T = K / BK;
    gemm_load_stage<AMODE>(A, Bt, m0, n0, 0, K, smem_u);
    cp_commit();
    gemm_load_stage<AMODE>(A, Bt, m0, n0, BK, K, smem_u + STAGE_F * 4);
    cp_commit();

    int s = 0;
    for (int kt = 0; kt < T; kt++) {
        cp_wait1();
        __syncthreads();
        if (kt + 2 < T) {
            int s2 = (s + 2 >= STAGES) ? s + 2 - STAGES : s + 2;
            gemm_load_stage<AMODE>(A, Bt, m0, n0, (kt + 2) * BK, K,
                                   smem_u + (uint32_t)s2 * STAGE_F * 4);
        }
        cp_commit();
        gemm_compute_stage(smem_u + (uint32_t)s * STAGE_F * 4, wm, wn, acc);
        s = (s + 1 == STAGES) ? 0 : s + 1;
    }

#pragma unroll
    for (int mt = 0; mt < 4; mt++) {
        const int r0 = m0 + wm + mt * 16 + g;
        const int r1 = r0 + 8;
#pragma unroll
        for (int nt = 0; nt < 4; nt++) {
            const int c = n0 + wn + nt * 8 + 2 * tg;
            float2 v0 = make_float2(acc[mt][nt][0], acc[mt][nt][1]);
            float2 v1 = make_float2(acc[mt][nt][2], acc[mt][nt][3]);
            if (bias) {
                float2 bb = *reinterpret_cast<const float2*>(bias + c);
                v0.x += bb.x; v0.y += bb.y; v1.x += bb.x; v1.y += bb.y;
            }
            if (res) {
                float2 q0r = *reinterpret_cast<const float2*>(res + (size_t)r0 * N + c);
                float2 q1r = *reinterpret_cast<const float2*>(res + (size_t)r1 * N + c);
                v0.x += q0r.x; v0.y += q0r.y; v1.x += q1r.x; v1.y += q1r.y;
            }
            *reinterpret_cast<float2*>(C + (size_t)r0 * N + c) = v0;
            *reinterpret_cast<float2*>(C + (size_t)r1 * N + c) = v1;
        }
    }
}

// ---- fused QKV: one GEMM over N=3072, scatter into q_bh/k_bh/v_bh ---------
// Also writes rounded K copy (token-major) and rounded V copy TRANSPOSED.
__global__ __launch_bounds__(GTH, 2)
void gemm_qkv_kernel(const float* __restrict__ A, const float* __restrict__ Wt,
                     float* __restrict__ Cq, float* __restrict__ Ck,
                     float* __restrict__ Cv, float* __restrict__ Ckr,
                     float* __restrict__ Cvt) {
    extern __shared__ float sm[];
    const uint32_t smem_u = (uint32_t)__cvta_generic_to_shared(sm);
    const int tid = threadIdx.x, wid = tid >> 5, lane = tid & 31;
    const int g = lane >> 2, tg = lane & 3;
    const int m0 = blockIdx.y * BM;
    const int arr = blockIdx.x >> 3;                 // 0..2 : which weight/output
    const int nb  = (blockIdx.x & 7) * BN;           // column base within the array
    const float* Bt = Wt + (size_t)arr * DMOD * DMOD; // Wq^T/Wk^T/Wv^T contiguous
    float* C  = (arr == 0) ? Cq : (arr == 1) ? Ck : Cv;
    const int wm = (wid & 1) * 64;
    const int wn = (wid >> 1) * 32;
    const int K = DMOD;

    float acc[4][4][4];
#pragma unroll
    for (int i = 0; i < 4; i++)
#pragma unroll
        for (int j = 0; j < 4; j++)
#pragma unroll
            for (int k = 0; k < 4; k++) acc[i][j][k] = 0.f;

    const int T = K / BK;
    gemm_load_stage<0>(A, Bt, m0, nb, 0, K, smem_u);
    cp_commit();
    gemm_load_stage<0>(A, Bt, m0, nb, BK, K, smem_u + STAGE_F * 4);
    cp_commit();

    int s = 0;
    for (int kt = 0; kt < T; kt++) {
        cp_wait1();
        __syncthreads();
        if (kt + 2 < T) {
            int s2 = (s + 2 >= STAGES) ? s + 2 - STAGES : s + 2;
            gemm_load_stage<0>(A, Bt, m0, nb, (kt + 2) * BK, K,
                               smem_u + (uint32_t)s2 * STAGE_F * 4);
        }
        cp_commit();
        gemm_compute_stage(smem_u + (uint32_t)s * STAGE_F * 4, wm, wn, acc);
        s = (s + 1 == STAGES) ? 0 : s + 1;
    }

    // scatter to (B*H, TOK, DHD) (+ rounded copies for flash)
#pragma unroll
    for (int mt = 0; mt < 4; mt++) {
        const int r0 = m0 + wm + mt * 16 + g;
        const int r1 = r0 + 8;
        const int b0_ = r0 >> 11, n0_ = r0 & (TOK - 1);
        const int b1_ = r1 >> 11, n1_ = r1 & (TOK - 1);
#pragma unroll
        for (int nt = 0; nt < 4; nt++) {
            const int cl = nb + wn + nt * 8 + 2 * tg;
            const int hh = cl >> 6, dd = cl & (DHD - 1);
            const size_t o0 = ((size_t)(b0_ * NH + hh) * TOK + n0_) * DHD + dd;
            const size_t o1 = ((size_t)(b1_ * NH + hh) * TOK + n1_) * DHD + dd;
            float2 v0 = make_float2(acc[mt][nt][0], acc[mt][nt][1]);
            float2 v1 = make_float2(acc[mt][nt][2], acc[mt][nt][3]);
            *reinterpret_cast<float2*>(C + o0) = v0;
            *reinterpret_cast<float2*>(C + o1) = v1;
            if (arr == 1) {
                float2 r0v = make_float2(f2tf32f(v0.x), f2tf32f(v0.y));
                float2 r1v = make_float2(f2tf32f(v1.x), f2tf32f(v1.y));
                *reinterpret_cast<float2*>(Ckr + o0) = r0v;
                *reinterpret_cast<float2*>(Ckr + o1) = r1v;
            } else if (arr == 2) {
                const size_t t0 = ((size_t)(b0_ * NH + hh) * DHD + dd) * TOK + n0_;
                const size_t t1 = ((size_t)(b1_ * NH + hh) * DHD + dd) * TOK + n1_;
                Cvt[t0]       = f2tf32f(v0.x);
                Cvt[t0 + TOK] = f2tf32f(v0.y);
                Cvt[t1]       = f2tf32f(v1.x);
                Cvt[t1 + TOK] = f2tf32f(v1.y);
            }
        }
    }
}

// ---------------- flash attention v4: 64-token KV tiles, 2 CTAs/SM ----------
// K from rounded token-major copy; V from rounded TRANSPOSED copy; P via smem.
constexpr int FA_TOKT   = 64;                       // tokens per KV tile
constexpr int FA_LDK    = DHD + 4;                  // 68 floats/row (K tile: rows=tok)
constexpr int FA_LDVT   = FA_TOKT + 4;              // 68 floats/row (Vt tile: rows=dh)
constexpr int FA_KTILE  = FA_TOKT * FA_LDK;         // 4352 floats
constexpr int FA_VTILE  = DHD * FA_LDVT;            // 4352 floats
constexpr int FA_STAGE_F = FA_KTILE + FA_VTILE;     // 8704 floats
constexpr int FA_P_OFF  = 2 * FA_STAGE_F;           // P strip after 2 KV stages
constexpr int FA_LDP    = FA_TOKT + 4;              // 68 floats/row
constexpr int SMEM_FA   = (FA_P_OFF + 128 * FA_LDP) * 4;  // 104448 bytes

__global__ __launch_bounds__(256, 2)
void flash_attn_kernel(const float* __restrict__ Q, const float* __restrict__ Kr,
                       const float* __restrict__ Vt, float* __restrict__ O,
                       float* __restrict__ Or) {
    extern __shared__ float sm[];
    const uint32_t smem_u = (uint32_t)__cvta_generic_to_shared(sm);

    const int tid = threadIdx.x, wid = tid >> 5, lane = tid & 31;
    const int g = lane >> 2, tg = lane & 3;
    const int bh = blockIdx.y;
    const int q0 = blockIdx.x * 128;
    const float* Qp  = Q  + (size_t)bh * TOK * DHD;
    const float* Kp  = Kr + (size_t)bh * TOK * DHD;
    const float* Vtp = Vt + (size_t)bh * DHD * TOK;   // [dh][token]
    float* Op  = O  + (size_t)bh * TOK * DHD;
    float* Opr = Or + (size_t)bh * TOK * DHD;
    const int wm = wid * 16;
    const int r0 = q0 + wm + g, r1 = r0 + 8;

    // Q fragments (scaled by 1/8 exact, tf32-rounded)
    uint32_t qf[8][4];
#pragma unroll
    for (int ks = 0; ks < 8; ks++) {
        int c = ks * 8 + tg;
        qf[ks][0] = f2tf32(Qp[(size_t)r0 * DHD + c] * 0.125f);
        qf[ks][1] = f2tf32(Qp[(size_t)r1 * DHD + c] * 0.125f);
        qf[ks][2] = f2tf32(Qp[(size_t)r0 * DHD + c + 4] * 0.125f);
        qf[ks][3] = f2tf32(Qp[(size_t)r1 * DHD + c + 4] * 0.125f);
    }

    // ldmatrix per-lane offsets (bytes)
    const uint32_t ldsk_off =
        (uint32_t)((((lane & 7) + ((lane >> 4) & 1) * 8) * FA_LDK +
                    ((lane >> 3) & 1) * 4)) * 4u;
    const uint32_t ldsv_off =
        (uint32_t)((((lane & 7) + ((lane >> 4) & 1) * 8) * FA_LDVT +
                    ((lane >> 3) & 1) * 4)) * 4u;
    // P strip addresses
    const uint32_t p_u = smem_u + (uint32_t)FA_P_OFF * 4u;
    const uint32_t p_st0 = p_u + (uint32_t)((wm + g) * FA_LDP + 2 * tg) * 4u;
    const uint32_t p_st1 = p_u + (uint32_t)((wm + 8 + g) * FA_LDP + 2 * tg) * 4u;
    const uint32_t p_ld  = p_u +
        (uint32_t)((wm + (lane & 15)) * FA_LDP + ((lane >> 4) << 2)) * 4u;

    float m0 = -1e30f, m1 = -1e30f, l0 = 0.f, l1 = 0.f;
    float o[8][4];
#pragma unroll
    for (int i = 0; i < 8; i++)
#pragma unroll
        for (int j = 0; j < 4; j++) o[i][j] = 0.f;

    auto loadKV = [&](int j, int st) {
        const uint32_t kd = smem_u + (uint32_t)st * FA_STAGE_F * 4u;
        const uint32_t vd = kd + (uint32_t)FA_KTILE * 4u;
#pragma unroll
        for (int i = 0; i < 4; i++) {          // K: 64 tok x 64 dh
            int s = tid + i * 256;
            int r = s >> 4, c = (s & 15) << 2;
            cp_async16(kd + (uint32_t)(r * FA_LDK + c) * 4u,
                       Kp + (size_t)(j + r) * DHD + c);
        }
#pragma unroll
        for (int i = 0; i < 4; i++) {          // Vt: 64 dh x 64 tok
            int s = tid + i * 256;
            int r = s >> 4, c = (s & 15) << 2;
            cp_async16(vd + (uint32_t)(r * FA_LDVT + c) * 4u,
                       Vtp + (size_t)r * TOK + j + c);
        }
    };

    loadKV(0, 0);
    cp_commit();

    const int NT = TOK / FA_TOKT;
    for (int jt = 0; jt < NT; jt++) {
        if (jt + 1 < NT) {
            loadKV((jt + 1) * FA_TOKT, (jt + 1) & 1);
            cp_commit();
            cp_wait1();
        } else {
            cp_wait0();
        }
        __syncthreads();

        const int st = jt & 1;
        const uint32_t ks_u = smem_u + (uint32_t)st * FA_STAGE_F * 4u;
        const uint32_t vt_u = ks_u + (uint32_t)FA_KTILE * 4u;

        // S = (Q/8) K^T : B-frags via ldmatrix (8 n-tiles of 8 tokens)
        float sc[8][4];
#pragma unroll
        for (int nt = 0; nt < 8; nt++)
#pragma unroll
            for (int k4 = 0; k4 < 4; k4++) sc[nt][k4] = 0.f;
#pragma unroll
        for (int ks = 0; ks < 8; ks++) {
            const uint32_t kaddr = ks_u + (uint32_t)(ks * 8) * 4u + ldsk_off;
#pragma unroll
            for (int nt4 = 0; nt4 < 2; nt4++) {
                uint32_t bf[4][2];
                LDSM_X4(bf[0][0], bf[0][1], bf[1][0], bf[1][1],
                        kaddr + (uint32_t)(nt4 * 32 * FA_LDK) * 4u);
                LDSM_X4(bf[2][0], bf[2][1], bf[3][0], bf[3][1],
                        kaddr + (uint32_t)((nt4 * 32 + 16) * FA_LDK) * 4u);
#pragma unroll
                for (int c4 = 0; c4 < 4; c4++)
                    mma_tf32(sc[nt4 * 4 + c4], qf[ks], bf[c4][0], bf[c4][1]);
            }
        }

        // online softmax; rounded P goes straight to smem strip
        float tm0 = -1e30f, tm1 = -1e30f;
#pragma unroll
        for (int nt = 0; nt < 8; nt++) {
            tm0 = fmaxf(tm0, fmaxf(sc[nt][0], sc[nt][1]));
            tm1 = fmaxf(tm1, fmaxf(sc[nt][2], sc[nt][3]));
        }
        tm0 = fmaxf(tm0, __shfl_xor_sync(0xffffffffu, tm0, 1));
        tm0 = fmaxf(tm0, __shfl_xor_sync(0xffffffffu, tm0, 2));
        tm1 = fmaxf(tm1, __shfl_xor_sync(0xffffffffu, tm1, 1));
        tm1 = fmaxf(tm1, __shfl_xor_sync(0xffffffffu, tm1, 2));
        const float nm0 = fmaxf(m0, tm0), nm1 = fmaxf(m1, tm1);
        const float a0 = __expf(m0 - nm0), a1 = __expf(m1 - nm1);
        float ts0 = 0.f, ts1 = 0.f;
#pragma unroll
        for (int nt = 0; nt < 8; nt++) {
            float p0 = __expf(sc[nt][0] - nm0);
            float p1 = __expf(sc[nt][1] - nm0);
            float p2 = __expf(sc[nt][2] - nm1);
            float p3 = __expf(sc[nt][3] - nm1);
            ts0 += p0 + p1; ts1 += p2 + p3;
            STS64(p_st0 + (uint32_t)(nt * 8) * 4u, f2tf32f(p0), f2tf32f(p1));
            STS64(p_st1 + (uint32_t)(nt * 8) * 4u, f2tf32f(p2), f2tf32f(p3));
        }
        __syncwarp();
        ts0 += __shfl_xor_sync(0xffffffffu, ts0, 1);
        ts0 += __shfl_xor_sync(0xffffffffu, ts0, 2);
        ts1 += __shfl_xor_sync(0xffffffffu, ts1, 1);
        ts1 += __shfl_xor_sync(0xffffffffu, ts1, 2);
        l0 = l0 * a0 + ts0; l1 = l1 * a1 + ts1;
        m0 = nm0; m1 = nm1;
#pragma unroll
        for (int nt = 0; nt < 8; nt++) {
            o[nt][0] *= a0; o[nt][1] *= a0; o[nt][2] *= a1; o[nt][3] *= a1;
        }

        // O += P @ V : A-frags from P strip, B-frags from Vt, all ldmatrix
#pragma unroll
        for (int kt = 0; kt < 8; kt++) {
            uint32_t af[4];
            LDSM_X4(af[0], af[1], af[2], af[3], p_ld + (uint32_t)(kt * 8) * 4u);
            const uint32_t vaddr = vt_u + (uint32_t)(kt * 8) * 4u + ldsv_off;
#pragma unroll
            for (int ntp = 0; ntp < 4; ntp++) {
                uint32_t vb[4];
                LDSM_X4(vb[0], vb[1], vb[2], vb[3],
                        vaddr + (uint32_t)(ntp * 16 * FA_LDVT) * 4u);
                mma_tf32(o[2 * ntp],     af, vb[0], vb[1]);
                mma_tf32(o[2 * ntp + 1], af, vb[2], vb[3]);
            }
        }
        __syncthreads();
    }

    const float il0 = 1.f / l0, il1 = 1.f / l1;
#pragma unroll
    for (int nt = 0; nt < 8; nt++) {
        int c = nt * 8 + 2 * tg;
        float2 v0 = make_float2(o[nt][0] * il0, o[nt][1] * il0);
        float2 v1 = make_float2(o[nt][2] * il1, o[nt][3] * il1);
        *reinterpret_cast<float2*>(Op + (size_t)r0 * DHD + c) = v0;
        *reinterpret_cast<float2*>(Op + (size_t)r1 * DHD + c) = v1;
        float2 r0v = make_float2(f2tf32f(v0.x), f2tf32f(v0.y));
        float2 r1v = make_float2(f2tf32f(v1.x), f2tf32f(v1.y));
        *reinterpret_cast<float2*>(Opr + (size_t)r0 * DHD + c) = r0v;
        *reinterpret_cast<float2*>(Opr + (size_t)r1 * DHD + c) = r1v;
    }
}

// ---------------- GEGLU (output tf32-rounded; it only feeds FF2 GEMM) ------
__global__ __launch_bounds__(256)
void geglu_kernel(const float* __restrict__ h, float* __restrict__ act) {
    const int idx = blockIdx.x * 256 + threadIdx.x;
    const int m = idx >> 10;
    const int c = (idx & 1023) << 2;
    const float4 a  = *reinterpret_cast<const float4*>(h + (size_t)m * (2 * FF) + c);
    const float4 gt = *reinterpret_cast<const float4*>(h + (size_t)m * (2 * FF) + FF + c);
    float4 o;
    o.x = f2tf32f(a.x * gelu_exact(gt.x));
    o.y = f2tf32f(a.y * gelu_exact(gt.y));
    o.z = f2tf32f(a.z * gelu_exact(gt.z));
    o.w = f2tf32f(a.w * gelu_exact(gt.w));
    *reinterpret_cast<float4*>(act + (size_t)m * FF + c) = o;
}

// ---------------- launch ---------------------------------------------------
extern "C" void kernel_launch(void* const* d_in, const int* in_sizes, int n_in,
                              void* d_out, int out_size) {
    (void)in_sizes; (void)n_in; (void)out_size;
    const float* x     = (const float*)d_in[0];
    const float* Wq    = (const float*)d_in[1];
    const float* Wk    = (const float*)d_in[2];
    const float* Wv    = (const float*)d_in[3];
    const float* Wo    = (const float*)d_in[4];
    const float* bo    = (const float*)d_in[5];
    const float* ln1_g = (const float*)d_in[6];
    const float* ln1_b = (const float*)d_in[7];
    const float* ln3_g = (const float*)d_in[8];
    const float* ln3_b = (const float*)d_in[9];
    const float* Wff1  = (const float*)d_in[10];
    const float* bff1  = (const float*)d_in[11];
    const float* Wff2  = (const float*)d_in[12];
    const float* bff2  = (const float*)d_in[13];

    float* out = (float*)d_out;
    const size_t SZ = (size_t)MROWS * DMOD;
    float* out_x  = out;            // x
    float* out_q  = out + SZ;       // q_bh
    float* out_k  = out + 2 * SZ;   // k_bh
    float* out_v  = out + 3 * SZ;   // v_bh
    float* out_io = out + 4 * SZ;   // inter_out
    float* out_xf = out + 5 * SZ;   // x_features

    float *x2, *xf2, *xfr, *ior, *kr, *vtr, *hbuf, *actbuf, *wbuf;
    cudaGetSymbolAddress((void**)&x2,     g_x2);
    cudaGetSymbolAddress((void**)&xf2,    g_xf2);
    cudaGetSymbolAddress((void**)&xfr,    g_xfr);
    cudaGetSymbolAddress((void**)&ior,    g_ior);
    cudaGetSymbolAddress((void**)&kr,     g_kr);
    cudaGetSymbolAddress((void**)&vtr,    g_vtr);
    cudaGetSymbolAddress((void**)&hbuf,   g_h);
    cudaGetSymbolAddress((void**)&actbuf, g_act);
    cudaGetSymbolAddress((void**)&wbuf,   g_w);

    cudaFuncSetAttribute(gemm_qkv_kernel,
                         cudaFuncAttributeMaxDynamicSharedMemorySize, SMEM_GEMM);
    cudaFuncSetAttribute(gemm3_kernel<0>,
                         cudaFuncAttributeMaxDynamicSharedMemorySize, SMEM_GEMM);
    cudaFuncSetAttribute(gemm3_kernel<1>,
                         cudaFuncAttributeMaxDynamicSharedMemorySize, SMEM_GEMM);
    cudaFuncSetAttribute(flash_attn_kernel,
                         cudaFuncAttributeMaxDynamicSharedMemorySize, SMEM_FA);

    const dim3 blk(GTH);

    // 0) transpose + round all weights to tf32 (Wt = [N][K], n-major)
    cvt_t_kernel<<<dim3(32, 32),  256>>>(Wq,   wbuf + WOFF_Q,   DMOD, DMOD);
    cvt_t_kernel<<<dim3(32, 32),  256>>>(Wk,   wbuf + WOFF_K,   DMOD, DMOD);
    cvt_t_kernel<<<dim3(32, 32),  256>>>(Wv,   wbuf + WOFF_V,   DMOD, DMOD);
    cvt_t_kernel<<<dim3(32, 32),  256>>>(Wo,   wbuf + WOFF_O,   DMOD, DMOD);
    cvt_t_kernel<<<dim3(256, 32), 256>>>(Wff1, wbuf + WOFF_FF1, DMOD, 2 * FF);
    cvt_t_kernel<<<dim3(32, 128), 256>>>(Wff2, wbuf + WOFF_FF2, FF,   DMOD);

    // 1) LN1 -> x_features (exact) + rounded copy for GEMM A
    ln_kernel<<<MROWS, 256>>>(x, ln1_g, ln1_b, out_xf, xfr);

    // 2) fused QKV GEMM; exact q/k/v to d_out, rounded k (token-major) + v (transposed)
    gemm_qkv_kernel<<<dim3(3 * DMOD / BN, MROWS / BM), blk, SMEM_GEMM>>>(
        xfr, wbuf + WOFF_Q, out_q, out_k, out_v, kr, vtr);

    // 3) attention -> inter_out (exact) + rounded copy
    flash_attn_kernel<<<dim3(TOK / 128, NBAT * NH), 256, SMEM_FA>>>(
        out_q, kr, vtr, out_io, ior);

    // 4) Wo GEMM (gather-A from rounded inter_out) + bo + residual x -> x2 (exact)
    gemm3_kernel<1><<<dim3(DMOD / BN, MROWS / BM), blk, SMEM_GEMM>>>(
        ior, wbuf + WOFF_O, x2, MROWS, DMOD, DMOD, bo, x);

    // 5) LN3 -> xf2 (rounded only; internal)
    ln_kernel<<<MROWS, 256>>>(x2, ln3_g, ln3_b, nullptr, xf2);

    // 6) FF1 GEMM (+bff1) -> h (exact; geglu needs exact gate)
    gemm3_kernel<0><<<dim3(2 * FF / BN, MROWS / BM), blk, SMEM_GEMM>>>(
        xf2, wbuf + WOFF_FF1, hbuf, MROWS, 2 * FF, DMOD, bff1, nullptr);

    // 7) GEGLU -> act (rounded)
    geglu_kernel<<<(MROWS * (FF / 4)) / 256, 256>>>(hbuf, actbuf);

    // 8) FF2 GEMM (+bff2) + residual x2 -> final x
    gemm3_kernel<0><<<dim3(DMOD / BN, MROWS / BM), blk, SMEM_GEMM>>>(
        actbuf, wbuf + WOFF_FF2, out_x, MROWS, DMOD, FF, bff2, x2);
}

// round 17
// speedup vs baseline: 1.2176x; 1.0218x over previous
#include <cuda_runtime.h>
#include <cstdint>
#include <cstdio>

#define TOK   2048
#define NBAT  2
#define NH    16
#define DHD   64
#define DMOD  1024
#define MROWS 4096   /* B*N */
#define FF    4096

// ---------------- scratch (static device globals; no runtime allocation) ---
__device__ float g_x2 [MROWS * DMOD];            // 16 MB : x after attn residual (exact)
__device__ float g_xf2[MROWS * DMOD];            // 16 MB : LN3 output (tf32-rounded)
__device__ float g_xfr[MROWS * DMOD];            // 16 MB : LN1 output (tf32-rounded)
__device__ float g_ior[MROWS * DMOD];            // 16 MB : inter_out (tf32-rounded)
__device__ float g_kr [MROWS * DMOD];            // 16 MB : k_bh tf32-rounded
__device__ float g_vtr[MROWS * DMOD];            // 16 MB : v_bh tf32-rounded TRANSPOSED [bh][dh][tok]
__device__ float g_act[(size_t)MROWS * FF];      // 64 MB : fused FF1+geglu output (tf32-rounded)
__device__ float g_w  [16 * 1024 * 1024];        // 64 MB : all weights, tf32-rounded + TRANSPOSED (n-major)
// offsets (floats) within g_w (each block is Wt = [N][K] row-major):
#define WOFF_Q    0
#define WOFF_K    (1024 * 1024)
#define WOFF_V    (2 * 1024 * 1024)
#define WOFF_O    (3 * 1024 * 1024)
#define WOFF_FF1  (4 * 1024 * 1024)
#define WOFF_FF2  (12 * 1024 * 1024)

// ---------------- helpers --------------------------------------------------
__device__ __forceinline__ uint32_t f2tf32(float x) {
    uint32_t t;
    asm("cvt.rna.tf32.f32 %0, %1;" : "=r"(t) : "f"(x));
    return t;
}
__device__ __forceinline__ float f2tf32f(float x) { return __uint_as_float(f2tf32(x)); }

__device__ __forceinline__ void mma_tf32(float c[4], const uint32_t a[4],
                                         uint32_t b0, uint32_t b1) {
    asm volatile(
        "mma.sync.aligned.m16n8k8.row.col.f32.tf32.tf32.f32 "
        "{%0,%1,%2,%3}, {%4,%5,%6,%7}, {%8,%9}, {%0,%1,%2,%3};\n"
        : "+f"(c[0]), "+f"(c[1]), "+f"(c[2]), "+f"(c[3])
        : "r"(a[0]), "r"(a[1]), "r"(a[2]), "r"(a[3]), "r"(b0), "r"(b1));
}

#define LDSM_X4(r0, r1, r2, r3, addr)                                         \
    asm volatile("ldmatrix.sync.aligned.m8n8.x4.shared.b16 {%0,%1,%2,%3}, [%4];" \
                 : "=r"(r0), "=r"(r1), "=r"(r2), "=r"(r3) : "r"(addr))

#define STS64(addr, v0, v1)                                                   \
    asm volatile("st.shared.v2.f32 [%0], {%1, %2};" :: "r"(addr), "f"(v0), "f"(v1))

__device__ __forceinline__ void cp_async16(uint32_t dst, const void* src) {
    asm volatile("cp.async.cg.shared.global [%0], [%1], 16;\n" :: "r"(dst), "l"(src));
}
__device__ __forceinline__ void cp_commit() {
    asm volatile("cp.async.commit_group;\n" ::: "memory");
}
__device__ __forceinline__ void cp_wait1() {
    asm volatile("cp.async.wait_group 1;\n" ::: "memory");
}
__device__ __forceinline__ void cp_wait0() {
    asm volatile("cp.async.wait_group 0;\n" ::: "memory");
}

__device__ __forceinline__ float gelu_exact(float x) {
    return 0.5f * x * (1.0f + erff(x * 0.70710678118654752f));
}

// ------------ weight transpose+round: src[K][N] -> dst[N][K], tf32 ----------
__global__ __launch_bounds__(256)
void cvt_t_kernel(const float* __restrict__ src, float* __restrict__ dst,
                  int K, int N) {
    __shared__ float t[32][33];
    const int k0 = blockIdx.y * 32, n0 = blockIdx.x * 32;
    const int tx = threadIdx.x & 31, ty = threadIdx.x >> 5;   // ty 0..7
#pragma unroll
    for (int i = 0; i < 32; i += 8)
        t[ty + i][tx] = f2tf32f(src[(size_t)(k0 + ty + i) * N + n0 + tx]);
    __syncthreads();
#pragma unroll
    for (int i = 0; i < 32; i += 8)
        dst[(size_t)(n0 + ty + i) * K + k0 + tx] = t[tx][ty + i];
}

// ---- FF1 variant: column-permuted transpose. New col 2j = old j (a-half),
//      new col 2j+1 = old FF+j (gate-half). src[K][2*FF] -> dst[2*FF][K].
__global__ __launch_bounds__(256)
void cvt_t_ff1_kernel(const float* __restrict__ src, float* __restrict__ dst,
                      int K) {
    __shared__ float t[32][33];
    const int k0 = blockIdx.y * 32, n0 = blockIdx.x * 32;   // n0: NEW col base
    const int tx = threadIdx.x & 31, ty = threadIdx.x >> 5;
    const int cn = n0 + tx;                                  // new column
    const int co = (cn & 1) ? FF + (cn >> 1) : (cn >> 1);    // old column
#pragma unroll
    for (int i = 0; i < 32; i += 8)
        t[ty + i][tx] = f2tf32f(src[(size_t)(k0 + ty + i) * (2 * FF) + co]);
    __syncthreads();
#pragma unroll
    for (int i = 0; i < 32; i += 8)
        dst[(size_t)(n0 + ty + i) * K + k0 + tx] = t[tx][ty + i];
}

// ---------------- LayerNorm (one block per row of 1024) --------------------
__global__ __launch_bounds__(256)
void ln_kernel(const float* __restrict__ x, const float* __restrict__ gw,
               const float* __restrict__ bw, float* __restrict__ y,
               float* __restrict__ yr) {
    __shared__ float red[16];
    const int row = blockIdx.x;
    const int tid = threadIdx.x;
    const float4 v = reinterpret_cast<const float4*>(x + (size_t)row * DMOD)[tid];
    float s  = v.x + v.y + v.z + v.w;
    float ss = v.x * v.x + v.y * v.y + v.z * v.z + v.w * v.w;
#pragma unroll
    for (int o = 16; o > 0; o >>= 1) {
        s  += __shfl_xor_sync(0xffffffffu, s,  o);
        ss += __shfl_xor_sync(0xffffffffu, ss, o);
    }
    if ((tid & 31) == 0) { red[tid >> 5] = s; red[8 + (tid >> 5)] = ss; }
    __syncthreads();
    float ts = 0.f, tss = 0.f;
#pragma unroll
    for (int w = 0; w < 8; w++) { ts += red[w]; tss += red[8 + w]; }
    const float mu  = ts * (1.0f / DMOD);
    const float var = tss * (1.0f / DMOD) - mu * mu;
    const float rs  = rsqrtf(var + 1e-5f);
    const float4 gv = reinterpret_cast<const float4*>(gw)[tid];
    const float4 bv = reinterpret_cast<const float4*>(bw)[tid];
    float4 o;
    o.x = (v.x - mu) * rs * gv.x + bv.x;
    o.y = (v.y - mu) * rs * gv.y + bv.y;
    o.z = (v.z - mu) * rs * gv.z + bv.z;
    o.w = (v.w - mu) * rs * gv.w + bv.w;
    if (y)  reinterpret_cast<float4*>(y  + (size_t)row * DMOD)[tid] = o;
    if (yr) {
        float4 r = make_float4(f2tf32f(o.x), f2tf32f(o.y), f2tf32f(o.z), f2tf32f(o.w));
        reinterpret_cast<float4*>(yr + (size_t)row * DMOD)[tid] = r;
    }
}

// -- TF32 GEMM v8: CTA 128x128, 256 thr, warp 64x32, cp.async 3-stage,
//    LDSM A+B; 2 CTAs/SM. EPI 0 = bias+res row-major store; EPI 1 = fused geglu.
constexpr int BM = 128, BN = 128, BK = 32, STAGES = 3;
constexpr int GTH = 256;                                       // GEMM threads
constexpr int LDA_S = 36, LDB_T = 36;
constexpr int STAGE_F = BM * LDA_S + BN * LDB_T;               // 9216 floats
constexpr int SMEM_GEMM = STAGES * STAGE_F * 4;                // 110592 bytes

// AMODE 0: A row-major [M][K].  AMODE 1: A gathered from inter_out (B,H,TOK,DHD).
template <int AMODE>
struct ALoader {
    static __device__ __forceinline__ const float* ptr(const float* A, int gm, int gk, int K) {
        if (AMODE == 0) return A + (size_t)gm * K + gk;
        int bb = gm >> 11, nn = gm & (TOK - 1);
        int hh = gk >> 6,  dd = gk & (DHD - 1);
        return A + (((size_t)(bb * NH + hh) * TOK + nn) * DHD + dd);
    }
};

// Bt: [N][K] row-major (ld = K). Tile: rows nb..nb+127, cols kb..kb+31.
template <int AMODE>
__device__ __forceinline__ void gemm_load_stage(
    const float* __restrict__ A, const float* __restrict__ Bt,
    int m0, int nb, int kb, int K, uint32_t smem_stage) {
#pragma unroll
    for (int i = 0; i < 4; i++) {                // A: 128x32 = 1024 chunks / 256 thr
        int c = i * GTH + threadIdx.x;
        int row = c >> 3, kc = (c & 7) << 2;
        const float* src = ALoader<AMODE>::ptr(A, m0 + row, kb + kc, K);
        cp_async16(smem_stage + (uint32_t)(row * LDA_S + kc) * 4u, src);
    }
    const uint32_t bs = smem_stage + (uint32_t)(BM * LDA_S) * 4u;
#pragma unroll
    for (int i = 0; i < 4; i++) {                // Bt: 128x32 = 1024 chunks / 256 thr
        int c = i * GTH + threadIdx.x;
        int row = c >> 3, kc = (c & 7) << 2;
        cp_async16(bs + (uint32_t)(row * LDB_T + kc) * 4u,
                   Bt + (size_t)(nb + row) * K + kb + kc);
    }
}

// A and B fragments both via ldmatrix.x4.
__device__ __forceinline__ void gemm_compute_stage(
    uint32_t st_u, int wm, int wn, float acc[4][4][4]) {
    const int lane = threadIdx.x & 31;
    const uint32_t a_base = st_u +
        (uint32_t)((wm + (lane & 15)) * LDA_S + ((lane >> 4) << 2)) * 4u;
    const uint32_t b_base = st_u + (uint32_t)(BM * LDA_S) * 4u +
        (uint32_t)((wn + (lane & 7) + ((lane >> 4) & 1) * 8) * LDB_T +
                   ((lane >> 3) & 1) * 4) * 4u;
#pragma unroll
    for (int kk = 0; kk < BK; kk += 8) {
        uint32_t af[4][4];
#pragma unroll
        for (int mt = 0; mt < 4; mt++) {
            LDSM_X4(af[mt][0], af[mt][1], af[mt][2], af[mt][3],
                    a_base + (uint32_t)(mt * 16 * LDA_S + kk) * 4u);
        }
        uint32_t bf0[4], bf1[4];
        LDSM_X4(bf0[0], bf0[1], bf0[2], bf0[3], b_base + (uint32_t)kk * 4u);
        LDSM_X4(bf1[0], bf1[1], bf1[2], bf1[3],
                b_base + (uint32_t)(16 * LDB_T + kk) * 4u);
#pragma unroll
        for (int mt = 0; mt < 4; mt++) {
            mma_tf32(acc[mt][0], af[mt], bf0[0], bf0[1]);
            mma_tf32(acc[mt][1], af[mt], bf0[2], bf0[3]);
            mma_tf32(acc[mt][2], af[mt], bf1[0], bf1[1]);
            mma_tf32(acc[mt][3], af[mt], bf1[2], bf1[3]);
        }
    }
}

// ---- EPI 0: C row-major (ldc = N), optional bias + residual.
// ---- EPI 1: fused geglu. Pair (c, c+1) = (a_j, gate_j), j = c/2;
//             writes act[M][FF] = tf32((a+ba)*gelu(gate+bg)); bias = raw bff1.
template <int AMODE, int EPI>
__global__ __launch_bounds__(GTH, 2)
void gemm3_kernel(const float* __restrict__ A, const float* __restrict__ Bt,
                  float* __restrict__ C, int M, int N, int K,
                  const float* __restrict__ bias, const float* __restrict__ res) {
    extern __shared__ float sm[];
    const uint32_t smem_u = (uint32_t)__cvta_generic_to_shared(sm);
    const int tid = threadIdx.x, wid = tid >> 5, lane = tid & 31;
    const int g = lane >> 2, tg = lane & 3;
    const int m0 = blockIdx.y * BM;
    const int n0 = blockIdx.x * BN;
    const int wm = (wid & 1) * 64;     // 2 warp-rows of 64
    const int wn = (wid >> 1) * 32;    // 4 warp-cols of 32

    float acc[4][4][4];
#pragma unroll
    for (int i = 0; i < 4; i++)
#pragma unroll
        for (int j = 0; j < 4; j++)
#pragma unroll
            for (int k = 0; k < 4; k++) acc[i][j][k] = 0.f;

    const int T = K / BK;
    gemm_load_stage<AMODE>(A, Bt, m0, n0, 0, K, smem_u);
    cp_commit();
    gemm_load_stage<AMODE>(A, Bt, m0, n0, BK, K, smem_u + STAGE_F * 4);
    cp_commit();

    int s = 0;
    for (int kt = 0; kt < T; kt++) {
        cp_wait1();
        __syncthreads();
        if (kt + 2 < T) {
            int s2 = (s + 2 >= STAGES) ? s + 2 - STAGES : s + 2;
            gemm_load_stage<AMODE>(A, Bt, m0, n0, (kt + 2) * BK, K,
                                   smem_u + (uint32_t)s2 * STAGE_F * 4);
        }
        cp_commit();
        gemm_compute_stage(smem_u + (uint32_t)s * STAGE_F * 4, wm, wn, acc);
        s = (s + 1 == STAGES) ? 0 : s + 1;
    }

#pragma unroll
    for (int mt = 0; mt < 4; mt++) {
        const int r0 = m0 + wm + mt * 16 + g;
        const int r1 = r0 + 8;
#pragma unroll
        for (int nt = 0; nt < 4; nt++) {
            const int c = n0 + wn + nt * 8 + 2 * tg;
            if (EPI == 0) {
                float2 v0 = make_float2(acc[mt][nt][0], acc[mt][nt][1]);
                float2 v1 = make_float2(acc[mt][nt][2], acc[mt][nt][3]);
                if (bias) {
                    float2 bb = *reinterpret_cast<const float2*>(bias + c);
                    v0.x += bb.x; v0.y += bb.y; v1.x += bb.x; v1.y += bb.y;
                }
                if (res) {
                    float2 q0r = *reinterpret_cast<const float2*>(res + (size_t)r0 * N + c);
                    float2 q1r = *reinterpret_cast<const float2*>(res + (size_t)r1 * N + c);
                    v0.x += q0r.x; v0.y += q0r.y; v1.x += q1r.x; v1.y += q1r.y;
                }
                *reinterpret_cast<float2*>(C + (size_t)r0 * N + c) = v0;
                *reinterpret_cast<float2*>(C + (size_t)r1 * N + c) = v1;
            } else {
                const int j  = c >> 1;            // output feature index
                const float ba = bias[j];
                const float bg = bias[FF + j];
                const float a0 = acc[mt][nt][0] + ba;
                const float g0 = acc[mt][nt][1] + bg;
                const float a1 = acc[mt][nt][2] + ba;
                const float g1 = acc[mt][nt][3] + bg;
                C[(size_t)r0 * FF + j] = f2tf32f(a0 * gelu_exact(g0));
                C[(size_t)r1 * FF + j] = f2tf32f(a1 * gelu_exact(g1));
            }
        }
    }
}

// ---- fused QKV: one GEMM over N=3072, scatter into q_bh/k_bh/v_bh ---------
// Also writes rounded K copy (token-major) and rounded V copy TRANSPOSED.
__global__ __launch_bounds__(GTH, 2)
void gemm_qkv_kernel(const float* __restrict__ A, const float* __restrict__ Wt,
                     float* __restrict__ Cq, float* __restrict__ Ck,
                     float* __restrict__ Cv, float* __restrict__ Ckr,
                     float* __restrict__ Cvt) {
    extern __shared__ float sm[];
    const uint32_t smem_u = (uint32_t)__cvta_generic_to_shared(sm);
    const int tid = threadIdx.x, wid = tid >> 5, lane = tid & 31;
    const int g = lane >> 2, tg = lane & 3;
    const int m0 = blockIdx.y * BM;
    const int arr = blockIdx.x >> 3;                 // 0..2 : which weight/output
    const int nb  = (blockIdx.x & 7) * BN;           // column base within the array
    const float* Bt = Wt + (size_t)arr * DMOD * DMOD; // Wq^T/Wk^T/Wv^T contiguous
    float* C  = (arr == 0) ? Cq : (arr == 1) ? Ck : Cv;
    const int wm = (wid & 1) * 64;
    const int wn = (wid >> 1) * 32;
    const int K = DMOD;

    float acc[4][4][4];
#pragma unroll
    for (int i = 0; i < 4; i++)
#pragma unroll
        for (int j = 0; j < 4; j++)
#pragma unroll
            for (int k = 0; k < 4; k++) acc[i][j][k] = 0.f;

    const int T = K / BK;
    gemm_load_stage<0>(A, Bt, m0, nb, 0, K, smem_u);
    cp_commit();
    gemm_load_stage<0>(A, Bt, m0, nb, BK, K, smem_u + STAGE_F * 4);
    cp_commit();

    int s = 0;
    for (int kt = 0; kt < T; kt++) {
        cp_wait1();
        __syncthreads();
        if (kt + 2 < T) {
            int s2 = (s + 2 >= STAGES) ? s + 2 - STAGES : s + 2;
            gemm_load_stage<0>(A, Bt, m0, nb, (kt + 2) * BK, K,
                               smem_u + (uint32_t)s2 * STAGE_F * 4);
        }
        cp_commit();
        gemm_compute_stage(smem_u + (uint32_t)s * STAGE_F * 4, wm, wn, acc);
        s = (s + 1 == STAGES) ? 0 : s + 1;
    }

    // scatter to (B*H, TOK, DHD) (+ rounded copies for flash)
#pragma unroll
    for (int mt = 0; mt < 4; mt++) {
        const int r0 = m0 + wm + mt * 16 + g;
        const int r1 = r0 + 8;
        const int b0_ = r0 >> 11, n0_ = r0 & (TOK - 1);
        const int b1_ = r1 >> 11, n1_ = r1 & (TOK - 1);
#pragma unroll
        for (int nt = 0; nt < 4; nt++) {
            const int cl = nb + wn + nt * 8 + 2 * tg;
            const int hh = cl >> 6, dd = cl & (DHD - 1);
            const size_t o0 = ((size_t)(b0_ * NH + hh) * TOK + n0_) * DHD + dd;
            const size_t o1 = ((size_t)(b1_ * NH + hh) * TOK + n1_) * DHD + dd;
            float2 v0 = make_float2(acc[mt][nt][0], acc[mt][nt][1]);
            float2 v1 = make_float2(acc[mt][nt][2], acc[mt][nt][3]);
            *reinterpret_cast<float2*>(C + o0) = v0;
            *reinterpret_cast<float2*>(C + o1) = v1;
            if (arr == 1) {
                float2 r0v = make_float2(f2tf32f(v0.x), f2tf32f(v0.y));
                float2 r1v = make_float2(f2tf32f(v1.x), f2tf32f(v1.y));
                *reinterpret_cast<float2*>(Ckr + o0) = r0v;
                *reinterpret_cast<float2*>(Ckr + o1) = r1v;
            } else if (arr == 2) {
                const size_t t0 = ((size_t)(b0_ * NH + hh) * DHD + dd) * TOK + n0_;
                const size_t t1 = ((size_t)(b1_ * NH + hh) * DHD + dd) * TOK + n1_;
                Cvt[t0]       = f2tf32f(v0.x);
                Cvt[t0 + TOK] = f2tf32f(v0.y);
                Cvt[t1]       = f2tf32f(v1.x);
                Cvt[t1 + TOK] = f2tf32f(v1.y);
            }
        }
    }
}

// ---------------- flash attention v4: 64-token KV tiles, 2 CTAs/SM ----------
// K from rounded token-major copy; V from rounded TRANSPOSED copy; P via smem.
constexpr int FA_TOKT   = 64;                       // tokens per KV tile
constexpr int FA_LDK    = DHD + 4;                  // 68 floats/row (K tile: rows=tok)
constexpr int FA_LDVT   = FA_TOKT + 4;              // 68 floats/row (Vt tile: rows=dh)
constexpr int FA_KTILE  = FA_TOKT * FA_LDK;         // 4352 floats
constexpr int FA_VTILE  = DHD * FA_LDVT;            // 4352 floats
constexpr int FA_STAGE_F = FA_KTILE + FA_VTILE;     // 8704 floats
constexpr int FA_P_OFF  = 2 * FA_STAGE_F;           // P strip after 2 KV stages
constexpr int FA_LDP    = FA_TOKT + 4;              // 68 floats/row
constexpr int SMEM_FA   = (FA_P_OFF + 128 * FA_LDP) * 4;  // 104448 bytes

__global__ __launch_bounds__(256, 2)
void flash_attn_kernel(const float* __restrict__ Q, const float* __restrict__ Kr,
                       const float* __restrict__ Vt, float* __restrict__ O,
                       float* __restrict__ Or) {
    extern __shared__ float sm[];
    const uint32_t smem_u = (uint32_t)__cvta_generic_to_shared(sm);

    const int tid = threadIdx.x, wid = tid >> 5, lane = tid & 31;
    const int g = lane >> 2, tg = lane & 3;
    const int bh = blockIdx.y;
    const int q0 = blockIdx.x * 128;
    const float* Qp  = Q  + (size_t)bh * TOK * DHD;
    const float* Kp  = Kr + (size_t)bh * TOK * DHD;
    const float* Vtp = Vt + (size_t)bh * DHD * TOK;   // [dh][token]
    float* Op  = O  + (size_t)bh * TOK * DHD;
    float* Opr = Or + (size_t)bh * TOK * DHD;
    const int wm = wid * 16;
    const int r0 = q0 + wm + g, r1 = r0 + 8;

    // Q fragments (scaled by 1/8 exact, tf32-rounded)
    uint32_t qf[8][4];
#pragma unroll
    for (int ks = 0; ks < 8; ks++) {
        int c = ks * 8 + tg;
        qf[ks][0] = f2tf32(Qp[(size_t)r0 * DHD + c] * 0.125f);
        qf[ks][1] = f2tf32(Qp[(size_t)r1 * DHD + c] * 0.125f);
        qf[ks][2] = f2tf32(Qp[(size_t)r0 * DHD + c + 4] * 0.125f);
        qf[ks][3] = f2tf32(Qp[(size_t)r1 * DHD + c + 4] * 0.125f);
    }

    // ldmatrix per-lane offsets (bytes)
    const uint32_t ldsk_off =
        (uint32_t)((((lane & 7) + ((lane >> 4) & 1) * 8) * FA_LDK +
                    ((lane >> 3) & 1) * 4)) * 4u;
    const uint32_t ldsv_off =
        (uint32_t)((((lane & 7) + ((lane >> 4) & 1) * 8) * FA_LDVT +
                    ((lane >> 3) & 1) * 4)) * 4u;
    // P strip addresses
    const uint32_t p_u = smem_u + (uint32_t)FA_P_OFF * 4u;
    const uint32_t p_st0 = p_u + (uint32_t)((wm + g) * FA_LDP + 2 * tg) * 4u;
    const uint32_t p_st1 = p_u + (uint32_t)((wm + 8 + g) * FA_LDP + 2 * tg) * 4u;
    const uint32_t p_ld  = p_u +
        (uint32_t)((wm + (lane & 15)) * FA_LDP + ((lane >> 4) << 2)) * 4u;

    float m0 = -1e30f, m1 = -1e30f, l0 = 0.f, l1 = 0.f;
    float o[8][4];
#pragma unroll
    for (int i = 0; i < 8; i++)
#pragma unroll
        for (int j = 0; j < 4; j++) o[i][j] = 0.f;

    auto loadKV = [&](int j, int st) {
        const uint32_t kd = smem_u + (uint32_t)st * FA_STAGE_F * 4u;
        const uint32_t vd = kd + (uint32_t)FA_KTILE * 4u;
#pragma unroll
        for (int i = 0; i < 4; i++) {          // K: 64 tok x 64 dh
            int s = tid + i * 256;
            int r = s >> 4, c = (s & 15) << 2;
            cp_async16(kd + (uint32_t)(r * FA_LDK + c) * 4u,
                       Kp + (size_t)(j + r) * DHD + c);
        }
#pragma unroll
        for (int i = 0; i < 4; i++) {          // Vt: 64 dh x 64 tok
            int s = tid + i * 256;
            int r = s >> 4, c = (s & 15) << 2;
            cp_async16(vd + (uint32_t)(r * FA_LDVT + c) * 4u,
                       Vtp + (size_t)r * TOK + j + c);
        }
    };

    loadKV(0, 0);
    cp_commit();

    const int NT = TOK / FA_TOKT;
    for (int jt = 0; jt < NT; jt++) {
        if (jt + 1 < NT) {
            loadKV((jt + 1) * FA_TOKT, (jt + 1) & 1);
            cp_commit();
            cp_wait1();
        } else {
            cp_wait0();
        }
        __syncthreads();

        const int st = jt & 1;
        const uint32_t ks_u = smem_u + (uint32_t)st * FA_STAGE_F * 4u;
        const uint32_t vt_u = ks_u + (uint32_t)FA_KTILE * 4u;

        // S = (Q/8) K^T : B-frags via ldmatrix (8 n-tiles of 8 tokens)
        float sc[8][4];
#pragma unroll
        for (int nt = 0; nt < 8; nt++)
#pragma unroll
            for (int k4 = 0; k4 < 4; k4++) sc[nt][k4] = 0.f;
#pragma unroll
        for (int ks = 0; ks < 8; ks++) {
            const uint32_t kaddr = ks_u + (uint32_t)(ks * 8) * 4u + ldsk_off;
#pragma unroll
            for (int nt4 = 0; nt4 < 2; nt4++) {
                uint32_t bf[4][2];
                LDSM_X4(bf[0][0], bf[0][1], bf[1][0], bf[1][1],
                        kaddr + (uint32_t)(nt4 * 32 * FA_LDK) * 4u);
                LDSM_X4(bf[2][0], bf[2][1], bf[3][0], bf[3][1],
                        kaddr + (uint32_t)((nt4 * 32 + 16) * FA_LDK) * 4u);
#pragma unroll
                for (int c4 = 0; c4 < 4; c4++)
                    mma_tf32(sc[nt4 * 4 + c4], qf[ks], bf[c4][0], bf[c4][1]);
            }
        }

        // online softmax; rounded P goes straight to smem strip
        float tm0 = -1e30f, tm1 = -1e30f;
#pragma unroll
        for (int nt = 0; nt < 8; nt++) {
            tm0 = fmaxf(tm0, fmaxf(sc[nt][0], sc[nt][1]));
            tm1 = fmaxf(tm1, fmaxf(sc[nt][2], sc[nt][3]));
        }
        tm0 = fmaxf(tm0, __shfl_xor_sync(0xffffffffu, tm0, 1));
        tm0 = fmaxf(tm0, __shfl_xor_sync(0xffffffffu, tm0, 2));
        tm1 = fmaxf(tm1, __shfl_xor_sync(0xffffffffu, tm1, 1));
        tm1 = fmaxf(tm1, __shfl_xor_sync(0xffffffffu, tm1, 2));
        const float nm0 = fmaxf(m0, tm0), nm1 = fmaxf(m1, tm1);
        const float a0 = __expf(m0 - nm0), a1 = __expf(m1 - nm1);
        float ts0 = 0.f, ts1 = 0.f;
#pragma unroll
        for (int nt = 0; nt < 8; nt++) {
            float p0 = __expf(sc[nt][0] - nm0);
            float p1 = __expf(sc[nt][1] - nm0);
            float p2 = __expf(sc[nt][2] - nm1);
            float p3 = __expf(sc[nt][3] - nm1);
            ts0 += p0 + p1; ts1 += p2 + p3;
            STS64(p_st0 + (uint32_t)(nt * 8) * 4u, f2tf32f(p0), f2tf32f(p1));
            STS64(p_st1 + (uint32_t)(nt * 8) * 4u, f2tf32f(p2), f2tf32f(p3));
        }
        __syncwarp();
        ts0 += __shfl_xor_sync(0xffffffffu, ts0, 1);
        ts0 += __shfl_xor_sync(0xffffffffu, ts0, 2);
        ts1 += __shfl_xor_sync(0xffffffffu, ts1, 1);
        ts1 += __shfl_xor_sync(0xffffffffu, ts1, 2);
        l0 = l0 * a0 + ts0; l1 = l1 * a1 + ts1;
        m0 = nm0; m1 = nm1;
#pragma unroll
        for (int nt = 0; nt < 8; nt++) {
            o[nt][0] *= a0; o[nt][1] *= a0; o[nt][2] *= a1; o[nt][3] *= a1;
        }

        // O += P @ V : A-frags from P strip, B-frags from Vt, all ldmatrix
#pragma unroll
        for (int kt = 0; kt < 8; kt++) {
            uint32_t af[4];
            LDSM_X4(af[0], af[1], af[2], af[3], p_ld + (uint32_t)(kt * 8) * 4u);
            const uint32_t vaddr = vt_u + (uint32_t)(kt * 8) * 4u + ldsv_off;
#pragma unroll
            for (int ntp = 0; ntp < 4; ntp++) {
                uint32_t vb[4];
                LDSM_X4(vb[0], vb[1], vb[2], vb[3],
                        vaddr + (uint32_t)(ntp * 16 * FA_LDVT) * 4u);
                mma_tf32(o[2 * ntp],     af, vb[0], vb[1]);
                mma_tf32(o[2 * ntp + 1], af, vb[2], vb[3]);
            }
        }
        __syncthreads();
    }

    const float il0 = 1.f / l0, il1 = 1.f / l1;
#pragma unroll
    for (int nt = 0; nt < 8; nt++) {
        int c = nt * 8 + 2 * tg;
        float2 v0 = make_float2(o[nt][0] * il0, o[nt][1] * il0);
        float2 v1 = make_float2(o[nt][2] * il1, o[nt][3] * il1);
        *reinterpret_cast<float2*>(Op + (size_t)r0 * DHD + c) = v0;
        *reinterpret_cast<float2*>(Op + (size_t)r1 * DHD + c) = v1;
        float2 r0v = make_float2(f2tf32f(v0.x), f2tf32f(v0.y));
        float2 r1v = make_float2(f2tf32f(v1.x), f2tf32f(v1.y));
        *reinterpret_cast<float2*>(Opr + (size_t)r0 * DHD + c) = r0v;
        *reinterpret_cast<float2*>(Opr + (size_t)r1 * DHD + c) = r1v;
    }
}

// ---------------- launch ---------------------------------------------------
extern "C" void kernel_launch(void* const* d_in, const int* in_sizes, int n_in,
                              void* d_out, int out_size) {
    (void)in_sizes; (void)n_in; (void)out_size;
    const float* x     = (const float*)d_in[0];
    const float* Wq    = (const float*)d_in[1];
    const float* Wk    = (const float*)d_in[2];
    const float* Wv    = (const float*)d_in[3];
    const float* Wo    = (const float*)d_in[4];
    const float* bo    = (const float*)d_in[5];
    const float* ln1_g = (const float*)d_in[6];
    const float* ln1_b = (const float*)d_in[7];
    const float* ln3_g = (const float*)d_in[8];
    const float* ln3_b = (const float*)d_in[9];
    const float* Wff1  = (const float*)d_in[10];
    const float* bff1  = (const float*)d_in[11];
    const float* Wff2  = (const float*)d_in[12];
    const float* bff2  = (const float*)d_in[13];

    float* out = (float*)d_out;
    const size_t SZ = (size_t)MROWS * DMOD;
    float* out_x  = out;            // x
    float* out_q  = out + SZ;       // q_bh
    float* out_k  = out + 2 * SZ;   // k_bh
    float* out_v  = out + 3 * SZ;   // v_bh
    float* out_io = out + 4 * SZ;   // inter_out
    float* out_xf = out + 5 * SZ;   // x_features

    float *x2, *xf2, *xfr, *ior, *kr, *vtr, *actbuf, *wbuf;
    cudaGetSymbolAddress((void**)&x2,     g_x2);
    cudaGetSymbolAddress((void**)&xf2,    g_xf2);
    cudaGetSymbolAddress((void**)&xfr,    g_xfr);
    cudaGetSymbolAddress((void**)&ior,    g_ior);
    cudaGetSymbolAddress((void**)&kr,     g_kr);
    cudaGetSymbolAddress((void**)&vtr,    g_vtr);
    cudaGetSymbolAddress((void**)&actbuf, g_act);
    cudaGetSymbolAddress((void**)&wbuf,   g_w);

    cudaFuncSetAttribute(gemm_qkv_kernel,
                         cudaFuncAttributeMaxDynamicSharedMemorySize, SMEM_GEMM);
    cudaFuncSetAttribute((const void*)gemm3_kernel<0, 0>,
                         cudaFuncAttributeMaxDynamicSharedMemorySize, SMEM_GEMM);
    cudaFuncSetAttribute((const void*)gemm3_kernel<1, 0>,
                         cudaFuncAttributeMaxDynamicSharedMemorySize, SMEM_GEMM);
    cudaFuncSetAttribute((const void*)gemm3_kernel<0, 1>,
                         cudaFuncAttributeMaxDynamicSharedMemorySize, SMEM_GEMM);
    cudaFuncSetAttribute(flash_attn_kernel,
                         cudaFuncAttributeMaxDynamicSharedMemorySize, SMEM_FA);

    const dim3 blk(GTH);

    // 0) transpose + round all weights to tf32 (Wt = [N][K], n-major);
    //    Wff1 gets the geglu column interleave (new 2j = a_j, 2j+1 = gate_j).
    cvt_t_kernel<<<dim3(32, 32),  256>>>(Wq,   wbuf + WOFF_Q,   DMOD, DMOD);
    cvt_t_kernel<<<dim3(32, 32),  256>>>(Wk,   wbuf + WOFF_K,   DMOD, DMOD);
    cvt_t_kernel<<<dim3(32, 32),  256>>>(Wv,   wbuf + WOFF_V,   DMOD, DMOD);
    cvt_t_kernel<<<dim3(32, 32),  256>>>(Wo,   wbuf + WOFF_O,   DMOD, DMOD);
    cvt_t_ff1_kernel<<<dim3(256, 32), 256>>>(Wff1, wbuf + WOFF_FF1, DMOD);
    cvt_t_kernel<<<dim3(32, 128), 256>>>(Wff2, wbuf + WOFF_FF2, FF,   DMOD);

    // 1) LN1 -> x_features (exact) + rounded copy for GEMM A
    ln_kernel<<<MROWS, 256>>>(x, ln1_g, ln1_b, out_xf, xfr);

    // 2) fused QKV GEMM; exact q/k/v to d_out, rounded k (token-major) + v (transposed)
    gemm_qkv_kernel<<<dim3(3 * DMOD / BN, MROWS / BM), blk, SMEM_GEMM>>>(
        xfr, wbuf + WOFF_Q, out_q, out_k, out_v, kr, vtr);

    // 3) attention -> inter_out (exact) + rounded copy
    flash_attn_kernel<<<dim3(TOK / 128, NBAT * NH), 256, SMEM_FA>>>(
        out_q, kr, vtr, out_io, ior);

    // 4) Wo GEMM (gather-A from rounded inter_out) + bo + residual x -> x2 (exact)
    gemm3_kernel<1, 0><<<dim3(DMOD / BN, MROWS / BM), blk, SMEM_GEMM>>>(
        ior, wbuf + WOFF_O, x2, MROWS, DMOD, DMOD, bo, x);

    // 5) LN3 -> xf2 (rounded only; internal)
    ln_kernel<<<MROWS, 256>>>(x2, ln3_g, ln3_b, nullptr, xf2);

    // 6) FF1 GEMM with fused bias+geglu epilogue -> act (tf32-rounded)
    gemm3_kernel<0, 1><<<dim3(2 * FF / BN, MROWS / BM), blk, SMEM_GEMM>>>(
        xf2, wbuf + WOFF_FF1, actbuf, MROWS, 2 * FF, DMOD, bff1, nullptr);

    // 7) FF2 GEMM (+bff2) + residual x2 -> final x
    gemm3_kernel<0, 0><<<dim3(DMOD / BN, MROWS / BM), blk, SMEM_GEMM>>>(
        actbuf, wbuf + WOFF_FF2, out_x, MROWS, DMOD, FF, bff2, x2);
}